// round 1
// baseline (speedup 1.0000x reference)
#include <cuda_runtime.h>
#include <math.h>

#define N_NODES 10000
#define N_EDGES 160000
#define HIDDEN 128
#define NUM_RBF 32
#define N_GRAPHS 128
#define LATENT 64
#define ETILE 16

// ---------------- scratch (device globals; no runtime allocation) ----------------
__device__ float g_x[N_NODES * HIDDEN];        // node features
__device__ float g_vec[N_NODES * 3 * HIDDEN];  // equivariant features
__device__ float g_vmix[N_NODES * 3 * HIDDEN]; // vec @ Wv (also reused for v2)
__device__ float g_dx[N_NODES * HIDDEN];       // edge scatter accumulator
__device__ float g_vn[N_NODES * HIDDEN];       // vnorm
__device__ float g_a[N_NODES * HIDDEN];        // silu(cat @ W_a)
__device__ float g_dirn[N_EDGES * 3];
__device__ float g_rbf[N_EDGES * NUM_RBF];
__device__ float g_pooled[N_GRAPHS * 65];

// ---------------- helpers ----------------
__global__ void k_zero(float* p, int n) {
    int i = blockIdx.x * blockDim.x + threadIdx.x;
    if (i < n) p[i] = 0.0f;
}

__global__ void k_init_x(const int* __restrict__ z, const float* __restrict__ emb) {
    int idx = blockIdx.x * blockDim.x + threadIdx.x;
    if (idx < N_NODES * HIDDEN) {
        int n = idx >> 7, j = idx & 127;
        g_x[idx] = emb[z[n] * HIDDEN + j];
    }
}

// edge geometry: dirn + expnorm RBF
__global__ void k_geom(const float* __restrict__ pos, const int* __restrict__ ei) {
    int e = blockIdx.x * blockDim.x + threadIdx.x;
    if (e >= N_EDGES) return;
    int s = ei[e], d = ei[N_EDGES + e];
    float dx = pos[d * 3 + 0] - pos[s * 3 + 0];
    float dy = pos[d * 3 + 1] - pos[s * 3 + 1];
    float dz = pos[d * 3 + 2] - pos[s * 3 + 2];
    float r = sqrtf(dx * dx + dy * dy + dz * dz + 1e-8f);
    float inv = 1.0f / r;
    g_dirn[e * 3 + 0] = dx * inv;
    g_dirn[e * 3 + 1] = dy * inv;
    g_dirn[e * 3 + 2] = dz * inv;

    const float c0 = expf(-5.0f);
    float tmp = (2.0f / 32.0f) * (1.0f - c0);
    float beta = 1.0f / (tmp * tmp);
    float cut = (r < 5.0f) ? 0.5f * (cosf(3.14159265358979f * r / 5.0f) + 1.0f) : 0.0f;
    float er = expf(-r);
    float step = (1.0f - c0) / 31.0f;
#pragma unroll
    for (int k = 0; k < NUM_RBF; ++k) {
        float m = c0 + (float)k * step;
        float dd = er - m;
        g_rbf[e * NUM_RBF + k] = cut * expf(-beta * dd * dd);
    }
}

// generic row-major GEMM: C[r][j] (op)= act( sum_i A[r][i]*W[i][j] (+bias) ), K=N=128
__global__ void k_gemm128(const float* __restrict__ A, const float* __restrict__ W,
                          const float* __restrict__ bias, float* __restrict__ C,
                          int R, int accum, int act) {
    extern __shared__ float sm[];
    float* W_s = sm;               // 128*128
    float* A_s = sm + 128 * 128;   // 128*8 (layout [i][e])
    int j = threadIdx.x;
    for (int m = j; m < 128 * 128; m += 128) W_s[m] = W[m];
    __syncthreads();
    int nT = R / 8;
    for (int t = blockIdx.x; t < nT; t += gridDim.x) {
        int r0 = t * 8;
        for (int m = j; m < 128 * 8; m += 128) {
            int i = m >> 3, e = m & 7;
            A_s[m] = A[(r0 + e) * 128 + i];
        }
        __syncthreads();
        float acc[8] = {0, 0, 0, 0, 0, 0, 0, 0};
#pragma unroll 4
        for (int i = 0; i < 128; ++i) {
            float w = W_s[i * 128 + j];
            const float4* ap = (const float4*)&A_s[i * 8];
            float4 a0 = ap[0], a1 = ap[1];
            acc[0] += a0.x * w; acc[1] += a0.y * w; acc[2] += a0.z * w; acc[3] += a0.w * w;
            acc[4] += a1.x * w; acc[5] += a1.y * w; acc[6] += a1.z * w; acc[7] += a1.w * w;
        }
        float b = bias ? bias[j] : 0.0f;
#pragma unroll
        for (int e = 0; e < 8; ++e) {
            float v = acc[e] + b;
            if (accum) v += C[(r0 + e) * 128 + j];
            if (act) v = v / (1.0f + expf(-v));
            C[(r0 + e) * 128 + j] = v;
        }
        __syncthreads();
    }
}

// fused edge kernel: filt -> phi -> scatter dx and vec-message
__global__ void k_edge(const int* __restrict__ ei, const float* __restrict__ Wrbf,
                       const float* __restrict__ W1) {
    extern __shared__ float sm[];
    float* W1_s = sm;                  // 16384
    float* Wrbf_s = sm + 16384;        // 4096
    float* t_s = Wrbf_s + 4096;        // 128*16 (layout [i][e])
    float* rbf_s = t_s + 2048;         // 32*16 (layout [k][e])
    float* dirn_s = rbf_s + 512;       // 16*3
    int* src_s = (int*)(dirn_s + 48);  // 16
    int* dst_s = src_s + 16;           // 16

    int j = threadIdx.x;
    for (int m = j; m < 16384; m += 128) W1_s[m] = W1[m];
    for (int m = j; m < 4096; m += 128) Wrbf_s[m] = Wrbf[m];
    __syncthreads();

    int nT = N_EDGES / ETILE;
    for (int t = blockIdx.x; t < nT; t += gridDim.x) {
        int e0 = t * ETILE;
        if (j < 16) src_s[j] = ei[e0 + j];
        else if (j < 32) dst_s[j - 16] = ei[N_EDGES + e0 + (j - 16)];
        else if (j < 80) { int m = j - 32; dirn_s[m] = g_dirn[e0 * 3 + m]; }
        for (int m = j; m < 512; m += 128) {
            int e = m >> 5, k = m & 31;
            rbf_s[k * 16 + e] = g_rbf[(e0 + e) * 32 + k];
        }
        __syncthreads();

        // filt[e] for this thread's channel j
        float f[16];
#pragma unroll
        for (int e = 0; e < 16; ++e) f[e] = 0.0f;
#pragma unroll
        for (int k = 0; k < 32; ++k) {
            float w = Wrbf_s[k * 128 + j];
            const float4* rp = (const float4*)&rbf_s[k * 16];
            float4 r0 = rp[0], r1 = rp[1], r2 = rp[2], r3 = rp[3];
            f[0] += r0.x * w; f[1] += r0.y * w; f[2] += r0.z * w; f[3] += r0.w * w;
            f[4] += r1.x * w; f[5] += r1.y * w; f[6] += r1.z * w; f[7] += r1.w * w;
            f[8] += r2.x * w; f[9] += r2.y * w; f[10] += r2.z * w; f[11] += r2.w * w;
            f[12] += r3.x * w; f[13] += r3.y * w; f[14] += r3.z * w; f[15] += r3.w * w;
        }

        // t[e] = x[src][j] * filt[e][j]; stash transposed for the matmul
        float tv[16];
#pragma unroll
        for (int e = 0; e < 16; ++e) tv[e] = g_x[src_s[e] * 128 + j] * f[e];
        float4* tp = (float4*)&t_s[j * 16];
        tp[0] = make_float4(tv[0], tv[1], tv[2], tv[3]);
        tp[1] = make_float4(tv[4], tv[5], tv[6], tv[7]);
        tp[2] = make_float4(tv[8], tv[9], tv[10], tv[11]);
        tp[3] = make_float4(tv[12], tv[13], tv[14], tv[15]);
        __syncthreads();

        // phi_pre[e][j] = sum_i t[e][i] * W1[i][j]
        float acc[16];
#pragma unroll
        for (int e = 0; e < 16; ++e) acc[e] = 0.0f;
#pragma unroll 2
        for (int i = 0; i < 128; ++i) {
            float w = W1_s[i * 128 + j];
            const float4* ap = (const float4*)&t_s[i * 16];
            float4 a0 = ap[0], a1 = ap[1], a2 = ap[2], a3 = ap[3];
            acc[0] += a0.x * w; acc[1] += a0.y * w; acc[2] += a0.z * w; acc[3] += a0.w * w;
            acc[4] += a1.x * w; acc[5] += a1.y * w; acc[6] += a1.z * w; acc[7] += a1.w * w;
            acc[8] += a2.x * w; acc[9] += a2.y * w; acc[10] += a2.z * w; acc[11] += a2.w * w;
            acc[12] += a3.x * w; acc[13] += a3.y * w; acc[14] += a3.z * w; acc[15] += a3.w * w;
        }

        // silu + scatter
#pragma unroll
        for (int e = 0; e < 16; ++e) {
            float p = acc[e];
            p = p / (1.0f + expf(-p));
            int d = dst_s[e], s = src_s[e];
            atomicAdd(&g_dx[d * 128 + j], p);
            float d0 = dirn_s[e * 3 + 0], d1 = dirn_s[e * 3 + 1], d2 = dirn_s[e * 3 + 2];
            float fe = f[e];
            atomicAdd(&g_vec[(d * 3 + 0) * 128 + j], g_vmix[(s * 3 + 0) * 128 + j] * fe + p * d0);
            atomicAdd(&g_vec[(d * 3 + 1) * 128 + j], g_vmix[(s * 3 + 1) * 128 + j] * fe + p * d1);
            atomicAdd(&g_vec[(d * 3 + 2) * 128 + j], g_vmix[(s * 3 + 2) * 128 + j] * fe + p * d2);
        }
        __syncthreads();
    }
}

__global__ void k_vnorm(const float* __restrict__ v2, float* __restrict__ vn) {
    int idx = blockIdx.x * blockDim.x + threadIdx.x;
    if (idx >= N_NODES * HIDDEN) return;
    int n = idx >> 7, k = idx & 127;
    float a = v2[(n * 3 + 0) * 128 + k];
    float b = v2[(n * 3 + 1) * 128 + k];
    float c = v2[(n * 3 + 2) * 128 + k];
    vn[idx] = sqrtf(a * a + b * b + c * c + 1e-8f);
}

// out = a @ W_b + b_b, pooled[batch[n]] += out
__global__ void k_pool(const float* __restrict__ a, const int* __restrict__ batch,
                       const float* __restrict__ Wb, const float* __restrict__ bb) {
    __shared__ float Wb_s[128 * 65];
    __shared__ float bb_s[65];
    __shared__ float a_s[4][128];
    int tx = threadIdx.x, ty = threadIdx.y;
    int tid = ty * 65 + tx;
    for (int m = tid; m < 128 * 65; m += 260) Wb_s[m] = Wb[m];
    if (tid < 65) bb_s[tid] = bb[tid];
    __syncthreads();
    for (int base = blockIdx.x * 4; base < N_NODES; base += gridDim.x * 4) {
        int n = base + ty;
        a_s[ty][tx] = a[n * 128 + tx];
        if (tx + 65 < 128) a_s[ty][tx + 65] = a[n * 128 + tx + 65];
        __syncthreads();
        float acc = bb_s[tx];
#pragma unroll 4
        for (int jj = 0; jj < 128; ++jj) acc += a_s[ty][jj] * Wb_s[jj * 65 + tx];
        atomicAdd(&g_pooled[batch[n] * 65 + tx], acc);
        __syncthreads();
    }
}

__global__ void k_final(float* __restrict__ out) {
    int idx = blockIdx.x * blockDim.x + threadIdx.x;
    if (idx < N_GRAPHS * LATENT) {
        int g = idx / LATENT, k = idx % LATENT;
        out[idx] = g_pooled[g * 65 + k];
    } else if (idx < N_GRAPHS * LATENT + N_GRAPHS) {
        int g = idx - N_GRAPHS * LATENT;
        float lv = g_pooled[g * 65 + 64];
        out[idx] = fminf(fmaxf(lv, -10.0f), 2.0f);
    }
}

extern "C" void kernel_launch(void* const* d_in, const int* in_sizes, int n_in,
                              void* d_out, int out_size) {
    (void)in_sizes; (void)n_in; (void)out_size;
    const int* z = (const int*)d_in[0];
    const float* pos = (const float*)d_in[1];
    const int* batch = (const int*)d_in[2];
    const int* ei = (const int*)d_in[3];
    const float* embed = (const float*)d_in[4];
    const float* W_rbf = (const float*)d_in[5];
    const float* W1 = (const float*)d_in[6];
    const float* Wo = (const float*)d_in[7];
    const float* Wv = (const float*)d_in[8];
    const float* Wvec2 = (const float*)d_in[10];
    const float* W_a = (const float*)d_in[11];
    const float* b_a = (const float*)d_in[12];
    const float* W_b = (const float*)d_in[13];
    const float* b_b = (const float*)d_in[14];
    float* out = (float*)d_out;

    float *p_x, *p_vec, *p_vmix, *p_dx, *p_vn, *p_a, *p_pooled;
    cudaGetSymbolAddress((void**)&p_x, g_x);
    cudaGetSymbolAddress((void**)&p_vec, g_vec);
    cudaGetSymbolAddress((void**)&p_vmix, g_vmix);
    cudaGetSymbolAddress((void**)&p_dx, g_dx);
    cudaGetSymbolAddress((void**)&p_vn, g_vn);
    cudaGetSymbolAddress((void**)&p_a, g_a);
    cudaGetSymbolAddress((void**)&p_pooled, g_pooled);

    size_t smem_gemm = (128 * 128 + 128 * 8) * sizeof(float);      // 69632 B
    size_t smem_edge = 23088 * sizeof(float) + 32 * sizeof(int);   // 92480 B
    cudaFuncSetAttribute(k_gemm128, cudaFuncAttributeMaxDynamicSharedMemorySize, (int)smem_gemm);
    cudaFuncSetAttribute(k_edge, cudaFuncAttributeMaxDynamicSharedMemorySize, (int)smem_edge);

    // init
    k_zero<<<(N_NODES * 384 + 255) / 256, 256>>>(p_vec, N_NODES * 384);
    k_zero<<<(N_GRAPHS * 65 + 255) / 256, 256>>>(p_pooled, N_GRAPHS * 65);
    k_init_x<<<(N_NODES * 128 + 255) / 256, 256>>>(z, embed);
    k_geom<<<(N_EDGES + 255) / 256, 256>>>(pos, ei);

    for (int l = 0; l < 2; ++l) {
        // vmix = vec @ Wv[l]  (30000 rows)
        k_gemm128<<<444, 128, smem_gemm>>>(p_vec, Wv + l * 128 * 128, nullptr, p_vmix,
                                           N_NODES * 3, 0, 0);
        k_zero<<<(N_NODES * 128 + 255) / 256, 256>>>(p_dx, N_NODES * 128);
        // fused edge pass: filt, phi, dx scatter, vec-message scatter
        k_edge<<<296, 128, smem_edge>>>(ei, W_rbf + l * 32 * 128, W1 + l * 128 * 128);
        // x += dx @ Wo[l]
        k_gemm128<<<444, 128, smem_gemm>>>(p_dx, Wo + l * 128 * 128, nullptr, p_x,
                                           N_NODES, 1, 0);
    }

    // v2 = vec @ Wvec2 (reuse vmix buffer), vnorm
    k_gemm128<<<444, 128, smem_gemm>>>(p_vec, Wvec2, nullptr, p_vmix, N_NODES * 3, 0, 0);
    k_vnorm<<<(N_NODES * 128 + 255) / 256, 256>>>(p_vmix, p_vn);

    // a = silu(x @ Wa_top + vnorm @ Wa_bot + b_a)
    k_gemm128<<<444, 128, smem_gemm>>>(p_x, W_a, nullptr, p_a, N_NODES, 0, 0);
    k_gemm128<<<444, 128, smem_gemm>>>(p_vn, W_a + 128 * 128, b_a, p_a, N_NODES, 1, 1);

    // pooled += (a @ W_b + b_b) per node
    dim3 pb(65, 4);
    k_pool<<<296, pb>>>(p_a, batch, W_b, b_b);

    // mu / clipped log_var
    k_final<<<(N_GRAPHS * LATENT + N_GRAPHS + 255) / 256, 256>>>(out);
}

// round 2
// speedup vs baseline: 1.1391x; 1.1391x over previous
#include <cuda_runtime.h>
#include <math.h>

#define N_NODES 10000
#define N_EDGES 160000
#define HIDDEN 128
#define NUM_RBF 32
#define N_GRAPHS 128
#define LATENT 64
#define ET 64            // edges per tile in k_edge
#define PAD 136          // smem row stride (floats): 136%32==8 -> conflict-free frag loads

// ---------------- scratch (device globals; no runtime allocation) ----------------
__device__ float g_x[N_NODES * HIDDEN];
__device__ float g_vec[N_NODES * 3 * HIDDEN];
__device__ float g_vmix[N_NODES * 3 * HIDDEN];
__device__ float g_dx[N_NODES * HIDDEN];
__device__ float g_vn[N_NODES * HIDDEN];
__device__ float g_a[N_NODES * HIDDEN];
__device__ float g_dirn[N_EDGES * 3];
__device__ float g_rbf[N_EDGES * NUM_RBF];
__device__ float g_pooled[N_GRAPHS * 65];

// ---------------- mma helpers ----------------
__device__ __forceinline__ unsigned f2tf(float f) {
    unsigned r;
    asm("cvt.rna.tf32.f32 %0, %1;" : "=r"(r) : "f"(f));
    return r;
}

__device__ __forceinline__ void mma_tf32(float c[4], unsigned a0, unsigned a1,
                                         unsigned a2, unsigned a3,
                                         unsigned b0, unsigned b1) {
    asm volatile(
        "mma.sync.aligned.m16n8k8.row.col.f32.tf32.tf32.f32 "
        "{%0,%1,%2,%3}, {%4,%5,%6,%7}, {%8,%9}, {%0,%1,%2,%3};"
        : "+f"(c[0]), "+f"(c[1]), "+f"(c[2]), "+f"(c[3])
        : "r"(a0), "r"(a1), "r"(a2), "r"(a3), "r"(b0), "r"(b1));
}

__device__ __forceinline__ float silu(float v) { return v / (1.0f + expf(-v)); }

// ---------------- small kernels ----------------
__global__ void k_zero(float* p, int n) {
    int i = blockIdx.x * blockDim.x + threadIdx.x;
    if (i < n) p[i] = 0.0f;
}

__global__ void k_init_x(const int* __restrict__ z, const float* __restrict__ emb) {
    int idx = blockIdx.x * blockDim.x + threadIdx.x;
    if (idx < N_NODES * HIDDEN) {
        int n = idx >> 7, j = idx & 127;
        g_x[idx] = emb[z[n] * HIDDEN + j];
    }
}

__global__ void k_geom(const float* __restrict__ pos, const int* __restrict__ ei) {
    int e = blockIdx.x * blockDim.x + threadIdx.x;
    if (e >= N_EDGES) return;
    int s = ei[e], d = ei[N_EDGES + e];
    float dx = pos[d * 3 + 0] - pos[s * 3 + 0];
    float dy = pos[d * 3 + 1] - pos[s * 3 + 1];
    float dz = pos[d * 3 + 2] - pos[s * 3 + 2];
    float r = sqrtf(dx * dx + dy * dy + dz * dz + 1e-8f);
    float inv = 1.0f / r;
    g_dirn[e * 3 + 0] = dx * inv;
    g_dirn[e * 3 + 1] = dy * inv;
    g_dirn[e * 3 + 2] = dz * inv;

    const float c0 = expf(-5.0f);
    float tmp = (2.0f / 32.0f) * (1.0f - c0);
    float beta = 1.0f / (tmp * tmp);
    float cut = (r < 5.0f) ? 0.5f * (cosf(3.14159265358979f * r / 5.0f) + 1.0f) : 0.0f;
    float er = expf(-r);
    float step = (1.0f - c0) / 31.0f;
#pragma unroll
    for (int k = 0; k < NUM_RBF; ++k) {
        float m = c0 + (float)k * step;
        float dd = er - m;
        g_rbf[e * NUM_RBF + k] = cut * expf(-beta * dd * dd);
    }
}

// ---------------- tensor-core node GEMM: C[r][j] (op)= act(A@W + bias) ----------------
// A: R x 128 row-major, W: 128 x 128 row-major. 64-row tiles, 256 threads.
__global__ __launch_bounds__(256) void k_gemm_mma(
    const float* __restrict__ A, const float* __restrict__ W,
    const float* __restrict__ bias, float* __restrict__ C,
    int R, int accum, int act) {
    extern __shared__ float sm[];
    unsigned* W_u = (unsigned*)sm;                 // 128 x PAD
    unsigned* A_u = (unsigned*)(sm + 128 * PAD);   // 64 x PAD
    int tid = threadIdx.x;
    int w = tid >> 5, lane = tid & 31, gid = lane >> 2, tig = lane & 3;

    for (int m = tid; m < 128 * 128; m += 256) {
        int i = m >> 7, j = m & 127;
        W_u[i * PAD + j] = f2tf(W[m]);
    }
    __syncthreads();

    int m0 = (w & 3) * 16;
    int nbase = (w >> 2) * 64;
    int nT = (R + 63) >> 6;
    for (int t = blockIdx.x; t < nT; t += gridDim.x) {
        int r0 = t << 6;
        for (int m = tid; m < 64 * 128; m += 256) {
            int r = m >> 7, c = m & 127;
            int rr = r0 + r;
            float v = (rr < R) ? A[rr * 128 + c] : 0.0f;
            A_u[r * PAD + c] = f2tf(v);
        }
        __syncthreads();

        float acc[8][4];
#pragma unroll
        for (int it = 0; it < 8; ++it)
#pragma unroll
            for (int q = 0; q < 4; ++q) acc[it][q] = 0.0f;

#pragma unroll
        for (int ks = 0; ks < 16; ++ks) {
            int k0 = ks * 8;
            unsigned a0 = A_u[(m0 + gid) * PAD + k0 + tig];
            unsigned a1 = A_u[(m0 + gid + 8) * PAD + k0 + tig];
            unsigned a2 = A_u[(m0 + gid) * PAD + k0 + tig + 4];
            unsigned a3 = A_u[(m0 + gid + 8) * PAD + k0 + tig + 4];
#pragma unroll
            for (int it = 0; it < 8; ++it) {
                int n0 = nbase + it * 8;
                unsigned b0 = W_u[(k0 + tig) * PAD + n0 + gid];
                unsigned b1 = W_u[(k0 + tig + 4) * PAD + n0 + gid];
                mma_tf32(acc[it], a0, a1, a2, a3, b0, b1);
            }
        }

        // epilogue
#pragma unroll
        for (int it = 0; it < 8; ++it) {
            int n0 = nbase + it * 8;
            int col = n0 + 2 * tig;
            float bb0 = bias ? bias[col] : 0.0f;
            float bb1 = bias ? bias[col + 1] : 0.0f;
#pragma unroll
            for (int h = 0; h < 2; ++h) {
                int row = r0 + m0 + gid + h * 8;
                if (row < R) {
                    float v0 = acc[it][2 * h + 0] + bb0;
                    float v1 = acc[it][2 * h + 1] + bb1;
                    if (accum) {
                        v0 += C[row * 128 + col];
                        v1 += C[row * 128 + col + 1];
                    }
                    if (act) { v0 = silu(v0); v1 = silu(v1); }
                    C[row * 128 + col] = v0;
                    C[row * 128 + col + 1] = v1;
                }
            }
        }
        __syncthreads();
    }
}

// ---------------- fused tensor-core edge kernel ----------------
// per 64-edge tile: filt = rbf@Wrbf (mma), t = x[src]*filt, phi = silu(t@W1) (mma),
// scatter dx and vec messages with fp32 atomics.
__global__ __launch_bounds__(256) void k_edge(
    const int* __restrict__ ei, const float* __restrict__ Wrbf,
    const float* __restrict__ W1) {
    extern __shared__ float sm[];
    // float-unit offsets
    float* W1_f   = sm;                        // 128*PAD (tf32 bits)
    float* Wrbf_f = W1_f + 128 * PAD;          // 32*PAD  (tf32 bits)
    float* filt_s = Wrbf_f + 32 * PAD;         // 64*PAD  (f32)
    float* t_f    = filt_s + ET * PAD;         // 64*PAD  (tf32 bits; aliased by phi f32)
    float* rbf_f  = t_f + ET * PAD;            // 64*40   (tf32 bits)
    float* dirn_s = rbf_f + ET * 40;           // 192
    int* src_s    = (int*)(dirn_s + 192);      // 64
    int* dst_s    = src_s + ET;                // 64

    unsigned* W1_u   = (unsigned*)W1_f;
    unsigned* Wrbf_u = (unsigned*)Wrbf_f;
    unsigned* t_u    = (unsigned*)t_f;
    unsigned* rbf_u  = (unsigned*)rbf_f;

    int tid = threadIdx.x;
    int w = tid >> 5, lane = tid & 31, gid = lane >> 2, tig = lane & 3;

    for (int m = tid; m < 128 * 128; m += 256) {
        int i = m >> 7, j = m & 127;
        W1_u[i * PAD + j] = f2tf(W1[m]);
    }
    for (int m = tid; m < 32 * 128; m += 256) {
        int k = m >> 7, j = m & 127;
        Wrbf_u[k * PAD + j] = f2tf(Wrbf[m]);
    }

    int m0 = (w & 3) * 16;
    int nbase = (w >> 2) * 64;
    int j = tid & 127;
    int eh = tid >> 7;

    int nTiles = N_EDGES / ET;
    for (int t = blockIdx.x; t < nTiles; t += gridDim.x) {
        int e0 = t * ET;
        __syncthreads();  // prev scatter done / W load done (first iter)

        // stage edge data
        if (tid < ET) src_s[tid] = ei[e0 + tid];
        else if (tid < 2 * ET) dst_s[tid - ET] = ei[N_EDGES + e0 + (tid - ET)];
        for (int m = tid; m < ET * 3; m += 256) dirn_s[m] = g_dirn[e0 * 3 + m];
        for (int m = tid; m < ET * 32; m += 256) {
            int e = m >> 5, k = m & 31;
            rbf_u[e * 40 + k] = f2tf(g_rbf[e0 * 32 + m]);
        }
        __syncthreads();

        // filt = rbf @ Wrbf  (M=64, N=128, K=32)
        {
            float acc[8][4];
#pragma unroll
            for (int it = 0; it < 8; ++it)
#pragma unroll
                for (int q = 0; q < 4; ++q) acc[it][q] = 0.0f;
#pragma unroll
            for (int ks = 0; ks < 4; ++ks) {
                int k0 = ks * 8;
                unsigned a0 = rbf_u[(m0 + gid) * 40 + k0 + tig];
                unsigned a1 = rbf_u[(m0 + gid + 8) * 40 + k0 + tig];
                unsigned a2 = rbf_u[(m0 + gid) * 40 + k0 + tig + 4];
                unsigned a3 = rbf_u[(m0 + gid + 8) * 40 + k0 + tig + 4];
#pragma unroll
                for (int it = 0; it < 8; ++it) {
                    int n0 = nbase + it * 8;
                    unsigned b0 = Wrbf_u[(k0 + tig) * PAD + n0 + gid];
                    unsigned b1 = Wrbf_u[(k0 + tig + 4) * PAD + n0 + gid];
                    mma_tf32(acc[it], a0, a1, a2, a3, b0, b1);
                }
            }
#pragma unroll
            for (int it = 0; it < 8; ++it) {
                int n0 = nbase + it * 8;
                filt_s[(m0 + gid) * PAD + n0 + 2 * tig]     = acc[it][0];
                filt_s[(m0 + gid) * PAD + n0 + 2 * tig + 1] = acc[it][1];
                filt_s[(m0 + gid + 8) * PAD + n0 + 2 * tig]     = acc[it][2];
                filt_s[(m0 + gid + 8) * PAD + n0 + 2 * tig + 1] = acc[it][3];
            }
        }
        __syncthreads();

        // t[e][j] = x[src[e]][j] * filt[e][j]  (tf32)
        {
            int ebase = eh * 32;
#pragma unroll 4
            for (int q = 0; q < 32; ++q) {
                int e = ebase + q;
                int s = src_s[e];
                float xv = g_x[s * 128 + j];
                t_u[e * PAD + j] = f2tf(xv * filt_s[e * PAD + j]);
            }
        }
        __syncthreads();

        // phi = t @ W1  (M=64, N=128, K=128)
        float acc[8][4];
#pragma unroll
        for (int it = 0; it < 8; ++it)
#pragma unroll
            for (int q = 0; q < 4; ++q) acc[it][q] = 0.0f;
#pragma unroll
        for (int ks = 0; ks < 16; ++ks) {
            int k0 = ks * 8;
            unsigned a0 = t_u[(m0 + gid) * PAD + k0 + tig];
            unsigned a1 = t_u[(m0 + gid + 8) * PAD + k0 + tig];
            unsigned a2 = t_u[(m0 + gid) * PAD + k0 + tig + 4];
            unsigned a3 = t_u[(m0 + gid + 8) * PAD + k0 + tig + 4];
#pragma unroll
            for (int it = 0; it < 8; ++it) {
                int n0 = nbase + it * 8;
                unsigned b0 = W1_u[(k0 + tig) * PAD + n0 + gid];
                unsigned b1 = W1_u[(k0 + tig + 4) * PAD + n0 + gid];
                mma_tf32(acc[it], a0, a1, a2, a3, b0, b1);
            }
        }
        __syncthreads();  // all t_u reads complete before aliasing with phi

        // silu, store phi into t_f (alias)
#pragma unroll
        for (int it = 0; it < 8; ++it) {
            int n0 = nbase + it * 8;
            t_f[(m0 + gid) * PAD + n0 + 2 * tig]     = silu(acc[it][0]);
            t_f[(m0 + gid) * PAD + n0 + 2 * tig + 1] = silu(acc[it][1]);
            t_f[(m0 + gid + 8) * PAD + n0 + 2 * tig]     = silu(acc[it][2]);
            t_f[(m0 + gid + 8) * PAD + n0 + 2 * tig + 1] = silu(acc[it][3]);
        }
        __syncthreads();

        // scatter: dx[dst] += phi ; vec[dst][c] += vmix[src][c]*filt + phi*dirn[c]
        {
            int ebase = eh * 32;
#pragma unroll 2
            for (int q = 0; q < 32; ++q) {
                int e = ebase + q;
                int s = src_s[e], d = dst_s[e];
                float p = t_f[e * PAD + j];
                float fe = filt_s[e * PAD + j];
                atomicAdd(&g_dx[d * 128 + j], p);
                float d0 = dirn_s[e * 3 + 0];
                float d1 = dirn_s[e * 3 + 1];
                float d2 = dirn_s[e * 3 + 2];
                atomicAdd(&g_vec[(d * 3 + 0) * 128 + j],
                          g_vmix[(s * 3 + 0) * 128 + j] * fe + p * d0);
                atomicAdd(&g_vec[(d * 3 + 1) * 128 + j],
                          g_vmix[(s * 3 + 1) * 128 + j] * fe + p * d1);
                atomicAdd(&g_vec[(d * 3 + 2) * 128 + j],
                          g_vmix[(s * 3 + 2) * 128 + j] * fe + p * d2);
            }
        }
    }
}

__global__ void k_vnorm(const float* __restrict__ v2, float* __restrict__ vn) {
    int idx = blockIdx.x * blockDim.x + threadIdx.x;
    if (idx >= N_NODES * HIDDEN) return;
    int n = idx >> 7, k = idx & 127;
    float a = v2[(n * 3 + 0) * 128 + k];
    float b = v2[(n * 3 + 1) * 128 + k];
    float c = v2[(n * 3 + 2) * 128 + k];
    vn[idx] = sqrtf(a * a + b * b + c * c + 1e-8f);
}

// out = a @ W_b + b_b, pooled[batch[n]] += out
__global__ void k_pool(const float* __restrict__ a, const int* __restrict__ batch,
                       const float* __restrict__ Wb, const float* __restrict__ bb) {
    __shared__ float Wb_s[128 * 65];
    __shared__ float bb_s[65];
    __shared__ float a_s[4][128];
    int tx = threadIdx.x, ty = threadIdx.y;
    int tid = ty * 65 + tx;
    for (int m = tid; m < 128 * 65; m += 260) Wb_s[m] = Wb[m];
    if (tid < 65) bb_s[tid] = bb[tid];
    __syncthreads();
    for (int base = blockIdx.x * 4; base < N_NODES; base += gridDim.x * 4) {
        int n = base + ty;
        a_s[ty][tx] = a[n * 128 + tx];
        if (tx + 65 < 128) a_s[ty][tx + 65] = a[n * 128 + tx + 65];
        __syncthreads();
        float acc = bb_s[tx];
#pragma unroll 4
        for (int jj = 0; jj < 128; ++jj) acc += a_s[ty][jj] * Wb_s[jj * 65 + tx];
        atomicAdd(&g_pooled[batch[n] * 65 + tx], acc);
        __syncthreads();
    }
}

__global__ void k_final(float* __restrict__ out) {
    int idx = blockIdx.x * blockDim.x + threadIdx.x;
    if (idx < N_GRAPHS * LATENT) {
        int g = idx / LATENT, k = idx % LATENT;
        out[idx] = g_pooled[g * 65 + k];
    } else if (idx < N_GRAPHS * LATENT + N_GRAPHS) {
        int g = idx - N_GRAPHS * LATENT;
        float lv = g_pooled[g * 65 + 64];
        out[idx] = fminf(fmaxf(lv, -10.0f), 2.0f);
    }
}

extern "C" void kernel_launch(void* const* d_in, const int* in_sizes, int n_in,
                              void* d_out, int out_size) {
    (void)in_sizes; (void)n_in; (void)out_size;
    const int* z = (const int*)d_in[0];
    const float* pos = (const float*)d_in[1];
    const int* batch = (const int*)d_in[2];
    const int* ei = (const int*)d_in[3];
    const float* embed = (const float*)d_in[4];
    const float* W_rbf = (const float*)d_in[5];
    const float* W1 = (const float*)d_in[6];
    const float* Wo = (const float*)d_in[7];
    const float* Wv = (const float*)d_in[8];
    const float* Wvec2 = (const float*)d_in[10];
    const float* W_a = (const float*)d_in[11];
    const float* b_a = (const float*)d_in[12];
    const float* W_b = (const float*)d_in[13];
    const float* b_b = (const float*)d_in[14];
    float* out = (float*)d_out;

    float *p_x, *p_vec, *p_vmix, *p_dx, *p_vn, *p_a, *p_pooled;
    cudaGetSymbolAddress((void**)&p_x, g_x);
    cudaGetSymbolAddress((void**)&p_vec, g_vec);
    cudaGetSymbolAddress((void**)&p_vmix, g_vmix);
    cudaGetSymbolAddress((void**)&p_dx, g_dx);
    cudaGetSymbolAddress((void**)&p_vn, g_vn);
    cudaGetSymbolAddress((void**)&p_a, g_a);
    cudaGetSymbolAddress((void**)&p_pooled, g_pooled);

    size_t smem_gemm = (size_t)(128 * PAD + 64 * PAD) * 4;                       // 104448
    size_t smem_edge = (size_t)(128 * PAD + 32 * PAD + ET * PAD * 2 + ET * 40
                                + 192) * 4 + 2 * ET * 4;                         // ~168 KB
    cudaFuncSetAttribute(k_gemm_mma, cudaFuncAttributeMaxDynamicSharedMemorySize, (int)smem_gemm);
    cudaFuncSetAttribute(k_edge, cudaFuncAttributeMaxDynamicSharedMemorySize, (int)smem_edge);

    // init
    k_zero<<<(N_NODES * 384 + 255) / 256, 256>>>(p_vec, N_NODES * 384);
    k_zero<<<(N_GRAPHS * 65 + 255) / 256, 256>>>(p_pooled, N_GRAPHS * 65);
    k_init_x<<<(N_NODES * 128 + 255) / 256, 256>>>(z, embed);
    k_geom<<<(N_EDGES + 255) / 256, 256>>>(pos, ei);

    for (int l = 0; l < 2; ++l) {
        // vmix = vec @ Wv[l]  (30000 rows)
        k_gemm_mma<<<296, 256, smem_gemm>>>(p_vec, Wv + l * 128 * 128, nullptr, p_vmix,
                                            N_NODES * 3, 0, 0);
        k_zero<<<(N_NODES * 128 + 255) / 256, 256>>>(p_dx, N_NODES * 128);
        // fused edge pass
        k_edge<<<148, 256, smem_edge>>>(ei, W_rbf + l * 32 * 128, W1 + l * 128 * 128);
        // x += dx @ Wo[l]
        k_gemm_mma<<<157, 256, smem_gemm>>>(p_dx, Wo + l * 128 * 128, nullptr, p_x,
                                            N_NODES, 1, 0);
    }

    // v2 = vec @ Wvec2 (reuse vmix buffer), vnorm
    k_gemm_mma<<<296, 256, smem_gemm>>>(p_vec, Wvec2, nullptr, p_vmix, N_NODES * 3, 0, 0);
    k_vnorm<<<(N_NODES * 128 + 255) / 256, 256>>>(p_vmix, p_vn);

    // a = silu(x @ Wa_top + vnorm @ Wa_bot + b_a)
    k_gemm_mma<<<157, 256, smem_gemm>>>(p_x, W_a, nullptr, p_a, N_NODES, 0, 0);
    k_gemm_mma<<<157, 256, smem_gemm>>>(p_vn, W_a + 128 * 128, b_a, p_a, N_NODES, 1, 1);

    // pooled += (a @ W_b + b_b) per node
    dim3 pb(65, 4);
    k_pool<<<296, pb>>>(p_a, batch, W_b, b_b);

    // mu / clipped log_var
    k_final<<<(N_GRAPHS * LATENT + N_GRAPHS + 255) / 256, 256>>>(out);
}

// round 4
// speedup vs baseline: 3.1408x; 2.7573x over previous
#include <cuda_runtime.h>
#include <math.h>

#define N_NODES 10000
#define N_EDGES 160000
#define HIDDEN 128
#define NUM_RBF 32
#define N_GRAPHS 128
#define LATENT 64
#define ET 64            // edges per tile in k_edge
#define PAD 136          // smem row stride (floats)

// ---------------- scratch ----------------
__device__ float g_x[N_NODES * HIDDEN];
__device__ float g_vec[N_NODES * 3 * HIDDEN];
__device__ float g_vmix[N_NODES * 3 * HIDDEN];
__device__ float g_dx[N_NODES * HIDDEN];
__device__ float g_vn[N_NODES * HIDDEN];
__device__ float g_a[N_NODES * HIDDEN];
__device__ float g_dirn[N_EDGES * 3];
__device__ float g_rbf[N_EDGES * NUM_RBF];
__device__ float g_pooled[N_GRAPHS * 65];

// ---------------- helpers ----------------
__device__ __forceinline__ unsigned f2tf(float f) {
    unsigned r;
    asm("cvt.rna.tf32.f32 %0, %1;" : "=r"(r) : "f"(f));
    return r;
}

__device__ __forceinline__ void mma_tf32(float c[4], unsigned a0, unsigned a1,
                                         unsigned a2, unsigned a3,
                                         unsigned b0, unsigned b1) {
    asm volatile(
        "mma.sync.aligned.m16n8k8.row.col.f32.tf32.tf32.f32 "
        "{%0,%1,%2,%3}, {%4,%5,%6,%7}, {%8,%9}, {%0,%1,%2,%3};"
        : "+f"(c[0]), "+f"(c[1]), "+f"(c[2]), "+f"(c[3])
        : "r"(a0), "r"(a1), "r"(a2), "r"(a3), "r"(b0), "r"(b1));
}

__device__ __forceinline__ void red4(float* p, float a, float b, float c, float d) {
    unsigned long long addr = (unsigned long long)p;
    asm volatile("red.global.add.v4.f32 [%0], {%1,%2,%3,%4};"
                 :: "l"(addr), "f"(a), "f"(b), "f"(c), "f"(d) : "memory");
}

__device__ __forceinline__ float silu(float v) {
    return __fdividef(v, 1.0f + __expf(-v));
}

// ---------------- setup: zero scratch + embed gather ----------------
__global__ void k_setup(const int* __restrict__ z, const float* __restrict__ emb) {
    int i = blockIdx.x * blockDim.x + threadIdx.x;
    if (i < N_NODES * 384) g_vec[i] = 0.0f;
    if (i < N_NODES * 128) {
        g_dx[i] = 0.0f;
        int n = i >> 7, j = i & 127;
        g_x[i] = emb[z[n] * HIDDEN + j];
    }
    if (i < N_GRAPHS * 65) g_pooled[i] = 0.0f;
}

__global__ void k_zero(float* p, int n) {
    int i = blockIdx.x * blockDim.x + threadIdx.x;
    if (i < n) p[i] = 0.0f;
}

__global__ void k_geom(const float* __restrict__ pos, const int* __restrict__ ei) {
    int e = blockIdx.x * blockDim.x + threadIdx.x;
    if (e >= N_EDGES) return;
    int s = ei[e], d = ei[N_EDGES + e];
    float dx = pos[d * 3 + 0] - pos[s * 3 + 0];
    float dy = pos[d * 3 + 1] - pos[s * 3 + 1];
    float dz = pos[d * 3 + 2] - pos[s * 3 + 2];
    float r = sqrtf(dx * dx + dy * dy + dz * dz + 1e-8f);
    float inv = 1.0f / r;
    g_dirn[e * 3 + 0] = dx * inv;
    g_dirn[e * 3 + 1] = dy * inv;
    g_dirn[e * 3 + 2] = dz * inv;

    const float c0 = expf(-5.0f);
    float tmp = (2.0f / 32.0f) * (1.0f - c0);
    float beta = 1.0f / (tmp * tmp);
    float cut = (r < 5.0f) ? 0.5f * (__cosf(3.14159265358979f * r / 5.0f) + 1.0f) : 0.0f;
    float er = __expf(-r);
    float step = (1.0f - c0) / 31.0f;
#pragma unroll
    for (int k = 0; k < NUM_RBF; ++k) {
        float m = c0 + (float)k * step;
        float dd = er - m;
        g_rbf[e * NUM_RBF + k] = cut * __expf(-beta * dd * dd);
    }
}

// ---------------- tensor-core node GEMM ----------------
__global__ __launch_bounds__(256) void k_gemm_mma(
    const float* __restrict__ A, const float* __restrict__ W,
    const float* __restrict__ bias, float* __restrict__ C,
    int R, int accum, int act) {
    extern __shared__ float sm[];
    unsigned* W_u = (unsigned*)sm;                 // 128 x PAD
    unsigned* A_u = (unsigned*)(sm + 128 * PAD);   // 64 x PAD
    int tid = threadIdx.x;
    int w = tid >> 5, lane = tid & 31, gid = lane >> 2, tig = lane & 3;

    for (int m4 = tid; m4 < 128 * 32; m4 += 256) {
        int i = m4 >> 5, j = (m4 & 31) * 4;
        float4 v = *(const float4*)&W[i * 128 + j];
        uint4 u = make_uint4(f2tf(v.x), f2tf(v.y), f2tf(v.z), f2tf(v.w));
        *(uint4*)&W_u[i * PAD + j] = u;
    }
    __syncthreads();

    int m0 = (w & 3) * 16;
    int nbase = (w >> 2) * 64;
    int nT = (R + 63) >> 6;
    for (int t = blockIdx.x; t < nT; t += gridDim.x) {
        int r0 = t << 6;
        for (int m4 = tid; m4 < 64 * 32; m4 += 256) {
            int r = m4 >> 5, c = (m4 & 31) * 4;
            int rr = r0 + r;
            float4 v = make_float4(0.f, 0.f, 0.f, 0.f);
            if (rr < R) v = *(const float4*)&A[rr * 128 + c];
            uint4 u = make_uint4(f2tf(v.x), f2tf(v.y), f2tf(v.z), f2tf(v.w));
            *(uint4*)&A_u[r * PAD + c] = u;
        }
        __syncthreads();

        float acc[8][4];
#pragma unroll
        for (int it = 0; it < 8; ++it)
#pragma unroll
            for (int q = 0; q < 4; ++q) acc[it][q] = 0.0f;

#pragma unroll
        for (int ks = 0; ks < 16; ++ks) {
            int k0 = ks * 8;
            unsigned a0 = A_u[(m0 + gid) * PAD + k0 + tig];
            unsigned a1 = A_u[(m0 + gid + 8) * PAD + k0 + tig];
            unsigned a2 = A_u[(m0 + gid) * PAD + k0 + tig + 4];
            unsigned a3 = A_u[(m0 + gid + 8) * PAD + k0 + tig + 4];
#pragma unroll
            for (int it = 0; it < 8; ++it) {
                int n0 = nbase + it * 8;
                unsigned b0 = W_u[(k0 + tig) * PAD + n0 + gid];
                unsigned b1 = W_u[(k0 + tig + 4) * PAD + n0 + gid];
                mma_tf32(acc[it], a0, a1, a2, a3, b0, b1);
            }
        }

#pragma unroll
        for (int it = 0; it < 8; ++it) {
            int n0 = nbase + it * 8;
            int col = n0 + 2 * tig;
            float bb0 = bias ? bias[col] : 0.0f;
            float bb1 = bias ? bias[col + 1] : 0.0f;
#pragma unroll
            for (int h = 0; h < 2; ++h) {
                int row = r0 + m0 + gid + h * 8;
                if (row < R) {
                    float v0 = acc[it][2 * h + 0] + bb0;
                    float v1 = acc[it][2 * h + 1] + bb1;
                    if (accum) {
                        v0 += C[row * 128 + col];
                        v1 += C[row * 128 + col + 1];
                    }
                    if (act) { v0 = silu(v0); v1 = silu(v1); }
                    C[row * 128 + col] = v0;
                    C[row * 128 + col + 1] = v1;
                }
            }
        }
        __syncthreads();
    }
}

// ---------------- fused edge kernel (512 threads) ----------------
__global__ __launch_bounds__(512) void k_edge(
    const int* __restrict__ ei, const float* __restrict__ Wrbf,
    const float* __restrict__ W1) {
    extern __shared__ float sm[];
    float* W1_f   = sm;                        // 128*PAD (tf32 bits)
    float* Wrbf_f = W1_f + 128 * PAD;          // 32*PAD
    float* filt_s = Wrbf_f + 32 * PAD;         // 64*PAD (f32)
    float* t_f    = filt_s + ET * PAD;         // 64*PAD (tf32 bits / phi f32 alias)
    float* rbf_f  = t_f + ET * PAD;            // 64*40
    float* dirn_s = rbf_f + ET * 40;           // 192
    int* src_s    = (int*)(dirn_s + 192);      // 64
    int* dst_s    = src_s + ET;                // 64

    unsigned* W1_u   = (unsigned*)W1_f;
    unsigned* Wrbf_u = (unsigned*)Wrbf_f;
    unsigned* t_u    = (unsigned*)t_f;
    unsigned* rbf_u  = (unsigned*)rbf_f;

    int tid = threadIdx.x;
    int w = tid >> 5, lane = tid & 31, gid = lane >> 2, tig = lane & 3;

    for (int m4 = tid; m4 < 128 * 32; m4 += 512) {
        int i = m4 >> 5, j = (m4 & 31) * 4;
        float4 v = *(const float4*)&W1[i * 128 + j];
        *(uint4*)&W1_u[i * PAD + j] =
            make_uint4(f2tf(v.x), f2tf(v.y), f2tf(v.z), f2tf(v.w));
    }
    for (int m4 = tid; m4 < 32 * 32; m4 += 512) {
        int k = m4 >> 5, j = (m4 & 31) * 4;
        float4 v = *(const float4*)&Wrbf[k * 128 + j];
        *(uint4*)&Wrbf_u[k * PAD + j] =
            make_uint4(f2tf(v.x), f2tf(v.y), f2tf(v.z), f2tf(v.w));
    }

    int m0 = (w & 3) * 16;       // warp row block
    int nbase = (w >> 2) * 32;   // warp col block
    int c4 = lane * 4;           // 4 channels per lane in warp-per-edge phases

    int nTiles = N_EDGES / ET;
    for (int t = blockIdx.x; t < nTiles; t += gridDim.x) {
        int e0 = t * ET;
        __syncthreads();  // previous tile fully consumed

        if (tid < ET) src_s[tid] = ei[e0 + tid];
        else if (tid < 2 * ET) dst_s[tid - ET] = ei[N_EDGES + e0 + (tid - ET)];
        if (tid < ET * 3) dirn_s[tid] = g_dirn[e0 * 3 + tid];
        for (int m4 = tid; m4 < ET * 8; m4 += 512) {
            int e = m4 >> 3, k = (m4 & 7) * 4;
            float4 v = *(const float4*)&g_rbf[(e0 + e) * 32 + k];
            *(uint4*)&rbf_u[e * 40 + k] =
                make_uint4(f2tf(v.x), f2tf(v.y), f2tf(v.z), f2tf(v.w));
        }
        __syncthreads();

        // filt = rbf @ Wrbf  (M=64, N=128, K=32)
        {
            float acc[4][4];
#pragma unroll
            for (int it = 0; it < 4; ++it)
#pragma unroll
                for (int q = 0; q < 4; ++q) acc[it][q] = 0.0f;
#pragma unroll
            for (int ks = 0; ks < 4; ++ks) {
                int k0 = ks * 8;
                unsigned a0 = rbf_u[(m0 + gid) * 40 + k0 + tig];
                unsigned a1 = rbf_u[(m0 + gid + 8) * 40 + k0 + tig];
                unsigned a2 = rbf_u[(m0 + gid) * 40 + k0 + tig + 4];
                unsigned a3 = rbf_u[(m0 + gid + 8) * 40 + k0 + tig + 4];
#pragma unroll
                for (int it = 0; it < 4; ++it) {
                    int n0 = nbase + it * 8;
                    unsigned b0 = Wrbf_u[(k0 + tig) * PAD + n0 + gid];
                    unsigned b1 = Wrbf_u[(k0 + tig + 4) * PAD + n0 + gid];
                    mma_tf32(acc[it], a0, a1, a2, a3, b0, b1);
                }
            }
#pragma unroll
            for (int it = 0; it < 4; ++it) {
                int n0 = nbase + it * 8;
                filt_s[(m0 + gid) * PAD + n0 + 2 * tig]     = acc[it][0];
                filt_s[(m0 + gid) * PAD + n0 + 2 * tig + 1] = acc[it][1];
                filt_s[(m0 + gid + 8) * PAD + n0 + 2 * tig]     = acc[it][2];
                filt_s[(m0 + gid + 8) * PAD + n0 + 2 * tig + 1] = acc[it][3];
            }
        }
        __syncthreads();

        // t[e][c] = x[src[e]][c] * filt[e][c]  — warp per edge, float4 per lane
#pragma unroll
        for (int q = 0; q < 4; ++q) {
            int e = w + 16 * q;
            int s = src_s[e];
            float4 xv = *(const float4*)&g_x[s * 128 + c4];
            float4 fv = *(const float4*)&filt_s[e * PAD + c4];
            *(uint4*)&t_u[e * PAD + c4] =
                make_uint4(f2tf(xv.x * fv.x), f2tf(xv.y * fv.y),
                           f2tf(xv.z * fv.z), f2tf(xv.w * fv.w));
        }
        __syncthreads();

        // phi = t @ W1  (M=64, N=128, K=128)
        float acc[4][4];
#pragma unroll
        for (int it = 0; it < 4; ++it)
#pragma unroll
            for (int q = 0; q < 4; ++q) acc[it][q] = 0.0f;
#pragma unroll
        for (int ks = 0; ks < 16; ++ks) {
            int k0 = ks * 8;
            unsigned a0 = t_u[(m0 + gid) * PAD + k0 + tig];
            unsigned a1 = t_u[(m0 + gid + 8) * PAD + k0 + tig];
            unsigned a2 = t_u[(m0 + gid) * PAD + k0 + tig + 4];
            unsigned a3 = t_u[(m0 + gid + 8) * PAD + k0 + tig + 4];
#pragma unroll
            for (int it = 0; it < 4; ++it) {
                int n0 = nbase + it * 8;
                unsigned b0 = W1_u[(k0 + tig) * PAD + n0 + gid];
                unsigned b1 = W1_u[(k0 + tig + 4) * PAD + n0 + gid];
                mma_tf32(acc[it], a0, a1, a2, a3, b0, b1);
            }
        }
        __syncthreads();  // t_u reads complete before phi alias

#pragma unroll
        for (int it = 0; it < 4; ++it) {
            int n0 = nbase + it * 8;
            t_f[(m0 + gid) * PAD + n0 + 2 * tig]     = silu(acc[it][0]);
            t_f[(m0 + gid) * PAD + n0 + 2 * tig + 1] = silu(acc[it][1]);
            t_f[(m0 + gid + 8) * PAD + n0 + 2 * tig]     = silu(acc[it][2]);
            t_f[(m0 + gid + 8) * PAD + n0 + 2 * tig + 1] = silu(acc[it][3]);
        }
        __syncthreads();

        // scatter — warp per edge, float4 lanes, vector REDs
#pragma unroll
        for (int q = 0; q < 4; ++q) {
            int e = w + 16 * q;
            int s = src_s[e], d = dst_s[e];
            float4 p  = *(const float4*)&t_f[e * PAD + c4];
            float4 fv = *(const float4*)&filt_s[e * PAD + c4];
            float d0 = dirn_s[e * 3 + 0];
            float d1 = dirn_s[e * 3 + 1];
            float d2 = dirn_s[e * 3 + 2];
            red4(&g_dx[d * 128 + c4], p.x, p.y, p.z, p.w);
            float4 m0v = *(const float4*)&g_vmix[(s * 3 + 0) * 128 + c4];
            red4(&g_vec[(d * 3 + 0) * 128 + c4],
                 m0v.x * fv.x + p.x * d0, m0v.y * fv.y + p.y * d0,
                 m0v.z * fv.z + p.z * d0, m0v.w * fv.w + p.w * d0);
            float4 m1v = *(const float4*)&g_vmix[(s * 3 + 1) * 128 + c4];
            red4(&g_vec[(d * 3 + 1) * 128 + c4],
                 m1v.x * fv.x + p.x * d1, m1v.y * fv.y + p.y * d1,
                 m1v.z * fv.z + p.z * d1, m1v.w * fv.w + p.w * d1);
            float4 m2v = *(const float4*)&g_vmix[(s * 3 + 2) * 128 + c4];
            red4(&g_vec[(d * 3 + 2) * 128 + c4],
                 m2v.x * fv.x + p.x * d2, m2v.y * fv.y + p.y * d2,
                 m2v.z * fv.z + p.z * d2, m2v.w * fv.w + p.w * d2);
        }
    }
}

__global__ void k_vnorm(const float* __restrict__ v2, float* __restrict__ vn) {
    int idx = blockIdx.x * blockDim.x + threadIdx.x;
    if (idx >= N_NODES * HIDDEN) return;
    int n = idx >> 7, k = idx & 127;
    float a = v2[(n * 3 + 0) * 128 + k];
    float b = v2[(n * 3 + 1) * 128 + k];
    float c = v2[(n * 3 + 2) * 128 + k];
    vn[idx] = sqrtf(a * a + b * b + c * c + 1e-8f);
}

__global__ void k_pool(const float* __restrict__ a, const int* __restrict__ batch,
                       const float* __restrict__ Wb, const float* __restrict__ bb) {
    __shared__ float Wb_s[128 * 65];
    __shared__ float bb_s[65];
    __shared__ float a_s[4][128];
    int tx = threadIdx.x, ty = threadIdx.y;
    int tid = ty * 65 + tx;
    for (int m = tid; m < 128 * 65; m += 260) Wb_s[m] = Wb[m];
    if (tid < 65) bb_s[tid] = bb[tid];
    __syncthreads();
    for (int base = blockIdx.x * 4; base < N_NODES; base += gridDim.x * 4) {
        int n = base + ty;
        a_s[ty][tx] = a[n * 128 + tx];
        if (tx + 65 < 128) a_s[ty][tx + 65] = a[n * 128 + tx + 65];
        __syncthreads();
        float acc = bb_s[tx];
#pragma unroll 4
        for (int jj = 0; jj < 128; ++jj) acc += a_s[ty][jj] * Wb_s[jj * 65 + tx];
        atomicAdd(&g_pooled[batch[n] * 65 + tx], acc);
        __syncthreads();
    }
}

__global__ void k_final(float* __restrict__ out) {
    int idx = blockIdx.x * blockDim.x + threadIdx.x;
    if (idx < N_GRAPHS * LATENT) {
        int g = idx / LATENT, k = idx % LATENT;
        out[idx] = g_pooled[g * 65 + k];
    } else if (idx < N_GRAPHS * LATENT + N_GRAPHS) {
        int g = idx - N_GRAPHS * LATENT;
        float lv = g_pooled[g * 65 + 64];
        out[idx] = fminf(fmaxf(lv, -10.0f), 2.0f);
    }
}

extern "C" void kernel_launch(void* const* d_in, const int* in_sizes, int n_in,
                              void* d_out, int out_size) {
    (void)in_sizes; (void)n_in; (void)out_size;
    const int* z = (const int*)d_in[0];
    const float* pos = (const float*)d_in[1];
    const int* batch = (const int*)d_in[2];
    const int* ei = (const int*)d_in[3];
    const float* embed = (const float*)d_in[4];
    const float* W_rbf = (const float*)d_in[5];
    const float* W1 = (const float*)d_in[6];
    const float* Wo = (const float*)d_in[7];
    const float* Wv = (const float*)d_in[8];
    const float* Wvec2 = (const float*)d_in[10];
    const float* W_a = (const float*)d_in[11];
    const float* b_a = (const float*)d_in[12];
    const float* W_b = (const float*)d_in[13];
    const float* b_b = (const float*)d_in[14];
    float* out = (float*)d_out;

    float *p_x, *p_vec, *p_vmix, *p_dx, *p_vn, *p_a;
    cudaGetSymbolAddress((void**)&p_x, g_x);
    cudaGetSymbolAddress((void**)&p_vec, g_vec);
    cudaGetSymbolAddress((void**)&p_vmix, g_vmix);
    cudaGetSymbolAddress((void**)&p_dx, g_dx);
    cudaGetSymbolAddress((void**)&p_vn, g_vn);
    cudaGetSymbolAddress((void**)&p_a, g_a);

    size_t smem_gemm = (size_t)(128 * PAD + 64 * PAD) * 4;
    size_t smem_edge = (size_t)(128 * PAD + 32 * PAD + ET * PAD * 2 + ET * 40
                                + 192) * 4 + 2 * ET * 4;
    cudaFuncSetAttribute(k_gemm_mma, cudaFuncAttributeMaxDynamicSharedMemorySize, (int)smem_gemm);
    cudaFuncSetAttribute(k_edge, cudaFuncAttributeMaxDynamicSharedMemorySize, (int)smem_edge);

    // 1: setup (zero vec/dx/pooled + embed gather)
    k_setup<<<(N_NODES * 384 + 255) / 256, 256>>>(z, embed);
    // 2: edge geometry
    k_geom<<<(N_EDGES + 255) / 256, 256>>>(pos, ei);

    for (int l = 0; l < 2; ++l) {
        // vmix = vec @ Wv[l]
        k_gemm_mma<<<296, 256, smem_gemm>>>(p_vec, Wv + l * 128 * 128, nullptr, p_vmix,
                                            N_NODES * 3, 0, 0);
        if (l) k_zero<<<(N_NODES * 128 + 255) / 256, 256>>>(p_dx, N_NODES * 128);
        // fused edge pass  (launch #4 on l==0 -> ncu target)
        k_edge<<<148, 512, smem_edge>>>(ei, W_rbf + l * 32 * 128, W1 + l * 128 * 128);
        // x += dx @ Wo[l]
        k_gemm_mma<<<157, 256, smem_gemm>>>(p_dx, Wo + l * 128 * 128, nullptr, p_x,
                                            N_NODES, 1, 0);
    }

    // v2 = vec @ Wvec2 (reuse vmix buffer), vnorm
    k_gemm_mma<<<296, 256, smem_gemm>>>(p_vec, Wvec2, nullptr, p_vmix, N_NODES * 3, 0, 0);
    k_vnorm<<<(N_NODES * 128 + 255) / 256, 256>>>(p_vmix, p_vn);

    // a = silu(x @ Wa_top + vnorm @ Wa_bot + b_a)
    k_gemm_mma<<<157, 256, smem_gemm>>>(p_x, W_a, nullptr, p_a, N_NODES, 0, 0);
    k_gemm_mma<<<157, 256, smem_gemm>>>(p_vn, W_a + 128 * 128, b_a, p_a, N_NODES, 1, 1);

    // pooled += (a @ W_b + b_b)
    dim3 pb(65, 4);
    k_pool<<<296, pb>>>(p_a, batch, W_b, b_b);

    k_final<<<(N_GRAPHS * LATENT + N_GRAPHS + 255) / 256, 256>>>(out);
}

// round 5
// speedup vs baseline: 4.3086x; 1.3718x over previous
#include <cuda_runtime.h>
#include <cuda_fp16.h>
#include <math.h>

#define N_NODES 10000
#define N_EDGES 160000
#define HIDDEN 128
#define NUM_RBF 32
#define N_GRAPHS 128
#define LATENT 64
#define ET 64            // edges per tile in k_edge
#define PAD 136          // f32 smem stride (node gemm)
#define PADH 136         // half stride for 128-wide rows
#define PADR 40          // half stride for 32-wide rows

// ---------------- scratch ----------------
__device__ float g_x[N_NODES * HIDDEN];
__device__ float g_vec[N_NODES * 3 * HIDDEN];
__device__ float g_vmix[N_NODES * 3 * HIDDEN];
__device__ float g_dx[N_NODES * HIDDEN];
__device__ float g_vn[N_NODES * HIDDEN];
__device__ float g_a[N_NODES * HIDDEN];
__device__ float g_dirn[N_EDGES * 3];
__device__ __half g_rbf[N_EDGES * NUM_RBF];
__device__ float g_pooled[N_GRAPHS * 65];

// ---------------- helpers ----------------
__device__ __forceinline__ unsigned f2tf(float f) {
    unsigned r;
    asm("cvt.rna.tf32.f32 %0, %1;" : "=r"(r) : "f"(f));
    return r;
}

__device__ __forceinline__ void mma_tf32(float c[4], unsigned a0, unsigned a1,
                                         unsigned a2, unsigned a3,
                                         unsigned b0, unsigned b1) {
    asm volatile(
        "mma.sync.aligned.m16n8k8.row.col.f32.tf32.tf32.f32 "
        "{%0,%1,%2,%3}, {%4,%5,%6,%7}, {%8,%9}, {%0,%1,%2,%3};"
        : "+f"(c[0]), "+f"(c[1]), "+f"(c[2]), "+f"(c[3])
        : "r"(a0), "r"(a1), "r"(a2), "r"(a3), "r"(b0), "r"(b1));
}

__device__ __forceinline__ void mma_f16(float c[4], unsigned a0, unsigned a1,
                                        unsigned a2, unsigned a3,
                                        unsigned b0, unsigned b1) {
    asm volatile(
        "mma.sync.aligned.m16n8k16.row.col.f32.f16.f16.f32 "
        "{%0,%1,%2,%3}, {%4,%5,%6,%7}, {%8,%9}, {%0,%1,%2,%3};"
        : "+f"(c[0]), "+f"(c[1]), "+f"(c[2]), "+f"(c[3])
        : "r"(a0), "r"(a1), "r"(a2), "r"(a3), "r"(b0), "r"(b1));
}

__device__ __forceinline__ void red4(float* p, float a, float b, float c, float d) {
    unsigned long long addr = (unsigned long long)p;
    asm volatile("red.global.add.v4.f32 [%0], {%1,%2,%3,%4};"
                 :: "l"(addr), "f"(a), "f"(b), "f"(c), "f"(d) : "memory");
}

__device__ __forceinline__ float silu(float v) {
    return __fdividef(v, 1.0f + __expf(-v));
}

#define H2U(p) (*(const unsigned*)(p))

// ---------------- setup ----------------
__global__ void k_setup(const int* __restrict__ z, const float* __restrict__ emb) {
    int i = blockIdx.x * blockDim.x + threadIdx.x;
    if (i < N_NODES * 384) g_vec[i] = 0.0f;
    if (i < N_NODES * 128) {
        g_dx[i] = 0.0f;
        int n = i >> 7, j = i & 127;
        g_x[i] = emb[z[n] * HIDDEN + j];
    }
    if (i < N_GRAPHS * 65) g_pooled[i] = 0.0f;
}

__global__ void k_zero(float* p, int n) {
    int i = blockIdx.x * blockDim.x + threadIdx.x;
    if (i < n) p[i] = 0.0f;
}

// edge geometry: dirn + windowed expnorm RBF (half output)
__global__ void k_geom(const float* __restrict__ pos, const int* __restrict__ ei) {
    int e = blockIdx.x * blockDim.x + threadIdx.x;
    if (e >= N_EDGES) return;
    int s = ei[e], d = ei[N_EDGES + e];
    float dx = pos[d * 3 + 0] - pos[s * 3 + 0];
    float dy = pos[d * 3 + 1] - pos[s * 3 + 1];
    float dz = pos[d * 3 + 2] - pos[s * 3 + 2];
    float r = sqrtf(dx * dx + dy * dy + dz * dz + 1e-8f);
    float inv = 1.0f / r;
    g_dirn[e * 3 + 0] = dx * inv;
    g_dirn[e * 3 + 1] = dy * inv;
    g_dirn[e * 3 + 2] = dz * inv;

    // zero all 32 half slots (64 B)
    uint4* rp = (uint4*)&g_rbf[e * 32];
    uint4 z4 = make_uint4(0, 0, 0, 0);
    rp[0] = z4; rp[1] = z4; rp[2] = z4; rp[3] = z4;

    if (r < 5.0f) {
        const float c0 = 0.006737946999085467f;          // exp(-5)
        const float step = (1.0f - c0) / 31.0f;
        const float tmp = (2.0f / 32.0f) * (1.0f - c0);
        const float beta = 1.0f / (tmp * tmp);
        float cut = 0.5f * (__cosf(0.6283185307179586f * r) + 1.0f);
        float er = __expf(-r);
        int kc = (int)((er - c0) * (1.0f / step));
        int base = kc - 8;
        base = base < 0 ? 0 : (base > 15 ? 15 : base);
#pragma unroll
        for (int kk = 0; kk < 17; ++kk) {
            int k = base + kk;
            float m = c0 + (float)k * step;
            float dd = er - m;
            g_rbf[e * 32 + k] = __float2half(cut * __expf(-beta * dd * dd));
        }
    }
}

// ---------------- tensor-core node GEMM (tf32) ----------------
__global__ __launch_bounds__(256) void k_gemm_mma(
    const float* __restrict__ A, const float* __restrict__ W,
    const float* __restrict__ bias, float* __restrict__ C,
    int R, int accum, int act) {
    extern __shared__ float sm[];
    unsigned* W_u = (unsigned*)sm;
    unsigned* A_u = (unsigned*)(sm + 128 * PAD);
    int tid = threadIdx.x;
    int w = tid >> 5, lane = tid & 31, gid = lane >> 2, tig = lane & 3;

    for (int m4 = tid; m4 < 128 * 32; m4 += 256) {
        int i = m4 >> 5, j = (m4 & 31) * 4;
        float4 v = *(const float4*)&W[i * 128 + j];
        *(uint4*)&W_u[i * PAD + j] =
            make_uint4(f2tf(v.x), f2tf(v.y), f2tf(v.z), f2tf(v.w));
    }
    __syncthreads();

    int m0 = (w & 3) * 16;
    int nbase = (w >> 2) * 64;
    int nT = (R + 63) >> 6;
    for (int t = blockIdx.x; t < nT; t += gridDim.x) {
        int r0 = t << 6;
        for (int m4 = tid; m4 < 64 * 32; m4 += 256) {
            int r = m4 >> 5, c = (m4 & 31) * 4;
            int rr = r0 + r;
            float4 v = make_float4(0.f, 0.f, 0.f, 0.f);
            if (rr < R) v = *(const float4*)&A[rr * 128 + c];
            *(uint4*)&A_u[r * PAD + c] =
                make_uint4(f2tf(v.x), f2tf(v.y), f2tf(v.z), f2tf(v.w));
        }
        __syncthreads();

        float acc[8][4];
#pragma unroll
        for (int it = 0; it < 8; ++it)
#pragma unroll
            for (int q = 0; q < 4; ++q) acc[it][q] = 0.0f;

#pragma unroll
        for (int ks = 0; ks < 16; ++ks) {
            int k0 = ks * 8;
            unsigned a0 = A_u[(m0 + gid) * PAD + k0 + tig];
            unsigned a1 = A_u[(m0 + gid + 8) * PAD + k0 + tig];
            unsigned a2 = A_u[(m0 + gid) * PAD + k0 + tig + 4];
            unsigned a3 = A_u[(m0 + gid + 8) * PAD + k0 + tig + 4];
#pragma unroll
            for (int it = 0; it < 8; ++it) {
                int n0 = nbase + it * 8;
                unsigned b0 = W_u[(k0 + tig) * PAD + n0 + gid];
                unsigned b1 = W_u[(k0 + tig + 4) * PAD + n0 + gid];
                mma_tf32(acc[it], a0, a1, a2, a3, b0, b1);
            }
        }

#pragma unroll
        for (int it = 0; it < 8; ++it) {
            int n0 = nbase + it * 8;
            int col = n0 + 2 * tig;
            float bb0 = bias ? bias[col] : 0.0f;
            float bb1 = bias ? bias[col + 1] : 0.0f;
#pragma unroll
            for (int h = 0; h < 2; ++h) {
                int row = r0 + m0 + gid + h * 8;
                if (row < R) {
                    float v0 = acc[it][2 * h + 0] + bb0;
                    float v1 = acc[it][2 * h + 1] + bb1;
                    if (accum) {
                        v0 += C[row * 128 + col];
                        v1 += C[row * 128 + col + 1];
                    }
                    if (act) { v0 = silu(v0); v1 = silu(v1); }
                    C[row * 128 + col] = v0;
                    C[row * 128 + col + 1] = v1;
                }
            }
        }
        __syncthreads();
    }
}

// ---------------- fused fp16 edge kernel (512 threads, 2 CTAs/SM) ----------------
__global__ __launch_bounds__(512) void k_edge(
    const int* __restrict__ ei, const float* __restrict__ Wrbf,
    const float* __restrict__ W1) {
    extern __shared__ __half smh[];
    __half* W1T   = smh;                       // [128 n][PADH k]
    __half* WrbfT = W1T + 128 * PADH;          // [128 n][PADR k]
    __half* filt_h = WrbfT + 128 * PADR;       // [64 e][PADH c]
    __half* t_h    = filt_h + ET * PADH;       // [64 e][PADH k]  (phi alias)
    __half* rbf_h  = t_h + ET * PADH;          // [64 e][PADR k]
    float* dirn_s = (float*)(rbf_h + ET * PADR);  // 192
    int* src_s = (int*)(dirn_s + 192);            // 64
    int* dst_s = src_s + ET;                      // 64

    int tid = threadIdx.x;
    int w = tid >> 5, lane = tid & 31, gid = lane >> 2, tig = lane & 3;

    // stage weights transposed to [n][k] half
    for (int m = tid; m < 128 * 128; m += 512) {
        int i = m >> 7, j = m & 127;   // i=k, j=n
        W1T[j * PADH + i] = __float2half(W1[m]);
    }
    for (int m = tid; m < 32 * 128; m += 512) {
        int i = m >> 7, j = m & 127;
        WrbfT[j * PADR + i] = __float2half(Wrbf[m]);
    }

    int m0 = (w & 3) * 16;       // edge-row block
    int nbase = (w >> 2) * 32;   // channel block
    int c4 = lane * 4;

    int nTiles = N_EDGES / ET;
    for (int t = blockIdx.x; t < nTiles; t += gridDim.x) {
        int e0 = t * ET;
        __syncthreads();  // prev tile consumed / weight staging done

        if (tid < ET) src_s[tid] = ei[e0 + tid];
        else if (tid < 2 * ET) dst_s[tid - ET] = ei[N_EDGES + e0 + (tid - ET)];
        if (tid < ET * 3) dirn_s[tid] = g_dirn[e0 * 3 + tid];
        for (int m4 = tid; m4 < ET * 4; m4 += 512) {
            int e = m4 >> 2, kk = (m4 & 3) * 8;
            *(uint4*)&rbf_h[e * PADR + kk] = *(const uint4*)&g_rbf[(e0 + e) * 32 + kk];
        }
        __syncthreads();

        // filt = rbf @ Wrbf  (M=64, N=128, K=32) fp16 mma
        {
            float acc[4][4];
#pragma unroll
            for (int it = 0; it < 4; ++it)
#pragma unroll
                for (int q = 0; q < 4; ++q) acc[it][q] = 0.0f;
#pragma unroll
            for (int ks = 0; ks < 2; ++ks) {
                int k0 = ks * 16;
                unsigned a0 = H2U(&rbf_h[(m0 + gid) * PADR + k0 + 2 * tig]);
                unsigned a1 = H2U(&rbf_h[(m0 + gid + 8) * PADR + k0 + 2 * tig]);
                unsigned a2 = H2U(&rbf_h[(m0 + gid) * PADR + k0 + 2 * tig + 8]);
                unsigned a3 = H2U(&rbf_h[(m0 + gid + 8) * PADR + k0 + 2 * tig + 8]);
#pragma unroll
                for (int it = 0; it < 4; ++it) {
                    int n0 = nbase + it * 8;
                    unsigned b0 = H2U(&WrbfT[(n0 + gid) * PADR + k0 + 2 * tig]);
                    unsigned b1 = H2U(&WrbfT[(n0 + gid) * PADR + k0 + 2 * tig + 8]);
                    mma_f16(acc[it], a0, a1, a2, a3, b0, b1);
                }
            }
#pragma unroll
            for (int it = 0; it < 4; ++it) {
                int n0 = nbase + it * 8;
                *(__half2*)&filt_h[(m0 + gid) * PADH + n0 + 2 * tig] =
                    __floats2half2_rn(acc[it][0], acc[it][1]);
                *(__half2*)&filt_h[(m0 + gid + 8) * PADH + n0 + 2 * tig] =
                    __floats2half2_rn(acc[it][2], acc[it][3]);
            }
        }
        __syncthreads();

        // t[e][c] = x[src[e]][c] * filt[e][c]  — warp per edge
#pragma unroll
        for (int q = 0; q < 4; ++q) {
            int e = w + 16 * q;
            int s = src_s[e];
            float4 xv = *(const float4*)&g_x[s * 128 + c4];
            float2 f01 = __half22float2(*(__half2*)&filt_h[e * PADH + c4]);
            float2 f23 = __half22float2(*(__half2*)&filt_h[e * PADH + c4 + 2]);
            *(__half2*)&t_h[e * PADH + c4] = __floats2half2_rn(xv.x * f01.x, xv.y * f01.y);
            *(__half2*)&t_h[e * PADH + c4 + 2] = __floats2half2_rn(xv.z * f23.x, xv.w * f23.y);
        }
        __syncthreads();

        // phi = t @ W1  (M=64, N=128, K=128) fp16 mma
        float acc[4][4];
#pragma unroll
        for (int it = 0; it < 4; ++it)
#pragma unroll
            for (int q = 0; q < 4; ++q) acc[it][q] = 0.0f;
#pragma unroll
        for (int ks = 0; ks < 8; ++ks) {
            int k0 = ks * 16;
            unsigned a0 = H2U(&t_h[(m0 + gid) * PADH + k0 + 2 * tig]);
            unsigned a1 = H2U(&t_h[(m0 + gid + 8) * PADH + k0 + 2 * tig]);
            unsigned a2 = H2U(&t_h[(m0 + gid) * PADH + k0 + 2 * tig + 8]);
            unsigned a3 = H2U(&t_h[(m0 + gid + 8) * PADH + k0 + 2 * tig + 8]);
#pragma unroll
            for (int it = 0; it < 4; ++it) {
                int n0 = nbase + it * 8;
                unsigned b0 = H2U(&W1T[(n0 + gid) * PADH + k0 + 2 * tig]);
                unsigned b1 = H2U(&W1T[(n0 + gid) * PADH + k0 + 2 * tig + 8]);
                mma_f16(acc[it], a0, a1, a2, a3, b0, b1);
            }
        }
        __syncthreads();  // t reads complete before phi alias write

#pragma unroll
        for (int it = 0; it < 4; ++it) {
            int n0 = nbase + it * 8;
            *(__half2*)&t_h[(m0 + gid) * PADH + n0 + 2 * tig] =
                __floats2half2_rn(silu(acc[it][0]), silu(acc[it][1]));
            *(__half2*)&t_h[(m0 + gid + 8) * PADH + n0 + 2 * tig] =
                __floats2half2_rn(silu(acc[it][2]), silu(acc[it][3]));
        }
        __syncthreads();

        // scatter — warp per edge, vector REDs
#pragma unroll
        for (int q = 0; q < 4; ++q) {
            int e = w + 16 * q;
            int s = src_s[e], d = dst_s[e];
            float2 p01 = __half22float2(*(__half2*)&t_h[e * PADH + c4]);
            float2 p23 = __half22float2(*(__half2*)&t_h[e * PADH + c4 + 2]);
            float2 f01 = __half22float2(*(__half2*)&filt_h[e * PADH + c4]);
            float2 f23 = __half22float2(*(__half2*)&filt_h[e * PADH + c4 + 2]);
            float d0 = dirn_s[e * 3 + 0];
            float d1 = dirn_s[e * 3 + 1];
            float d2 = dirn_s[e * 3 + 2];
            red4(&g_dx[d * 128 + c4], p01.x, p01.y, p23.x, p23.y);
            float4 m0v = *(const float4*)&g_vmix[(s * 3 + 0) * 128 + c4];
            red4(&g_vec[(d * 3 + 0) * 128 + c4],
                 m0v.x * f01.x + p01.x * d0, m0v.y * f01.y + p01.y * d0,
                 m0v.z * f23.x + p23.x * d0, m0v.w * f23.y + p23.y * d0);
            float4 m1v = *(const float4*)&g_vmix[(s * 3 + 1) * 128 + c4];
            red4(&g_vec[(d * 3 + 1) * 128 + c4],
                 m1v.x * f01.x + p01.x * d1, m1v.y * f01.y + p01.y * d1,
                 m1v.z * f23.x + p23.x * d1, m1v.w * f23.y + p23.y * d1);
            float4 m2v = *(const float4*)&g_vmix[(s * 3 + 2) * 128 + c4];
            red4(&g_vec[(d * 3 + 2) * 128 + c4],
                 m2v.x * f01.x + p01.x * d2, m2v.y * f01.y + p01.y * d2,
                 m2v.z * f23.x + p23.x * d2, m2v.w * f23.y + p23.y * d2);
        }
    }
}

__global__ void k_vnorm(const float* __restrict__ v2, float* __restrict__ vn) {
    int idx = blockIdx.x * blockDim.x + threadIdx.x;
    if (idx >= N_NODES * HIDDEN) return;
    int n = idx >> 7, k = idx & 127;
    float a = v2[(n * 3 + 0) * 128 + k];
    float b = v2[(n * 3 + 1) * 128 + k];
    float c = v2[(n * 3 + 2) * 128 + k];
    vn[idx] = sqrtf(a * a + b * b + c * c + 1e-8f);
}

__global__ void k_pool(const float* __restrict__ a, const int* __restrict__ batch,
                       const float* __restrict__ Wb, const float* __restrict__ bb) {
    __shared__ float Wb_s[128 * 65];
    __shared__ float bb_s[65];
    __shared__ float a_s[4][128];
    int tx = threadIdx.x, ty = threadIdx.y;
    int tid = ty * 65 + tx;
    for (int m = tid; m < 128 * 65; m += 260) Wb_s[m] = Wb[m];
    if (tid < 65) bb_s[tid] = bb[tid];
    __syncthreads();
    for (int base = blockIdx.x * 4; base < N_NODES; base += gridDim.x * 4) {
        int n = base + ty;
        a_s[ty][tx] = a[n * 128 + tx];
        if (tx + 65 < 128) a_s[ty][tx + 65] = a[n * 128 + tx + 65];
        __syncthreads();
        float acc = bb_s[tx];
#pragma unroll 4
        for (int jj = 0; jj < 128; ++jj) acc += a_s[ty][jj] * Wb_s[jj * 65 + tx];
        atomicAdd(&g_pooled[batch[n] * 65 + tx], acc);
        __syncthreads();
    }
}

__global__ void k_final(float* __restrict__ out) {
    int idx = blockIdx.x * blockDim.x + threadIdx.x;
    if (idx < N_GRAPHS * LATENT) {
        int g = idx / LATENT, k = idx % LATENT;
        out[idx] = g_pooled[g * 65 + k];
    } else if (idx < N_GRAPHS * LATENT + N_GRAPHS) {
        int g = idx - N_GRAPHS * LATENT;
        float lv = g_pooled[g * 65 + 64];
        out[idx] = fminf(fmaxf(lv, -10.0f), 2.0f);
    }
}

extern "C" void kernel_launch(void* const* d_in, const int* in_sizes, int n_in,
                              void* d_out, int out_size) {
    (void)in_sizes; (void)n_in; (void)out_size;
    const int* z = (const int*)d_in[0];
    const float* pos = (const float*)d_in[1];
    const int* batch = (const int*)d_in[2];
    const int* ei = (const int*)d_in[3];
    const float* embed = (const float*)d_in[4];
    const float* W_rbf = (const float*)d_in[5];
    const float* W1 = (const float*)d_in[6];
    const float* Wo = (const float*)d_in[7];
    const float* Wv = (const float*)d_in[8];
    const float* Wvec2 = (const float*)d_in[10];
    const float* W_a = (const float*)d_in[11];
    const float* b_a = (const float*)d_in[12];
    const float* W_b = (const float*)d_in[13];
    const float* b_b = (const float*)d_in[14];
    float* out = (float*)d_out;

    float *p_x, *p_vec, *p_vmix, *p_dx, *p_vn, *p_a;
    cudaGetSymbolAddress((void**)&p_x, g_x);
    cudaGetSymbolAddress((void**)&p_vec, g_vec);
    cudaGetSymbolAddress((void**)&p_vmix, g_vmix);
    cudaGetSymbolAddress((void**)&p_dx, g_dx);
    cudaGetSymbolAddress((void**)&p_vn, g_vn);
    cudaGetSymbolAddress((void**)&p_a, g_a);

    size_t smem_gemm = (size_t)(128 * PAD + 64 * PAD) * 4;
    size_t smem_edge = (size_t)(128 * PADH + 128 * PADR + 2 * ET * PADH
                                + ET * PADR) * 2 + 192 * 4 + 2 * ET * 4;  // ~86.3 KB
    cudaFuncSetAttribute(k_gemm_mma, cudaFuncAttributeMaxDynamicSharedMemorySize, (int)smem_gemm);
    cudaFuncSetAttribute(k_edge, cudaFuncAttributeMaxDynamicSharedMemorySize, (int)smem_edge);

    k_setup<<<(N_NODES * 384 + 255) / 256, 256>>>(z, embed);
    k_geom<<<(N_EDGES + 255) / 256, 256>>>(pos, ei);

    for (int l = 0; l < 2; ++l) {
        k_gemm_mma<<<296, 256, smem_gemm>>>(p_vec, Wv + l * 128 * 128, nullptr, p_vmix,
                                            N_NODES * 3, 0, 0);
        if (l) k_zero<<<(N_NODES * 128 + 255) / 256, 256>>>(p_dx, N_NODES * 128);
        // fused edge pass — 2 CTAs/SM
        k_edge<<<296, 512, smem_edge>>>(ei, W_rbf + l * 32 * 128, W1 + l * 128 * 128);
        k_gemm_mma<<<157, 256, smem_gemm>>>(p_dx, Wo + l * 128 * 128, nullptr, p_x,
                                            N_NODES, 1, 0);
    }

    k_gemm_mma<<<296, 256, smem_gemm>>>(p_vec, Wvec2, nullptr, p_vmix, N_NODES * 3, 0, 0);
    k_vnorm<<<(N_NODES * 128 + 255) / 256, 256>>>(p_vmix, p_vn);

    k_gemm_mma<<<157, 256, smem_gemm>>>(p_x, W_a, nullptr, p_a, N_NODES, 0, 0);
    k_gemm_mma<<<157, 256, smem_gemm>>>(p_vn, W_a + 128 * 128, b_a, p_a, N_NODES, 1, 1);

    dim3 pb(65, 4);
    k_pool<<<296, pb>>>(p_a, batch, W_b, b_b);

    k_final<<<(N_GRAPHS * LATENT + N_GRAPHS + 255) / 256, 256>>>(out);
}

// round 6
// speedup vs baseline: 4.3568x; 1.0112x over previous
#include <cuda_runtime.h>
#include <cuda_fp16.h>
#include <math.h>

#define N_NODES 10000
#define N_EDGES 160000
#define HIDDEN 128
#define NUM_RBF 32
#define N_GRAPHS 128
#define LATENT 64
#define ET 64            // edges per tile in k_edge
#define PAD 136          // f32 smem stride (node gemm)
#define PADH 136         // half stride for 128-wide rows

// ---------------- scratch ----------------
__device__ float g_x[N_NODES * HIDDEN];
__device__ float g_vec[N_NODES * 3 * HIDDEN];
__device__ float g_vmix[N_NODES * 3 * HIDDEN];
__device__ float g_dx[N_NODES * HIDDEN];
__device__ float g_a[N_NODES * HIDDEN];
__device__ float g_dirn[N_EDGES * 3];
__device__ __half g_rbf[N_EDGES * NUM_RBF];
__device__ unsigned g_wrbfp[2 * 128 * 16];   // packed Wrbf^T half2: [l][n][k/2]
__device__ float g_pooled[N_GRAPHS * 65];

// ---------------- helpers ----------------
__device__ __forceinline__ unsigned f2tf(float f) {
    unsigned r;
    asm("cvt.rna.tf32.f32 %0, %1;" : "=r"(r) : "f"(f));
    return r;
}

__device__ __forceinline__ void mma_tf32(float c[4], unsigned a0, unsigned a1,
                                         unsigned a2, unsigned a3,
                                         unsigned b0, unsigned b1) {
    asm volatile(
        "mma.sync.aligned.m16n8k8.row.col.f32.tf32.tf32.f32 "
        "{%0,%1,%2,%3}, {%4,%5,%6,%7}, {%8,%9}, {%0,%1,%2,%3};"
        : "+f"(c[0]), "+f"(c[1]), "+f"(c[2]), "+f"(c[3])
        : "r"(a0), "r"(a1), "r"(a2), "r"(a3), "r"(b0), "r"(b1));
}

__device__ __forceinline__ void mma_f16(float c[4], unsigned a0, unsigned a1,
                                        unsigned a2, unsigned a3,
                                        unsigned b0, unsigned b1) {
    asm volatile(
        "mma.sync.aligned.m16n8k16.row.col.f32.f16.f16.f32 "
        "{%0,%1,%2,%3}, {%4,%5,%6,%7}, {%8,%9}, {%0,%1,%2,%3};"
        : "+f"(c[0]), "+f"(c[1]), "+f"(c[2]), "+f"(c[3])
        : "r"(a0), "r"(a1), "r"(a2), "r"(a3), "r"(b0), "r"(b1));
}

__device__ __forceinline__ void red4(float* p, float a, float b, float c, float d) {
    unsigned long long addr = (unsigned long long)p;
    asm volatile("red.global.add.v4.f32 [%0], {%1,%2,%3,%4};"
                 :: "l"(addr), "f"(a), "f"(b), "f"(c), "f"(d) : "memory");
}

__device__ __forceinline__ float silu(float v) {
    return __fdividef(v, 1.0f + __expf(-v));
}

#define H2U(p) (*(const unsigned*)(p))

// ---------------- setup: zero scratch + embed gather + Wrbf pack ----------------
__global__ void k_setup(const int* __restrict__ z, const float* __restrict__ emb,
                        const float* __restrict__ W_rbf) {
    int i = blockIdx.x * blockDim.x + threadIdx.x;
    if (i < N_NODES * 384) g_vec[i] = 0.0f;
    if (i < N_NODES * 128) {
        g_dx[i] = 0.0f;
        int n = i >> 7, j = i & 127;
        g_x[i] = emb[z[n] * HIDDEN + j];
    }
    if (i < N_GRAPHS * 65) g_pooled[i] = 0.0f;
    if (i < 2 * 128 * 16) {
        int l = i >> 11, n = (i >> 4) & 127, kk = i & 15;
        const float* base = W_rbf + l * 32 * 128;
        __half lo = __float2half(base[(2 * kk) * 128 + n]);
        __half hi = __float2half(base[(2 * kk + 1) * 128 + n]);
        __half2 h2 = __halves2half2(lo, hi);
        g_wrbfp[i] = *(unsigned*)&h2;
    }
}

__global__ void k_zero(float* p, int n) {
    int i = blockIdx.x * blockDim.x + threadIdx.x;
    if (i < n) p[i] = 0.0f;
}

// edge geometry: dirn + windowed expnorm RBF (half output)
__global__ void k_geom(const float* __restrict__ pos, const int* __restrict__ ei) {
    int e = blockIdx.x * blockDim.x + threadIdx.x;
    if (e >= N_EDGES) return;
    int s = ei[e], d = ei[N_EDGES + e];
    float dx = pos[d * 3 + 0] - pos[s * 3 + 0];
    float dy = pos[d * 3 + 1] - pos[s * 3 + 1];
    float dz = pos[d * 3 + 2] - pos[s * 3 + 2];
    float r = sqrtf(dx * dx + dy * dy + dz * dz + 1e-8f);
    float inv = 1.0f / r;
    g_dirn[e * 3 + 0] = dx * inv;
    g_dirn[e * 3 + 1] = dy * inv;
    g_dirn[e * 3 + 2] = dz * inv;

    uint4* rp = (uint4*)&g_rbf[e * 32];
    uint4 z4 = make_uint4(0, 0, 0, 0);
    rp[0] = z4; rp[1] = z4; rp[2] = z4; rp[3] = z4;

    if (r < 5.0f) {
        const float c0 = 0.006737946999085467f;          // exp(-5)
        const float step = (1.0f - c0) / 31.0f;
        const float tmp = (2.0f / 32.0f) * (1.0f - c0);
        const float beta = 1.0f / (tmp * tmp);
        float cut = 0.5f * (__cosf(0.6283185307179586f * r) + 1.0f);
        float er = __expf(-r);
        int kc = (int)((er - c0) * (1.0f / step));
        int base = kc - 8;
        base = base < 0 ? 0 : (base > 15 ? 15 : base);
#pragma unroll
        for (int kk = 0; kk < 17; ++kk) {
            int k = base + kk;
            float m = c0 + (float)k * step;
            float dd = er - m;
            g_rbf[e * 32 + k] = __float2half(cut * __expf(-beta * dd * dd));
        }
    }
}

// ---------------- tensor-core node GEMM (tf32) ----------------
// vnorm=1: A is v2 [R][3][128]; staged value = sqrt(sum_c v2[r][c][j]^2 + eps)
__global__ __launch_bounds__(256) void k_gemm_mma(
    const float* __restrict__ A, const float* __restrict__ W,
    const float* __restrict__ bias, float* __restrict__ C,
    int R, int accum, int act, int vnorm) {
    extern __shared__ float sm[];
    unsigned* W_u = (unsigned*)sm;
    unsigned* A_u = (unsigned*)(sm + 128 * PAD);
    int tid = threadIdx.x;
    int w = tid >> 5, lane = tid & 31, gid = lane >> 2, tig = lane & 3;

    for (int m4 = tid; m4 < 128 * 32; m4 += 256) {
        int i = m4 >> 5, j = (m4 & 31) * 4;
        float4 v = *(const float4*)&W[i * 128 + j];
        *(uint4*)&W_u[i * PAD + j] =
            make_uint4(f2tf(v.x), f2tf(v.y), f2tf(v.z), f2tf(v.w));
    }
    __syncthreads();

    int m0 = (w & 3) * 16;
    int nbase = (w >> 2) * 64;
    int nT = (R + 63) >> 6;
    for (int t = blockIdx.x; t < nT; t += gridDim.x) {
        int r0 = t << 6;
        for (int m4 = tid; m4 < 64 * 32; m4 += 256) {
            int r = m4 >> 5, c = (m4 & 31) * 4;
            int rr = r0 + r;
            float4 v = make_float4(0.f, 0.f, 0.f, 0.f);
            if (rr < R) {
                if (vnorm) {
                    float4 a0 = *(const float4*)&A[(rr * 3 + 0) * 128 + c];
                    float4 a1 = *(const float4*)&A[(rr * 3 + 1) * 128 + c];
                    float4 a2 = *(const float4*)&A[(rr * 3 + 2) * 128 + c];
                    v.x = sqrtf(a0.x * a0.x + a1.x * a1.x + a2.x * a2.x + 1e-8f);
                    v.y = sqrtf(a0.y * a0.y + a1.y * a1.y + a2.y * a2.y + 1e-8f);
                    v.z = sqrtf(a0.z * a0.z + a1.z * a1.z + a2.z * a2.z + 1e-8f);
                    v.w = sqrtf(a0.w * a0.w + a1.w * a1.w + a2.w * a2.w + 1e-8f);
                } else {
                    v = *(const float4*)&A[rr * 128 + c];
                }
            }
            *(uint4*)&A_u[r * PAD + c] =
                make_uint4(f2tf(v.x), f2tf(v.y), f2tf(v.z), f2tf(v.w));
        }
        __syncthreads();

        float acc[8][4];
#pragma unroll
        for (int it = 0; it < 8; ++it)
#pragma unroll
            for (int q = 0; q < 4; ++q) acc[it][q] = 0.0f;

#pragma unroll
        for (int ks = 0; ks < 16; ++ks) {
            int k0 = ks * 8;
            unsigned a0 = A_u[(m0 + gid) * PAD + k0 + tig];
            unsigned a1 = A_u[(m0 + gid + 8) * PAD + k0 + tig];
            unsigned a2 = A_u[(m0 + gid) * PAD + k0 + tig + 4];
            unsigned a3 = A_u[(m0 + gid + 8) * PAD + k0 + tig + 4];
#pragma unroll
            for (int it = 0; it < 8; ++it) {
                int n0 = nbase + it * 8;
                unsigned b0 = W_u[(k0 + tig) * PAD + n0 + gid];
                unsigned b1 = W_u[(k0 + tig + 4) * PAD + n0 + gid];
                mma_tf32(acc[it], a0, a1, a2, a3, b0, b1);
            }
        }

#pragma unroll
        for (int it = 0; it < 8; ++it) {
            int n0 = nbase + it * 8;
            int col = n0 + 2 * tig;
            float bb0 = bias ? bias[col] : 0.0f;
            float bb1 = bias ? bias[col + 1] : 0.0f;
#pragma unroll
            for (int h = 0; h < 2; ++h) {
                int row = r0 + m0 + gid + h * 8;
                if (row < R) {
                    float v0 = acc[it][2 * h + 0] + bb0;
                    float v1 = acc[it][2 * h + 1] + bb1;
                    if (accum) {
                        v0 += C[row * 128 + col];
                        v1 += C[row * 128 + col + 1];
                    }
                    if (act) { v0 = silu(v0); v1 = silu(v1); }
                    C[row * 128 + col] = v0;
                    C[row * 128 + col + 1] = v1;
                }
            }
        }
        __syncthreads();
    }
}

// ---------------- fused fp16 edge kernel (512 threads, 3 CTAs/SM) ----------------
__global__ __launch_bounds__(512, 3) void k_edge(
    const int* __restrict__ ei, const unsigned* __restrict__ wrbfp,
    const float* __restrict__ W1) {
    extern __shared__ __half smh[];
    __half* W1T    = smh;                      // [128 n][PADH k]  34816 B
    __half* filt_h = W1T + 128 * PADH;         // [64 e][PADH c]   17408 B
    __half* t_h    = filt_h + ET * PADH;       // [64 e][PADH k]   17408 B (phi alias)
    float* dirn_s = (float*)(t_h + ET * PADH); // 768 B
    int* src_s = (int*)(dirn_s + 192);         // 256 B
    int* dst_s = src_s + ET;                   // 256 B

    int tid = threadIdx.x;
    int w = tid >> 5, lane = tid & 31, gid = lane >> 2, tig = lane & 3;

    // stage W1 transposed to [n][k] half
    for (int m = tid; m < 128 * 128; m += 512) {
        int i = m >> 7, j = m & 127;   // i=k, j=n
        W1T[j * PADH + i] = __float2half(W1[m]);
    }

    int m0 = (w & 3) * 16;       // edge-row block
    int nbase = (w >> 2) * 32;   // channel block
    int c4 = lane * 4;

    int nTiles = N_EDGES / ET;
    for (int t = blockIdx.x; t < nTiles; t += gridDim.x) {
        int e0 = t * ET;
        __syncthreads();  // prev tile consumed / W1 staging done

        if (tid < ET) src_s[tid] = ei[e0 + tid];
        else if (tid < 2 * ET) dst_s[tid - ET] = ei[N_EDGES + e0 + (tid - ET)];
        if (tid < ET * 3) dirn_s[tid] = g_dirn[e0 * 3 + tid];
        __syncthreads();

        // filt = rbf @ Wrbf  (M=64, N=128, K=32); A from gmem rbf, B from packed gmem
        {
            float acc[4][4];
#pragma unroll
            for (int it = 0; it < 4; ++it)
#pragma unroll
                for (int q = 0; q < 4; ++q) acc[it][q] = 0.0f;
#pragma unroll
            for (int ks = 0; ks < 2; ++ks) {
                int k0 = ks * 16;
                unsigned a0 = H2U(&g_rbf[(e0 + m0 + gid) * 32 + k0 + 2 * tig]);
                unsigned a1 = H2U(&g_rbf[(e0 + m0 + gid + 8) * 32 + k0 + 2 * tig]);
                unsigned a2 = H2U(&g_rbf[(e0 + m0 + gid) * 32 + k0 + 2 * tig + 8]);
                unsigned a3 = H2U(&g_rbf[(e0 + m0 + gid + 8) * 32 + k0 + 2 * tig + 8]);
#pragma unroll
                for (int it = 0; it < 4; ++it) {
                    int n0 = nbase + it * 8;
                    unsigned b0 = wrbfp[(n0 + gid) * 16 + 8 * ks + tig];
                    unsigned b1 = wrbfp[(n0 + gid) * 16 + 8 * ks + tig + 4];
                    mma_f16(acc[it], a0, a1, a2, a3, b0, b1);
                }
            }
#pragma unroll
            for (int it = 0; it < 4; ++it) {
                int n0 = nbase + it * 8;
                *(__half2*)&filt_h[(m0 + gid) * PADH + n0 + 2 * tig] =
                    __floats2half2_rn(acc[it][0], acc[it][1]);
                *(__half2*)&filt_h[(m0 + gid + 8) * PADH + n0 + 2 * tig] =
                    __floats2half2_rn(acc[it][2], acc[it][3]);
            }
        }
        __syncthreads();

        // t[e][c] = x[src[e]][c] * filt[e][c]  — warp per edge
#pragma unroll
        for (int q = 0; q < 4; ++q) {
            int e = w + 16 * q;
            int s = src_s[e];
            float4 xv = *(const float4*)&g_x[s * 128 + c4];
            float2 f01 = __half22float2(*(__half2*)&filt_h[e * PADH + c4]);
            float2 f23 = __half22float2(*(__half2*)&filt_h[e * PADH + c4 + 2]);
            *(__half2*)&t_h[e * PADH + c4] = __floats2half2_rn(xv.x * f01.x, xv.y * f01.y);
            *(__half2*)&t_h[e * PADH + c4 + 2] = __floats2half2_rn(xv.z * f23.x, xv.w * f23.y);
        }
        __syncthreads();

        // phi = t @ W1  (M=64, N=128, K=128) fp16 mma
        float acc[4][4];
#pragma unroll
        for (int it = 0; it < 4; ++it)
#pragma unroll
            for (int q = 0; q < 4; ++q) acc[it][q] = 0.0f;
#pragma unroll
        for (int ks = 0; ks < 8; ++ks) {
            int k0 = ks * 16;
            unsigned a0 = H2U(&t_h[(m0 + gid) * PADH + k0 + 2 * tig]);
            unsigned a1 = H2U(&t_h[(m0 + gid + 8) * PADH + k0 + 2 * tig]);
            unsigned a2 = H2U(&t_h[(m0 + gid) * PADH + k0 + 2 * tig + 8]);
            unsigned a3 = H2U(&t_h[(m0 + gid + 8) * PADH + k0 + 2 * tig + 8]);
#pragma unroll
            for (int it = 0; it < 4; ++it) {
                int n0 = nbase + it * 8;
                unsigned b0 = H2U(&W1T[(n0 + gid) * PADH + k0 + 2 * tig]);
                unsigned b1 = H2U(&W1T[(n0 + gid) * PADH + k0 + 2 * tig + 8]);
                mma_f16(acc[it], a0, a1, a2, a3, b0, b1);
            }
        }
        __syncthreads();  // t reads complete before phi alias write

#pragma unroll
        for (int it = 0; it < 4; ++it) {
            int n0 = nbase + it * 8;
            *(__half2*)&t_h[(m0 + gid) * PADH + n0 + 2 * tig] =
                __floats2half2_rn(silu(acc[it][0]), silu(acc[it][1]));
            *(__half2*)&t_h[(m0 + gid + 8) * PADH + n0 + 2 * tig] =
                __floats2half2_rn(silu(acc[it][2]), silu(acc[it][3]));
        }
        __syncthreads();

        // scatter — warp per edge, vector REDs
#pragma unroll
        for (int q = 0; q < 4; ++q) {
            int e = w + 16 * q;
            int s = src_s[e], d = dst_s[e];
            float2 p01 = __half22float2(*(__half2*)&t_h[e * PADH + c4]);
            float2 p23 = __half22float2(*(__half2*)&t_h[e * PADH + c4 + 2]);
            float2 f01 = __half22float2(*(__half2*)&filt_h[e * PADH + c4]);
            float2 f23 = __half22float2(*(__half2*)&filt_h[e * PADH + c4 + 2]);
            float d0 = dirn_s[e * 3 + 0];
            float d1 = dirn_s[e * 3 + 1];
            float d2 = dirn_s[e * 3 + 2];
            red4(&g_dx[d * 128 + c4], p01.x, p01.y, p23.x, p23.y);
            float4 m0v = *(const float4*)&g_vmix[(s * 3 + 0) * 128 + c4];
            red4(&g_vec[(d * 3 + 0) * 128 + c4],
                 m0v.x * f01.x + p01.x * d0, m0v.y * f01.y + p01.y * d0,
                 m0v.z * f23.x + p23.x * d0, m0v.w * f23.y + p23.y * d0);
            float4 m1v = *(const float4*)&g_vmix[(s * 3 + 1) * 128 + c4];
            red4(&g_vec[(d * 3 + 1) * 128 + c4],
                 m1v.x * f01.x + p01.x * d1, m1v.y * f01.y + p01.y * d1,
                 m1v.z * f23.x + p23.x * d1, m1v.w * f23.y + p23.y * d1);
            float4 m2v = *(const float4*)&g_vmix[(s * 3 + 2) * 128 + c4];
            red4(&g_vec[(d * 3 + 2) * 128 + c4],
                 m2v.x * f01.x + p01.x * d2, m2v.y * f01.y + p01.y * d2,
                 m2v.z * f23.x + p23.x * d2, m2v.w * f23.y + p23.y * d2);
        }
    }
}

__global__ void k_pool(const float* __restrict__ a, const int* __restrict__ batch,
                       const float* __restrict__ Wb, const float* __restrict__ bb) {
    __shared__ float Wb_s[128 * 65];
    __shared__ float bb_s[65];
    __shared__ float a_s[4][128];
    int tx = threadIdx.x, ty = threadIdx.y;
    int tid = ty * 65 + tx;
    for (int m = tid; m < 128 * 65; m += 260) Wb_s[m] = Wb[m];
    if (tid < 65) bb_s[tid] = bb[tid];
    __syncthreads();
    for (int base = blockIdx.x * 4; base < N_NODES; base += gridDim.x * 4) {
        int n = base + ty;
        a_s[ty][tx] = a[n * 128 + tx];
        if (tx + 65 < 128) a_s[ty][tx + 65] = a[n * 128 + tx + 65];
        __syncthreads();
        float acc = bb_s[tx];
#pragma unroll 4
        for (int jj = 0; jj < 128; ++jj) acc += a_s[ty][jj] * Wb_s[jj * 65 + tx];
        atomicAdd(&g_pooled[batch[n] * 65 + tx], acc);
        __syncthreads();
    }
}

__global__ void k_final(float* __restrict__ out) {
    int idx = blockIdx.x * blockDim.x + threadIdx.x;
    if (idx < N_GRAPHS * LATENT) {
        int g = idx / LATENT, k = idx % LATENT;
        out[idx] = g_pooled[g * 65 + k];
    } else if (idx < N_GRAPHS * LATENT + N_GRAPHS) {
        int g = idx - N_GRAPHS * LATENT;
        float lv = g_pooled[g * 65 + 64];
        out[idx] = fminf(fmaxf(lv, -10.0f), 2.0f);
    }
}

extern "C" void kernel_launch(void* const* d_in, const int* in_sizes, int n_in,
                              void* d_out, int out_size) {
    (void)in_sizes; (void)n_in; (void)out_size;
    const int* z = (const int*)d_in[0];
    const float* pos = (const float*)d_in[1];
    const int* batch = (const int*)d_in[2];
    const int* ei = (const int*)d_in[3];
    const float* embed = (const float*)d_in[4];
    const float* W_rbf = (const float*)d_in[5];
    const float* W1 = (const float*)d_in[6];
    const float* Wo = (const float*)d_in[7];
    const float* Wv = (const float*)d_in[8];
    const float* Wvec2 = (const float*)d_in[10];
    const float* W_a = (const float*)d_in[11];
    const float* b_a = (const float*)d_in[12];
    const float* W_b = (const float*)d_in[13];
    const float* b_b = (const float*)d_in[14];
    float* out = (float*)d_out;

    float *p_x, *p_vec, *p_vmix, *p_dx, *p_a;
    unsigned* p_wrbfp;
    cudaGetSymbolAddress((void**)&p_x, g_x);
    cudaGetSymbolAddress((void**)&p_vec, g_vec);
    cudaGetSymbolAddress((void**)&p_vmix, g_vmix);
    cudaGetSymbolAddress((void**)&p_dx, g_dx);
    cudaGetSymbolAddress((void**)&p_a, g_a);
    cudaGetSymbolAddress((void**)&p_wrbfp, g_wrbfp);

    size_t smem_gemm = (size_t)(128 * PAD + 64 * PAD) * 4;
    size_t smem_edge = (size_t)(128 * PADH + 2 * ET * PADH) * 2
                       + 192 * 4 + 2 * ET * 4;  // ~69.3 KB
    cudaFuncSetAttribute(k_gemm_mma, cudaFuncAttributeMaxDynamicSharedMemorySize, (int)smem_gemm);
    cudaFuncSetAttribute(k_edge, cudaFuncAttributeMaxDynamicSharedMemorySize, (int)smem_edge);

    k_setup<<<(N_NODES * 384 + 255) / 256, 256>>>(z, embed, W_rbf);
    k_geom<<<(N_EDGES + 255) / 256, 256>>>(pos, ei);

    for (int l = 0; l < 2; ++l) {
        k_gemm_mma<<<296, 256, smem_gemm>>>(p_vec, Wv + l * 128 * 128, nullptr, p_vmix,
                                            N_NODES * 3, 0, 0, 0);
        if (l) k_zero<<<(N_NODES * 128 + 255) / 256, 256>>>(p_dx, N_NODES * 128);
        // fused edge pass — 3 CTAs/SM
        k_edge<<<444, 512, smem_edge>>>(ei, p_wrbfp + l * 128 * 16, W1 + l * 128 * 128);
        k_gemm_mma<<<157, 256, smem_gemm>>>(p_dx, Wo + l * 128 * 128, nullptr, p_x,
                                            N_NODES, 1, 0, 0);
    }

    // v2 = vec @ Wvec2 (reuse vmix buffer)
    k_gemm_mma<<<296, 256, smem_gemm>>>(p_vec, Wvec2, nullptr, p_vmix, N_NODES * 3, 0, 0, 0);

    // a = silu(x @ Wa_top + vnorm(v2) @ Wa_bot + b_a)  — vnorm fused into A-staging
    k_gemm_mma<<<157, 256, smem_gemm>>>(p_x, W_a, nullptr, p_a, N_NODES, 0, 0, 0);
    k_gemm_mma<<<157, 256, smem_gemm>>>(p_vmix, W_a + 128 * 128, b_a, p_a, N_NODES, 1, 1, 1);

    dim3 pb(65, 4);
    k_pool<<<296, pb>>>(p_a, batch, W_b, b_b);

    k_final<<<(N_GRAPHS * LATENT + N_GRAPHS + 255) / 256, 256>>>(out);
}

// round 8
// speedup vs baseline: 4.3633x; 1.0015x over previous
#include <cuda_runtime.h>
#include <cuda_fp16.h>
#include <math.h>

#define N_NODES 10000
#define N_EDGES 160000
#define HIDDEN 128
#define NUM_RBF 32
#define N_GRAPHS 128
#define LATENT 64
#define ET 64            // edges per tile in k_edge
#define PAD 136          // f32 smem stride (node gemm)
#define PADH 136         // half stride for 128-wide rows

// ---------------- scratch ----------------
__device__ float g_x[N_NODES * HIDDEN];
__device__ float g_vec[N_NODES * 3 * HIDDEN];
__device__ float g_vmix[N_NODES * 3 * HIDDEN];
__device__ float g_dx[N_NODES * HIDDEN];
__device__ float g_a[N_NODES * HIDDEN];
__device__ float g_dirn[N_EDGES * 3];
__device__ __half g_rbf[N_EDGES * NUM_RBF];
__device__ unsigned g_wrbfp[2 * 128 * 16];   // packed Wrbf^T half2: [l][n][k/2]
__device__ float g_pooled[N_GRAPHS * 65];

// ---------------- helpers ----------------
__device__ __forceinline__ unsigned f2tf(float f) {
    unsigned r;
    asm("cvt.rna.tf32.f32 %0, %1;" : "=r"(r) : "f"(f));
    return r;
}

__device__ __forceinline__ void mma_tf32(float c[4], unsigned a0, unsigned a1,
                                         unsigned a2, unsigned a3,
                                         unsigned b0, unsigned b1) {
    asm volatile(
        "mma.sync.aligned.m16n8k8.row.col.f32.tf32.tf32.f32 "
        "{%0,%1,%2,%3}, {%4,%5,%6,%7}, {%8,%9}, {%0,%1,%2,%3};"
        : "+f"(c[0]), "+f"(c[1]), "+f"(c[2]), "+f"(c[3])
        : "r"(a0), "r"(a1), "r"(a2), "r"(a3), "r"(b0), "r"(b1));
}

__device__ __forceinline__ void mma_f16(float c[4], unsigned a0, unsigned a1,
                                        unsigned a2, unsigned a3,
                                        unsigned b0, unsigned b1) {
    asm volatile(
        "mma.sync.aligned.m16n8k16.row.col.f32.f16.f16.f32 "
        "{%0,%1,%2,%3}, {%4,%5,%6,%7}, {%8,%9}, {%0,%1,%2,%3};"
        : "+f"(c[0]), "+f"(c[1]), "+f"(c[2]), "+f"(c[3])
        : "r"(a0), "r"(a1), "r"(a2), "r"(a3), "r"(b0), "r"(b1));
}

__device__ __forceinline__ void ldsm_x4(unsigned& r0, unsigned& r1,
                                        unsigned& r2, unsigned& r3, unsigned addr) {
    asm volatile("ldmatrix.sync.aligned.m8n8.x4.shared.b16 {%0,%1,%2,%3}, [%4];"
                 : "=r"(r0), "=r"(r1), "=r"(r2), "=r"(r3) : "r"(addr));
}

__device__ __forceinline__ void red4(float* p, float a, float b, float c, float d) {
    unsigned long long addr = (unsigned long long)p;
    asm volatile("red.global.add.v4.f32 [%0], {%1,%2,%3,%4};"
                 :: "l"(addr), "f"(a), "f"(b), "f"(c), "f"(d) : "memory");
}

__device__ __forceinline__ float silu(float v) {
    return __fdividef(v, 1.0f + __expf(-v));
}

#define H2U(p) (*(const unsigned*)(p))

// ---------------- setup: zero scratch + embed gather + Wrbf pack ----------------
__global__ void k_setup(const int* __restrict__ z, const float* __restrict__ emb,
                        const float* __restrict__ W_rbf) {
    int i = blockIdx.x * blockDim.x + threadIdx.x;
    if (i < N_NODES * 384) g_vec[i] = 0.0f;
    if (i < N_NODES * 128) {
        g_dx[i] = 0.0f;
        int n = i >> 7, j = i & 127;
        g_x[i] = emb[z[n] * HIDDEN + j];
    }
    if (i < N_GRAPHS * 65) g_pooled[i] = 0.0f;
    if (i < 2 * 128 * 16) {
        int l = i >> 11, n = (i >> 4) & 127, kk = i & 15;
        const float* base = W_rbf + l * 32 * 128;
        __half lo = __float2half(base[(2 * kk) * 128 + n]);
        __half hi = __float2half(base[(2 * kk + 1) * 128 + n]);
        __half2 h2 = __halves2half2(lo, hi);
        g_wrbfp[i] = *(unsigned*)&h2;
    }
}

__global__ void k_zero(float* p, int n) {
    int i = blockIdx.x * blockDim.x + threadIdx.x;
    if (i < n) p[i] = 0.0f;
}

// edge geometry: dirn + windowed expnorm RBF (half output)
__global__ void k_geom(const float* __restrict__ pos, const int* __restrict__ ei) {
    int e = blockIdx.x * blockDim.x + threadIdx.x;
    if (e >= N_EDGES) return;
    int s = ei[e], d = ei[N_EDGES + e];
    float dx = pos[d * 3 + 0] - pos[s * 3 + 0];
    float dy = pos[d * 3 + 1] - pos[s * 3 + 1];
    float dz = pos[d * 3 + 2] - pos[s * 3 + 2];
    float r = sqrtf(dx * dx + dy * dy + dz * dz + 1e-8f);
    float inv = 1.0f / r;
    g_dirn[e * 3 + 0] = dx * inv;
    g_dirn[e * 3 + 1] = dy * inv;
    g_dirn[e * 3 + 2] = dz * inv;

    uint4* rp = (uint4*)&g_rbf[e * 32];
    uint4 z4 = make_uint4(0, 0, 0, 0);
    rp[0] = z4; rp[1] = z4; rp[2] = z4; rp[3] = z4;

    if (r < 5.0f) {
        const float c0 = 0.006737946999085467f;          // exp(-5)
        const float step = (1.0f - c0) / 31.0f;
        const float tmp = (2.0f / 32.0f) * (1.0f - c0);
        const float beta = 1.0f / (tmp * tmp);
        float cut = 0.5f * (__cosf(0.6283185307179586f * r) + 1.0f);
        float er = __expf(-r);
        int kc = (int)((er - c0) * (1.0f / step));
        int base = kc - 8;
        base = base < 0 ? 0 : (base > 15 ? 15 : base);
#pragma unroll
        for (int kk = 0; kk < 17; ++kk) {
            int k = base + kk;
            float m = c0 + (float)k * step;
            float dd = er - m;
            g_rbf[e * 32 + k] = __float2half(cut * __expf(-beta * dd * dd));
        }
    }
}

// ---------------- tensor-core node GEMM (tf32) ----------------
__global__ __launch_bounds__(256) void k_gemm_mma(
    const float* __restrict__ A, const float* __restrict__ W,
    const float* __restrict__ bias, float* __restrict__ C,
    int R, int accum, int act, int vnorm) {
    extern __shared__ float sm[];
    unsigned* W_u = (unsigned*)sm;
    unsigned* A_u = (unsigned*)(sm + 128 * PAD);
    int tid = threadIdx.x;
    int w = tid >> 5, lane = tid & 31, gid = lane >> 2, tig = lane & 3;

    for (int m4 = tid; m4 < 128 * 32; m4 += 256) {
        int i = m4 >> 5, j = (m4 & 31) * 4;
        float4 v = *(const float4*)&W[i * 128 + j];
        *(uint4*)&W_u[i * PAD + j] =
            make_uint4(f2tf(v.x), f2tf(v.y), f2tf(v.z), f2tf(v.w));
    }
    __syncthreads();

    int m0 = (w & 3) * 16;
    int nbase = (w >> 2) * 64;
    int nT = (R + 63) >> 6;
    for (int t = blockIdx.x; t < nT; t += gridDim.x) {
        int r0 = t << 6;
        for (int m4 = tid; m4 < 64 * 32; m4 += 256) {
            int r = m4 >> 5, c = (m4 & 31) * 4;
            int rr = r0 + r;
            float4 v = make_float4(0.f, 0.f, 0.f, 0.f);
            if (rr < R) {
                if (vnorm) {
                    float4 a0 = *(const float4*)&A[(rr * 3 + 0) * 128 + c];
                    float4 a1 = *(const float4*)&A[(rr * 3 + 1) * 128 + c];
                    float4 a2 = *(const float4*)&A[(rr * 3 + 2) * 128 + c];
                    v.x = sqrtf(a0.x * a0.x + a1.x * a1.x + a2.x * a2.x + 1e-8f);
                    v.y = sqrtf(a0.y * a0.y + a1.y * a1.y + a2.y * a2.y + 1e-8f);
                    v.z = sqrtf(a0.z * a0.z + a1.z * a1.z + a2.z * a2.z + 1e-8f);
                    v.w = sqrtf(a0.w * a0.w + a1.w * a1.w + a2.w * a2.w + 1e-8f);
                } else {
                    v = *(const float4*)&A[rr * 128 + c];
                }
            }
            *(uint4*)&A_u[r * PAD + c] =
                make_uint4(f2tf(v.x), f2tf(v.y), f2tf(v.z), f2tf(v.w));
        }
        __syncthreads();

        float acc[8][4];
#pragma unroll
        for (int it = 0; it < 8; ++it)
#pragma unroll
            for (int q = 0; q < 4; ++q) acc[it][q] = 0.0f;

#pragma unroll
        for (int ks = 0; ks < 16; ++ks) {
            int k0 = ks * 8;
            unsigned a0 = A_u[(m0 + gid) * PAD + k0 + tig];
            unsigned a1 = A_u[(m0 + gid + 8) * PAD + k0 + tig];
            unsigned a2 = A_u[(m0 + gid) * PAD + k0 + tig + 4];
            unsigned a3 = A_u[(m0 + gid + 8) * PAD + k0 + tig + 4];
#pragma unroll
            for (int it = 0; it < 8; ++it) {
                int n0 = nbase + it * 8;
                unsigned b0 = W_u[(k0 + tig) * PAD + n0 + gid];
                unsigned b1 = W_u[(k0 + tig + 4) * PAD + n0 + gid];
                mma_tf32(acc[it], a0, a1, a2, a3, b0, b1);
            }
        }

#pragma unroll
        for (int it = 0; it < 8; ++it) {
            int n0 = nbase + it * 8;
            int col = n0 + 2 * tig;
            float bb0 = bias ? bias[col] : 0.0f;
            float bb1 = bias ? bias[col + 1] : 0.0f;
#pragma unroll
            for (int h = 0; h < 2; ++h) {
                int row = r0 + m0 + gid + h * 8;
                if (row < R) {
                    float v0 = acc[it][2 * h + 0] + bb0;
                    float v1 = acc[it][2 * h + 1] + bb1;
                    if (accum) {
                        v0 += C[row * 128 + col];
                        v1 += C[row * 128 + col + 1];
                    }
                    if (act) { v0 = silu(v0); v1 = silu(v1); }
                    C[row * 128 + col] = v0;
                    C[row * 128 + col + 1] = v1;
                }
            }
        }
        __syncthreads();
    }
}

// ---------------- fused fp16 edge kernel (512 threads, 3 CTAs/SM, LDSM frags) ----------------
__global__ __launch_bounds__(512, 3) void k_edge(
    const int* __restrict__ ei, const unsigned* __restrict__ wrbfp,
    const float* __restrict__ W1) {
    extern __shared__ __half smh[];
    __half* W1T    = smh;                      // [128 n][PADH k]  34816 B
    __half* filt_h = W1T + 128 * PADH;         // [64 e][PADH c]   17408 B
    __half* t_h    = filt_h + ET * PADH;       // [64 e][PADH k]   17408 B (phi alias)
    float* dirn_s = (float*)(t_h + ET * PADH); // 768 B
    int* src_s = (int*)(dirn_s + 192);         // 256 B
    int* dst_s = src_s + ET;                   // 256 B

    int tid = threadIdx.x;
    int w = tid >> 5, lane = tid & 31, gid = lane >> 2, tig = lane & 3;

    // stage W1 transposed to [n][k] half
    for (int m = tid; m < 128 * 128; m += 512) {
        int i = m >> 7, j = m & 127;   // i=k, j=n
        W1T[j * PADH + i] = __float2half(W1[m]);
    }

    int m0 = (w & 3) * 16;       // edge-row block
    int nbase = (w >> 2) * 32;   // channel block
    int c4 = lane * 4;

    // ldmatrix lane addresses (byte offsets into shared)
    int sec = lane >> 3, r8 = lane & 7;
    unsigned t_base  = (unsigned)__cvta_generic_to_shared(t_h);
    unsigned w1_base = (unsigned)__cvta_generic_to_shared(W1T);
    // A frags from t_h: row = m0 + r8 + (sec&1)*8, col off = (sec>>1)*8
    unsigned aAddr = t_base +
        (((m0 + r8 + ((sec & 1) << 3)) * PADH + ((sec >> 1) << 3)) << 1);
    // B frags from W1T: row n = nb + r8 + (sec>>1)*8, col off = (sec&1)*8
    unsigned bAddr1 = w1_base +
        (((nbase + r8 + ((sec >> 1) << 3)) * PADH + ((sec & 1) << 3)) << 1);
    unsigned bAddr2 = bAddr1 + ((16 * PADH) << 1);

    int nTiles = N_EDGES / ET;
    for (int t = blockIdx.x; t < nTiles; t += gridDim.x) {
        int e0 = t * ET;
        __syncthreads();  // prev tile consumed / W1 staging done

        if (tid < ET) src_s[tid] = ei[e0 + tid];
        else if (tid < 2 * ET) dst_s[tid - ET] = ei[N_EDGES + e0 + (tid - ET)];
        if (tid < ET * 3) dirn_s[tid] = g_dirn[e0 * 3 + tid];
        __syncthreads();

        // filt = rbf @ Wrbf  (M=64, N=128, K=32); A from gmem rbf, B from packed gmem
        {
            float acc[4][4];
#pragma unroll
            for (int it = 0; it < 4; ++it)
#pragma unroll
                for (int q = 0; q < 4; ++q) acc[it][q] = 0.0f;
#pragma unroll
            for (int ks = 0; ks < 2; ++ks) {
                int k0 = ks * 16;
                unsigned a0 = H2U(&g_rbf[(e0 + m0 + gid) * 32 + k0 + 2 * tig]);
                unsigned a1 = H2U(&g_rbf[(e0 + m0 + gid + 8) * 32 + k0 + 2 * tig]);
                unsigned a2 = H2U(&g_rbf[(e0 + m0 + gid) * 32 + k0 + 2 * tig + 8]);
                unsigned a3 = H2U(&g_rbf[(e0 + m0 + gid + 8) * 32 + k0 + 2 * tig + 8]);
#pragma unroll
                for (int it = 0; it < 4; ++it) {
                    int n0 = nbase + it * 8;
                    unsigned b0 = wrbfp[(n0 + gid) * 16 + 8 * ks + tig];
                    unsigned b1 = wrbfp[(n0 + gid) * 16 + 8 * ks + tig + 4];
                    mma_f16(acc[it], a0, a1, a2, a3, b0, b1);
                }
            }
#pragma unroll
            for (int it = 0; it < 4; ++it) {
                int n0 = nbase + it * 8;
                *(__half2*)&filt_h[(m0 + gid) * PADH + n0 + 2 * tig] =
                    __floats2half2_rn(acc[it][0], acc[it][1]);
                *(__half2*)&filt_h[(m0 + gid + 8) * PADH + n0 + 2 * tig] =
                    __floats2half2_rn(acc[it][2], acc[it][3]);
            }
        }
        __syncthreads();

        // t[e][c] = x[src[e]][c] * filt[e][c]  — warp per edge
#pragma unroll
        for (int q = 0; q < 4; ++q) {
            int e = w + 16 * q;
            int s = src_s[e];
            float4 xv = *(const float4*)&g_x[s * 128 + c4];
            uint2 fu = *(const uint2*)&filt_h[e * PADH + c4];   // 4 halves
            float2 f01 = __half22float2(*(__half2*)&fu.x);
            float2 f23 = __half22float2(*(__half2*)&fu.y);
            __half2 h0 = __floats2half2_rn(xv.x * f01.x, xv.y * f01.y);
            __half2 h1 = __floats2half2_rn(xv.z * f23.x, xv.w * f23.y);
            uint2 tu = make_uint2(*(unsigned*)&h0, *(unsigned*)&h1);
            *(uint2*)&t_h[e * PADH + c4] = tu;
        }
        __syncthreads();

        // phi = t @ W1  (M=64, N=128, K=128) fp16 mma, LDSM fragment loads
        float acc[4][4];
#pragma unroll
        for (int it = 0; it < 4; ++it)
#pragma unroll
            for (int q = 0; q < 4; ++q) acc[it][q] = 0.0f;
#pragma unroll
        for (int ks = 0; ks < 8; ++ks) {
            unsigned koff = ks * 32;   // 16 halves = 32 bytes
            unsigned a0, a1, a2, a3;
            ldsm_x4(a0, a1, a2, a3, aAddr + koff);
            unsigned b00, b01, b10, b11;
            ldsm_x4(b00, b01, b10, b11, bAddr1 + koff);
            unsigned b20, b21, b30, b31;
            ldsm_x4(b20, b21, b30, b31, bAddr2 + koff);
            mma_f16(acc[0], a0, a1, a2, a3, b00, b01);
            mma_f16(acc[1], a0, a1, a2, a3, b10, b11);
            mma_f16(acc[2], a0, a1, a2, a3, b20, b21);
            mma_f16(acc[3], a0, a1, a2, a3, b30, b31);
        }
        __syncthreads();  // t reads complete before phi alias write

#pragma unroll
        for (int it = 0; it < 4; ++it) {
            int n0 = nbase + it * 8;
            *(__half2*)&t_h[(m0 + gid) * PADH + n0 + 2 * tig] =
                __floats2half2_rn(silu(acc[it][0]), silu(acc[it][1]));
            *(__half2*)&t_h[(m0 + gid + 8) * PADH + n0 + 2 * tig] =
                __floats2half2_rn(silu(acc[it][2]), silu(acc[it][3]));
        }
        __syncthreads();

        // scatter — warp per edge, vector REDs
#pragma unroll
        for (int q = 0; q < 4; ++q) {
            int e = w + 16 * q;
            int s = src_s[e], d = dst_s[e];
            uint2 pu = *(const uint2*)&t_h[e * PADH + c4];
            uint2 fu = *(const uint2*)&filt_h[e * PADH + c4];
            float2 p01 = __half22float2(*(__half2*)&pu.x);
            float2 p23 = __half22float2(*(__half2*)&pu.y);
            float2 f01 = __half22float2(*(__half2*)&fu.x);
            float2 f23 = __half22float2(*(__half2*)&fu.y);
            float d0 = dirn_s[e * 3 + 0];
            float d1 = dirn_s[e * 3 + 1];
            float d2 = dirn_s[e * 3 + 2];
            red4(&g_dx[d * 128 + c4], p01.x, p01.y, p23.x, p23.y);
            float4 m0v = *(const float4*)&g_vmix[(s * 3 + 0) * 128 + c4];
            red4(&g_vec[(d * 3 + 0) * 128 + c4],
                 m0v.x * f01.x + p01.x * d0, m0v.y * f01.y + p01.y * d0,
                 m0v.z * f23.x + p23.x * d0, m0v.w * f23.y + p23.y * d0);
            float4 m1v = *(const float4*)&g_vmix[(s * 3 + 1) * 128 + c4];
            red4(&g_vec[(d * 3 + 1) * 128 + c4],
                 m1v.x * f01.x + p01.x * d1, m1v.y * f01.y + p01.y * d1,
                 m1v.z * f23.x + p23.x * d1, m1v.w * f23.y + p23.y * d1);
            float4 m2v = *(const float4*)&g_vmix[(s * 3 + 2) * 128 + c4];
            red4(&g_vec[(d * 3 + 2) * 128 + c4],
                 m2v.x * f01.x + p01.x * d2, m2v.y * f01.y + p01.y * d2,
                 m2v.z * f23.x + p23.x * d2, m2v.w * f23.y + p23.y * d2);
        }
    }
}

__global__ void k_pool(const float* __restrict__ a, const int* __restrict__ batch,
                       const float* __restrict__ Wb, const float* __restrict__ bb) {
    __shared__ float Wb_s[128 * 65];
    __shared__ float bb_s[65];
    __shared__ float a_s[4][128];
    int tx = threadIdx.x, ty = threadIdx.y;
    int tid = ty * 65 + tx;
    for (int m = tid; m < 128 * 65; m += 260) Wb_s[m] = Wb[m];
    if (tid < 65) bb_s[tid] = bb[tid];
    __syncthreads();
    for (int base = blockIdx.x * 4; base < N_NODES; base += gridDim.x * 4) {
        int n = base + ty;
        a_s[ty][tx] = a[n * 128 + tx];
        if (tx + 65 < 128) a_s[ty][tx + 65] = a[n * 128 + tx + 65];
        __syncthreads();
        float acc = bb_s[tx];
#pragma unroll 4
        for (int jj = 0; jj < 128; ++jj) acc += a_s[ty][jj] * Wb_s[jj * 65 + tx];
        atomicAdd(&g_pooled[batch[n] * 65 + tx], acc);
        __syncthreads();
    }
}

__global__ void k_final(float* __restrict__ out) {
    int idx = blockIdx.x * blockDim.x + threadIdx.x;
    if (idx < N_GRAPHS * LATENT) {
        int g = idx / LATENT, k = idx % LATENT;
        out[idx] = g_pooled[g * 65 + k];
    } else if (idx < N_GRAPHS * LATENT + N_GRAPHS) {
        int g = idx - N_GRAPHS * LATENT;
        float lv = g_pooled[g * 65 + 64];
        out[idx] = fminf(fmaxf(lv, -10.0f), 2.0f);
    }
}

extern "C" void kernel_launch(void* const* d_in, const int* in_sizes, int n_in,
                              void* d_out, int out_size) {
    (void)in_sizes; (void)n_in; (void)out_size;
    const int* z = (const int*)d_in[0];
    const float* pos = (const float*)d_in[1];
    const int* batch = (const int*)d_in[2];
    const int* ei = (const int*)d_in[3];
    const float* embed = (const float*)d_in[4];
    const float* W_rbf = (const float*)d_in[5];
    const float* W1 = (const float*)d_in[6];
    const float* Wo = (const float*)d_in[7];
    const float* Wv = (const float*)d_in[8];
    const float* Wvec2 = (const float*)d_in[10];
    const float* W_a = (const float*)d_in[11];
    const float* b_a = (const float*)d_in[12];
    const float* W_b = (const float*)d_in[13];
    const float* b_b = (const float*)d_in[14];
    float* out = (float*)d_out;

    float *p_x, *p_vec, *p_vmix, *p_dx, *p_a;
    unsigned* p_wrbfp;
    cudaGetSymbolAddress((void**)&p_x, g_x);
    cudaGetSymbolAddress((void**)&p_vec, g_vec);
    cudaGetSymbolAddress((void**)&p_vmix, g_vmix);
    cudaGetSymbolAddress((void**)&p_dx, g_dx);
    cudaGetSymbolAddress((void**)&p_a, g_a);
    cudaGetSymbolAddress((void**)&p_wrbfp, g_wrbfp);

    size_t smem_gemm = (size_t)(128 * PAD + 64 * PAD) * 4;
    size_t smem_edge = (size_t)(128 * PADH + 2 * ET * PADH) * 2
                       + 192 * 4 + 2 * ET * 4;  // ~69.3 KB
    cudaFuncSetAttribute(k_gemm_mma, cudaFuncAttributeMaxDynamicSharedMemorySize, (int)smem_gemm);
    cudaFuncSetAttribute(k_edge, cudaFuncAttributeMaxDynamicSharedMemorySize, (int)smem_edge);

    k_setup<<<(N_NODES * 384 + 255) / 256, 256>>>(z, embed, W_rbf);
    k_geom<<<(N_EDGES + 255) / 256, 256>>>(pos, ei);

    for (int l = 0; l < 2; ++l) {
        k_gemm_mma<<<296, 256, smem_gemm>>>(p_vec, Wv + l * 128 * 128, nullptr, p_vmix,
                                            N_NODES * 3, 0, 0, 0);
        if (l) k_zero<<<(N_NODES * 128 + 255) / 256, 256>>>(p_dx, N_NODES * 128);
        // fused edge pass — 3 CTAs/SM
        k_edge<<<444, 512, smem_edge>>>(ei, p_wrbfp + l * 128 * 16, W1 + l * 128 * 128);
        k_gemm_mma<<<157, 256, smem_gemm>>>(p_dx, Wo + l * 128 * 128, nullptr, p_x,
                                            N_NODES, 1, 0, 0);
    }

    // v2 = vec @ Wvec2 (reuse vmix buffer)
    k_gemm_mma<<<296, 256, smem_gemm>>>(p_vec, Wvec2, nullptr, p_vmix, N_NODES * 3, 0, 0, 0);

    // a = silu(x @ Wa_top + vnorm(v2) @ Wa_bot + b_a)  — vnorm fused into A-staging
    k_gemm_mma<<<157, 256, smem_gemm>>>(p_x, W_a, nullptr, p_a, N_NODES, 0, 0, 0);
    k_gemm_mma<<<157, 256, smem_gemm>>>(p_vmix, W_a + 128 * 128, b_a, p_a, N_NODES, 1, 1, 1);

    dim3 pb(65, 4);
    k_pool<<<296, pb>>>(p_a, batch, W_b, b_b);

    k_final<<<(N_GRAPHS * LATENT + N_GRAPHS + 255) / 256, 256>>>(out);
}

// round 9
// speedup vs baseline: 4.6115x; 1.0569x over previous
#include <cuda_runtime.h>
#include <cuda_fp16.h>
#include <math.h>

#define N_NODES 10000
#define N_EDGES 160000
#define HIDDEN 128
#define NUM_RBF 32
#define N_GRAPHS 128
#define LATENT 64
#define ET 64            // edges per tile in k_edge
#define PAD 136          // f32 smem stride (node gemm)
#define PADH 136         // half stride for 128-wide rows

// ---------------- scratch ----------------
__device__ float g_x[N_NODES * HIDDEN];
__device__ float g_vec[N_NODES * 3 * HIDDEN];
__device__ float g_vmix[N_NODES * 3 * HIDDEN];
__device__ float g_dx[N_NODES * HIDDEN];
__device__ float g_a[N_NODES * HIDDEN];
__device__ float g_dirn[N_EDGES * 3];
__device__ __half g_rbf[N_EDGES * NUM_RBF];
__device__ unsigned g_wrbfp[2 * 128 * 16];   // packed Wrbf^T half2: [l][n][k/2]
__device__ float g_pooled[N_GRAPHS * 65];

// ---------------- helpers ----------------
__device__ __forceinline__ unsigned f2tf(float f) {
    unsigned r;
    asm("cvt.rna.tf32.f32 %0, %1;" : "=r"(r) : "f"(f));
    return r;
}

__device__ __forceinline__ void mma_tf32(float c[4], unsigned a0, unsigned a1,
                                         unsigned a2, unsigned a3,
                                         unsigned b0, unsigned b1) {
    asm volatile(
        "mma.sync.aligned.m16n8k8.row.col.f32.tf32.tf32.f32 "
        "{%0,%1,%2,%3}, {%4,%5,%6,%7}, {%8,%9}, {%0,%1,%2,%3};"
        : "+f"(c[0]), "+f"(c[1]), "+f"(c[2]), "+f"(c[3])
        : "r"(a0), "r"(a1), "r"(a2), "r"(a3), "r"(b0), "r"(b1));
}

__device__ __forceinline__ void mma_f16(float c[4], unsigned a0, unsigned a1,
                                        unsigned a2, unsigned a3,
                                        unsigned b0, unsigned b1) {
    asm volatile(
        "mma.sync.aligned.m16n8k16.row.col.f32.f16.f16.f32 "
        "{%0,%1,%2,%3}, {%4,%5,%6,%7}, {%8,%9}, {%0,%1,%2,%3};"
        : "+f"(c[0]), "+f"(c[1]), "+f"(c[2]), "+f"(c[3])
        : "r"(a0), "r"(a1), "r"(a2), "r"(a3), "r"(b0), "r"(b1));
}

__device__ __forceinline__ void ldsm_x4(unsigned& r0, unsigned& r1,
                                        unsigned& r2, unsigned& r3, unsigned addr) {
    asm volatile("ldmatrix.sync.aligned.m8n8.x4.shared.b16 {%0,%1,%2,%3}, [%4];"
                 : "=r"(r0), "=r"(r1), "=r"(r2), "=r"(r3) : "r"(addr));
}

__device__ __forceinline__ void red4(float* p, float a, float b, float c, float d) {
    unsigned long long addr = (unsigned long long)p;
    asm volatile("red.global.add.v4.f32 [%0], {%1,%2,%3,%4};"
                 :: "l"(addr), "f"(a), "f"(b), "f"(c), "f"(d) : "memory");
}

__device__ __forceinline__ float silu(float v) {
    return __fdividef(v, 1.0f + __expf(-v));
}

#define H2U(p) (*(const unsigned*)(p))

// ---------------- setup: zero scratch + embed gather + Wrbf pack ----------------
__global__ void k_setup(const int* __restrict__ z, const float* __restrict__ emb,
                        const float* __restrict__ W_rbf) {
    int i = blockIdx.x * blockDim.x + threadIdx.x;
    if (i < N_NODES * 384) g_vec[i] = 0.0f;
    if (i < N_NODES * 128) {
        g_dx[i] = 0.0f;
        int n = i >> 7, j = i & 127;
        g_x[i] = emb[z[n] * HIDDEN + j];
    }
    if (i < N_GRAPHS * 65) g_pooled[i] = 0.0f;
    if (i < 2 * 128 * 16) {
        int l = i >> 11, n = (i >> 4) & 127, kk = i & 15;
        const float* base = W_rbf + l * 32 * 128;
        __half lo = __float2half(base[(2 * kk) * 128 + n]);
        __half hi = __float2half(base[(2 * kk + 1) * 128 + n]);
        __half2 h2 = __halves2half2(lo, hi);
        g_wrbfp[i] = *(unsigned*)&h2;
    }
}

// edge geometry: dirn + windowed expnorm RBF (half output)
__global__ void k_geom(const float* __restrict__ pos, const int* __restrict__ ei) {
    int e = blockIdx.x * blockDim.x + threadIdx.x;
    if (e >= N_EDGES) return;
    int s = ei[e], d = ei[N_EDGES + e];
    float dx = pos[d * 3 + 0] - pos[s * 3 + 0];
    float dy = pos[d * 3 + 1] - pos[s * 3 + 1];
    float dz = pos[d * 3 + 2] - pos[s * 3 + 2];
    float r = sqrtf(dx * dx + dy * dy + dz * dz + 1e-8f);
    float inv = 1.0f / r;
    g_dirn[e * 3 + 0] = dx * inv;
    g_dirn[e * 3 + 1] = dy * inv;
    g_dirn[e * 3 + 2] = dz * inv;

    uint4* rp = (uint4*)&g_rbf[e * 32];
    uint4 z4 = make_uint4(0, 0, 0, 0);
    rp[0] = z4; rp[1] = z4; rp[2] = z4; rp[3] = z4;

    if (r < 5.0f) {
        const float c0 = 0.006737946999085467f;          // exp(-5)
        const float step = (1.0f - c0) / 31.0f;
        const float tmp = (2.0f / 32.0f) * (1.0f - c0);
        const float beta = 1.0f / (tmp * tmp);
        float cut = 0.5f * (__cosf(0.6283185307179586f * r) + 1.0f);
        float er = __expf(-r);
        int kc = (int)((er - c0) * (1.0f / step));
        int base = kc - 8;
        base = base < 0 ? 0 : (base > 15 ? 15 : base);
#pragma unroll
        for (int kk = 0; kk < 17; ++kk) {
            int k = base + kk;
            float m = c0 + (float)k * step;
            float dd = er - m;
            g_rbf[e * 32 + k] = __float2half(cut * __expf(-beta * dd * dd));
        }
    }
}

// ---------------- tensor-core node GEMM (tf32) ----------------
// vnorm: A is v2 [R][3][128], staged value = row-norm; clearA: zero A after read
__global__ __launch_bounds__(256) void k_gemm_mma(
    const float* __restrict__ A, const float* __restrict__ W,
    const float* __restrict__ bias, float* __restrict__ C,
    int R, int accum, int act, int vnorm, int clearA) {
    extern __shared__ float sm[];
    unsigned* W_u = (unsigned*)sm;
    unsigned* A_u = (unsigned*)(sm + 128 * PAD);
    int tid = threadIdx.x;
    int w = tid >> 5, lane = tid & 31, gid = lane >> 2, tig = lane & 3;

    for (int m4 = tid; m4 < 128 * 32; m4 += 256) {
        int i = m4 >> 5, j = (m4 & 31) * 4;
        float4 v = *(const float4*)&W[i * 128 + j];
        *(uint4*)&W_u[i * PAD + j] =
            make_uint4(f2tf(v.x), f2tf(v.y), f2tf(v.z), f2tf(v.w));
    }
    __syncthreads();

    int m0 = (w & 3) * 16;
    int nbase = (w >> 2) * 64;
    int nT = (R + 63) >> 6;
    for (int t = blockIdx.x; t < nT; t += gridDim.x) {
        int r0 = t << 6;
        for (int m4 = tid; m4 < 64 * 32; m4 += 256) {
            int r = m4 >> 5, c = (m4 & 31) * 4;
            int rr = r0 + r;
            float4 v = make_float4(0.f, 0.f, 0.f, 0.f);
            if (rr < R) {
                if (vnorm) {
                    float4 a0 = *(const float4*)&A[(rr * 3 + 0) * 128 + c];
                    float4 a1 = *(const float4*)&A[(rr * 3 + 1) * 128 + c];
                    float4 a2 = *(const float4*)&A[(rr * 3 + 2) * 128 + c];
                    v.x = sqrtf(a0.x * a0.x + a1.x * a1.x + a2.x * a2.x + 1e-8f);
                    v.y = sqrtf(a0.y * a0.y + a1.y * a1.y + a2.y * a2.y + 1e-8f);
                    v.z = sqrtf(a0.z * a0.z + a1.z * a1.z + a2.z * a2.z + 1e-8f);
                    v.w = sqrtf(a0.w * a0.w + a1.w * a1.w + a2.w * a2.w + 1e-8f);
                } else {
                    v = *(const float4*)&A[rr * 128 + c];
                    if (clearA)
                        *(float4*)&((float*)A)[rr * 128 + c] =
                            make_float4(0.f, 0.f, 0.f, 0.f);
                }
            }
            *(uint4*)&A_u[r * PAD + c] =
                make_uint4(f2tf(v.x), f2tf(v.y), f2tf(v.z), f2tf(v.w));
        }
        __syncthreads();

        float acc[8][4];
#pragma unroll
        for (int it = 0; it < 8; ++it)
#pragma unroll
            for (int q = 0; q < 4; ++q) acc[it][q] = 0.0f;

#pragma unroll
        for (int ks = 0; ks < 16; ++ks) {
            int k0 = ks * 8;
            unsigned a0 = A_u[(m0 + gid) * PAD + k0 + tig];
            unsigned a1 = A_u[(m0 + gid + 8) * PAD + k0 + tig];
            unsigned a2 = A_u[(m0 + gid) * PAD + k0 + tig + 4];
            unsigned a3 = A_u[(m0 + gid + 8) * PAD + k0 + tig + 4];
#pragma unroll
            for (int it = 0; it < 8; ++it) {
                int n0 = nbase + it * 8;
                unsigned b0 = W_u[(k0 + tig) * PAD + n0 + gid];
                unsigned b1 = W_u[(k0 + tig + 4) * PAD + n0 + gid];
                mma_tf32(acc[it], a0, a1, a2, a3, b0, b1);
            }
        }

#pragma unroll
        for (int it = 0; it < 8; ++it) {
            int n0 = nbase + it * 8;
            int col = n0 + 2 * tig;
            float bb0 = bias ? bias[col] : 0.0f;
            float bb1 = bias ? bias[col + 1] : 0.0f;
#pragma unroll
            for (int h = 0; h < 2; ++h) {
                int row = r0 + m0 + gid + h * 8;
                if (row < R) {
                    float v0 = acc[it][2 * h + 0] + bb0;
                    float v1 = acc[it][2 * h + 1] + bb1;
                    if (accum) {
                        v0 += C[row * 128 + col];
                        v1 += C[row * 128 + col + 1];
                    }
                    if (act) { v0 = silu(v0); v1 = silu(v1); }
                    C[row * 128 + col] = v0;
                    C[row * 128 + col + 1] = v1;
                }
            }
        }
        __syncthreads();
    }
}

// ---------------- fused fp16 edge kernel (512 threads, 3 CTAs/SM, LDSM frags) ----------------
// novmix=1 (layer 0): vmix == 0, skip the gathers and f*vmix terms.
__global__ __launch_bounds__(512, 3) void k_edge(
    const int* __restrict__ ei, const unsigned* __restrict__ wrbfp,
    const float* __restrict__ W1, int novmix) {
    extern __shared__ __half smh[];
    __half* W1T    = smh;                      // [128 n][PADH k]  34816 B
    __half* filt_h = W1T + 128 * PADH;         // [64 e][PADH c]   17408 B
    __half* t_h    = filt_h + ET * PADH;       // [64 e][PADH k]   17408 B (phi alias)
    float* dirn_s = (float*)(t_h + ET * PADH); // 768 B
    int* src_s = (int*)(dirn_s + 192);         // 256 B
    int* dst_s = src_s + ET;                   // 256 B

    int tid = threadIdx.x;
    int w = tid >> 5, lane = tid & 31, gid = lane >> 2, tig = lane & 3;

    for (int m = tid; m < 128 * 128; m += 512) {
        int i = m >> 7, j = m & 127;   // i=k, j=n
        W1T[j * PADH + i] = __float2half(W1[m]);
    }

    int m0 = (w & 3) * 16;
    int nbase = (w >> 2) * 32;
    int c4 = lane * 4;

    int sec = lane >> 3, r8 = lane & 7;
    unsigned t_base  = (unsigned)__cvta_generic_to_shared(t_h);
    unsigned w1_base = (unsigned)__cvta_generic_to_shared(W1T);
    unsigned aAddr = t_base +
        (((m0 + r8 + ((sec & 1) << 3)) * PADH + ((sec >> 1) << 3)) << 1);
    unsigned bAddr1 = w1_base +
        (((nbase + r8 + ((sec >> 1) << 3)) * PADH + ((sec & 1) << 3)) << 1);
    unsigned bAddr2 = bAddr1 + ((16 * PADH) << 1);

    int nTiles = N_EDGES / ET;
    for (int t = blockIdx.x; t < nTiles; t += gridDim.x) {
        int e0 = t * ET;
        __syncthreads();

        if (tid < ET) src_s[tid] = ei[e0 + tid];
        else if (tid < 2 * ET) dst_s[tid - ET] = ei[N_EDGES + e0 + (tid - ET)];
        if (tid < ET * 3) dirn_s[tid] = g_dirn[e0 * 3 + tid];
        __syncthreads();

        // filt = rbf @ Wrbf  (M=64, N=128, K=32)
        {
            float acc[4][4];
#pragma unroll
            for (int it = 0; it < 4; ++it)
#pragma unroll
                for (int q = 0; q < 4; ++q) acc[it][q] = 0.0f;
#pragma unroll
            for (int ks = 0; ks < 2; ++ks) {
                int k0 = ks * 16;
                unsigned a0 = H2U(&g_rbf[(e0 + m0 + gid) * 32 + k0 + 2 * tig]);
                unsigned a1 = H2U(&g_rbf[(e0 + m0 + gid + 8) * 32 + k0 + 2 * tig]);
                unsigned a2 = H2U(&g_rbf[(e0 + m0 + gid) * 32 + k0 + 2 * tig + 8]);
                unsigned a3 = H2U(&g_rbf[(e0 + m0 + gid + 8) * 32 + k0 + 2 * tig + 8]);
#pragma unroll
                for (int it = 0; it < 4; ++it) {
                    int n0 = nbase + it * 8;
                    unsigned b0 = wrbfp[(n0 + gid) * 16 + 8 * ks + tig];
                    unsigned b1 = wrbfp[(n0 + gid) * 16 + 8 * ks + tig + 4];
                    mma_f16(acc[it], a0, a1, a2, a3, b0, b1);
                }
            }
#pragma unroll
            for (int it = 0; it < 4; ++it) {
                int n0 = nbase + it * 8;
                *(__half2*)&filt_h[(m0 + gid) * PADH + n0 + 2 * tig] =
                    __floats2half2_rn(acc[it][0], acc[it][1]);
                *(__half2*)&filt_h[(m0 + gid + 8) * PADH + n0 + 2 * tig] =
                    __floats2half2_rn(acc[it][2], acc[it][3]);
            }
        }
        __syncthreads();

        // t[e][c] = x[src[e]][c] * filt[e][c]
#pragma unroll
        for (int q = 0; q < 4; ++q) {
            int e = w + 16 * q;
            int s = src_s[e];
            float4 xv = *(const float4*)&g_x[s * 128 + c4];
            uint2 fu = *(const uint2*)&filt_h[e * PADH + c4];
            float2 f01 = __half22float2(*(__half2*)&fu.x);
            float2 f23 = __half22float2(*(__half2*)&fu.y);
            __half2 h0 = __floats2half2_rn(xv.x * f01.x, xv.y * f01.y);
            __half2 h1 = __floats2half2_rn(xv.z * f23.x, xv.w * f23.y);
            uint2 tu = make_uint2(*(unsigned*)&h0, *(unsigned*)&h1);
            *(uint2*)&t_h[e * PADH + c4] = tu;
        }
        __syncthreads();

        // phi = t @ W1  (fp16 mma, LDSM frags)
        float acc[4][4];
#pragma unroll
        for (int it = 0; it < 4; ++it)
#pragma unroll
            for (int q = 0; q < 4; ++q) acc[it][q] = 0.0f;
#pragma unroll
        for (int ks = 0; ks < 8; ++ks) {
            unsigned koff = ks * 32;
            unsigned a0, a1, a2, a3;
            ldsm_x4(a0, a1, a2, a3, aAddr + koff);
            unsigned b00, b01, b10, b11;
            ldsm_x4(b00, b01, b10, b11, bAddr1 + koff);
            unsigned b20, b21, b30, b31;
            ldsm_x4(b20, b21, b30, b31, bAddr2 + koff);
            mma_f16(acc[0], a0, a1, a2, a3, b00, b01);
            mma_f16(acc[1], a0, a1, a2, a3, b10, b11);
            mma_f16(acc[2], a0, a1, a2, a3, b20, b21);
            mma_f16(acc[3], a0, a1, a2, a3, b30, b31);
        }
        __syncthreads();

#pragma unroll
        for (int it = 0; it < 4; ++it) {
            int n0 = nbase + it * 8;
            *(__half2*)&t_h[(m0 + gid) * PADH + n0 + 2 * tig] =
                __floats2half2_rn(silu(acc[it][0]), silu(acc[it][1]));
            *(__half2*)&t_h[(m0 + gid + 8) * PADH + n0 + 2 * tig] =
                __floats2half2_rn(silu(acc[it][2]), silu(acc[it][3]));
        }
        __syncthreads();

        // scatter
#pragma unroll
        for (int q = 0; q < 4; ++q) {
            int e = w + 16 * q;
            int s = src_s[e], d = dst_s[e];
            uint2 pu = *(const uint2*)&t_h[e * PADH + c4];
            float2 p01 = __half22float2(*(__half2*)&pu.x);
            float2 p23 = __half22float2(*(__half2*)&pu.y);
            float d0 = dirn_s[e * 3 + 0];
            float d1 = dirn_s[e * 3 + 1];
            float d2 = dirn_s[e * 3 + 2];
            red4(&g_dx[d * 128 + c4], p01.x, p01.y, p23.x, p23.y);
            if (novmix) {
                red4(&g_vec[(d * 3 + 0) * 128 + c4],
                     p01.x * d0, p01.y * d0, p23.x * d0, p23.y * d0);
                red4(&g_vec[(d * 3 + 1) * 128 + c4],
                     p01.x * d1, p01.y * d1, p23.x * d1, p23.y * d1);
                red4(&g_vec[(d * 3 + 2) * 128 + c4],
                     p01.x * d2, p01.y * d2, p23.x * d2, p23.y * d2);
            } else {
                uint2 fu = *(const uint2*)&filt_h[e * PADH + c4];
                float2 f01 = __half22float2(*(__half2*)&fu.x);
                float2 f23 = __half22float2(*(__half2*)&fu.y);
                float4 m0v = *(const float4*)&g_vmix[(s * 3 + 0) * 128 + c4];
                red4(&g_vec[(d * 3 + 0) * 128 + c4],
                     m0v.x * f01.x + p01.x * d0, m0v.y * f01.y + p01.y * d0,
                     m0v.z * f23.x + p23.x * d0, m0v.w * f23.y + p23.y * d0);
                float4 m1v = *(const float4*)&g_vmix[(s * 3 + 1) * 128 + c4];
                red4(&g_vec[(d * 3 + 1) * 128 + c4],
                     m1v.x * f01.x + p01.x * d1, m1v.y * f01.y + p01.y * d1,
                     m1v.z * f23.x + p23.x * d1, m1v.w * f23.y + p23.y * d1);
                float4 m2v = *(const float4*)&g_vmix[(s * 3 + 2) * 128 + c4];
                red4(&g_vec[(d * 3 + 2) * 128 + c4],
                     m2v.x * f01.x + p01.x * d2, m2v.y * f01.y + p01.y * d2,
                     m2v.z * f23.x + p23.x * d2, m2v.w * f23.y + p23.y * d2);
            }
        }
    }
}

__global__ void k_pool(const float* __restrict__ a, const int* __restrict__ batch,
                       const float* __restrict__ Wb, const float* __restrict__ bb) {
    __shared__ float Wb_s[128 * 65];
    __shared__ float bb_s[65];
    __shared__ float a_s[4][128];
    int tx = threadIdx.x, ty = threadIdx.y;
    int tid = ty * 65 + tx;
    for (int m = tid; m < 128 * 65; m += 260) Wb_s[m] = Wb[m];
    if (tid < 65) bb_s[tid] = bb[tid];
    __syncthreads();
    for (int base = blockIdx.x * 4; base < N_NODES; base += gridDim.x * 4) {
        int n = base + ty;
        a_s[ty][tx] = a[n * 128 + tx];
        if (tx + 65 < 128) a_s[ty][tx + 65] = a[n * 128 + tx + 65];
        __syncthreads();
        float acc = bb_s[tx];
#pragma unroll 4
        for (int jj = 0; jj < 128; ++jj) acc += a_s[ty][jj] * Wb_s[jj * 65 + tx];
        atomicAdd(&g_pooled[batch[n] * 65 + tx], acc);
        __syncthreads();
    }
}

__global__ void k_final(float* __restrict__ out) {
    int idx = blockIdx.x * blockDim.x + threadIdx.x;
    if (idx < N_GRAPHS * LATENT) {
        int g = idx / LATENT, k = idx % LATENT;
        out[idx] = g_pooled[g * 65 + k];
    } else if (idx < N_GRAPHS * LATENT + N_GRAPHS) {
        int g = idx - N_GRAPHS * LATENT;
        float lv = g_pooled[g * 65 + 64];
        out[idx] = fminf(fmaxf(lv, -10.0f), 2.0f);
    }
}

extern "C" void kernel_launch(void* const* d_in, const int* in_sizes, int n_in,
                              void* d_out, int out_size) {
    (void)in_sizes; (void)n_in; (void)out_size;
    const int* z = (const int*)d_in[0];
    const float* pos = (const float*)d_in[1];
    const int* batch = (const int*)d_in[2];
    const int* ei = (const int*)d_in[3];
    const float* embed = (const float*)d_in[4];
    const float* W_rbf = (const float*)d_in[5];
    const float* W1 = (const float*)d_in[6];
    const float* Wo = (const float*)d_in[7];
    const float* Wv = (const float*)d_in[8];
    const float* Wvec2 = (const float*)d_in[10];
    const float* W_a = (const float*)d_in[11];
    const float* b_a = (const float*)d_in[12];
    const float* W_b = (const float*)d_in[13];
    const float* b_b = (const float*)d_in[14];
    float* out = (float*)d_out;

    float *p_x, *p_vec, *p_vmix, *p_dx, *p_a;
    unsigned* p_wrbfp;
    cudaGetSymbolAddress((void**)&p_x, g_x);
    cudaGetSymbolAddress((void**)&p_vec, g_vec);
    cudaGetSymbolAddress((void**)&p_vmix, g_vmix);
    cudaGetSymbolAddress((void**)&p_dx, g_dx);
    cudaGetSymbolAddress((void**)&p_a, g_a);
    cudaGetSymbolAddress((void**)&p_wrbfp, g_wrbfp);

    size_t smem_gemm = (size_t)(128 * PAD + 64 * PAD) * 4;
    size_t smem_edge = (size_t)(128 * PADH + 2 * ET * PADH) * 2
                       + 192 * 4 + 2 * ET * 4;  // ~69.3 KB
    cudaFuncSetAttribute(k_gemm_mma, cudaFuncAttributeMaxDynamicSharedMemorySize, (int)smem_gemm);
    cudaFuncSetAttribute(k_edge, cudaFuncAttributeMaxDynamicSharedMemorySize, (int)smem_edge);

    k_setup<<<(N_NODES * 384 + 255) / 256, 256>>>(z, embed, W_rbf);
    k_geom<<<(N_EDGES + 255) / 256, 256>>>(pos, ei);

    // ---- layer 0: vec == 0 -> vmix == 0; skip Wv GEMM and vmix gathers ----
    k_edge<<<444, 512, smem_edge>>>(ei, p_wrbfp, W1, 1);
    // x += dx @ Wo[0]; clear dx for next layer while staging
    k_gemm_mma<<<157, 256, smem_gemm>>>(p_dx, Wo, nullptr, p_x, N_NODES, 1, 0, 0, 1);

    // ---- layer 1 ----
    k_gemm_mma<<<296, 256, smem_gemm>>>(p_vec, Wv + 128 * 128, nullptr, p_vmix,
                                        N_NODES * 3, 0, 0, 0, 0);
    k_edge<<<444, 512, smem_edge>>>(ei, p_wrbfp + 128 * 16, W1 + 128 * 128, 0);
    k_gemm_mma<<<157, 256, smem_gemm>>>(p_dx, Wo + 128 * 128, nullptr, p_x,
                                        N_NODES, 1, 0, 0, 0);

    // v2 = vec @ Wvec2 (reuse vmix buffer)
    k_gemm_mma<<<296, 256, smem_gemm>>>(p_vec, Wvec2, nullptr, p_vmix,
                                        N_NODES * 3, 0, 0, 0, 0);

    // a = silu(x @ Wa_top + vnorm(v2) @ Wa_bot + b_a)
    k_gemm_mma<<<157, 256, smem_gemm>>>(p_x, W_a, nullptr, p_a, N_NODES, 0, 0, 0, 0);
    k_gemm_mma<<<157, 256, smem_gemm>>>(p_vmix, W_a + 128 * 128, b_a, p_a,
                                        N_NODES, 1, 1, 1, 0);

    dim3 pb(65, 4);
    k_pool<<<296, pb>>>(p_a, batch, W_b, b_b);

    k_final<<<(N_GRAPHS * LATENT + N_GRAPHS + 255) / 256, 256>>>(out);
}

// round 11
// speedup vs baseline: 4.6370x; 1.0055x over previous
#include <cuda_runtime.h>
#include <cuda_fp16.h>
#include <math.h>

#define N_NODES 10000
#define N_EDGES 160000
#define HIDDEN 128
#define NUM_RBF 32
#define N_GRAPHS 128
#define LATENT 64
#define ET 64            // edges per tile in k_edge
#define PADH 136         // half stride for 128-wide rows

// ---------------- scratch ----------------
__device__ float g_x[N_NODES * HIDDEN];
__device__ float g_vec[N_NODES * 3 * HIDDEN];
__device__ float g_vmix[N_NODES * 3 * HIDDEN];
__device__ float g_dx[N_NODES * HIDDEN];
__device__ float g_a[N_NODES * HIDDEN];
__device__ float g_dirn[N_EDGES * 3];
__device__ __half g_rbf[N_EDGES * NUM_RBF];
__device__ unsigned g_wrbfp[2 * 128 * 16];   // packed Wrbf^T half2: [l][n][k/2]
__device__ float g_pooled[N_GRAPHS * 65];

// ---------------- helpers ----------------
__device__ __forceinline__ void mma_f16(float c[4], unsigned a0, unsigned a1,
                                        unsigned a2, unsigned a3,
                                        unsigned b0, unsigned b1) {
    asm volatile(
        "mma.sync.aligned.m16n8k16.row.col.f32.f16.f16.f32 "
        "{%0,%1,%2,%3}, {%4,%5,%6,%7}, {%8,%9}, {%0,%1,%2,%3};"
        : "+f"(c[0]), "+f"(c[1]), "+f"(c[2]), "+f"(c[3])
        : "r"(a0), "r"(a1), "r"(a2), "r"(a3), "r"(b0), "r"(b1));
}

__device__ __forceinline__ void ldsm_x4(unsigned& r0, unsigned& r1,
                                        unsigned& r2, unsigned& r3, unsigned addr) {
    asm volatile("ldmatrix.sync.aligned.m8n8.x4.shared.b16 {%0,%1,%2,%3}, [%4];"
                 : "=r"(r0), "=r"(r1), "=r"(r2), "=r"(r3) : "r"(addr));
}

__device__ __forceinline__ void red4(float* p, float a, float b, float c, float d) {
    unsigned long long addr = (unsigned long long)p;
    asm volatile("red.global.add.v4.f32 [%0], {%1,%2,%3,%4};"
                 :: "l"(addr), "f"(a), "f"(b), "f"(c), "f"(d) : "memory");
}

__device__ __forceinline__ float silu(float v) {
    return __fdividef(v, 1.0f + __expf(-v));
}

#define H2U(p) (*(const unsigned*)(p))

// ---------------- setup ----------------
__global__ void k_setup(const int* __restrict__ z, const float* __restrict__ emb,
                        const float* __restrict__ W_rbf) {
    int i = blockIdx.x * blockDim.x + threadIdx.x;
    if (i < N_NODES * 384) g_vec[i] = 0.0f;
    if (i < N_NODES * 128) {
        g_dx[i] = 0.0f;
        int n = i >> 7, j = i & 127;
        g_x[i] = emb[z[n] * HIDDEN + j];
    }
    if (i < N_GRAPHS * 65) g_pooled[i] = 0.0f;
    if (i < 2 * 128 * 16) {
        int l = i >> 11, n = (i >> 4) & 127, kk = i & 15;
        const float* base = W_rbf + l * 32 * 128;
        __half lo = __float2half(base[(2 * kk) * 128 + n]);
        __half hi = __float2half(base[(2 * kk + 1) * 128 + n]);
        __half2 h2 = __halves2half2(lo, hi);
        g_wrbfp[i] = *(unsigned*)&h2;
    }
}

// edge geometry: dirn + windowed expnorm RBF (half output)
__global__ void k_geom(const float* __restrict__ pos, const int* __restrict__ ei) {
    int e = blockIdx.x * blockDim.x + threadIdx.x;
    if (e >= N_EDGES) return;
    int s = ei[e], d = ei[N_EDGES + e];
    float dx = pos[d * 3 + 0] - pos[s * 3 + 0];
    float dy = pos[d * 3 + 1] - pos[s * 3 + 1];
    float dz = pos[d * 3 + 2] - pos[s * 3 + 2];
    float r = sqrtf(dx * dx + dy * dy + dz * dz + 1e-8f);
    float inv = 1.0f / r;
    g_dirn[e * 3 + 0] = dx * inv;
    g_dirn[e * 3 + 1] = dy * inv;
    g_dirn[e * 3 + 2] = dz * inv;

    uint4* rp = (uint4*)&g_rbf[e * 32];
    uint4 z4 = make_uint4(0, 0, 0, 0);
    rp[0] = z4; rp[1] = z4; rp[2] = z4; rp[3] = z4;

    if (r < 5.0f) {
        const float c0 = 0.006737946999085467f;          // exp(-5)
        const float step = (1.0f - c0) / 31.0f;
        const float tmp = (2.0f / 32.0f) * (1.0f - c0);
        const float beta = 1.0f / (tmp * tmp);
        float cut = 0.5f * (__cosf(0.6283185307179586f * r) + 1.0f);
        float er = __expf(-r);
        int kc = (int)((er - c0) * (1.0f / step));
        int base = kc - 8;
        base = base < 0 ? 0 : (base > 15 ? 15 : base);
#pragma unroll
        for (int kk = 0; kk < 17; ++kk) {
            int k = base + kk;
            float m = c0 + (float)k * step;
            float dd = er - m;
            g_rbf[e * 32 + k] = __float2half(cut * __expf(-beta * dd * dd));
        }
    }
}

// ---------------- fp16 node GEMM ----------------
// K = 128 or 256. mode 0: A row-major RxK. mode 2 (K=256): row = [x | vnorm(A2)].
// clearA zeroes A after staging (mode 0). Epilogue: optional accum into C, bias, silu.
template <int K, int MODE>
__global__ __launch_bounds__(256, 3) void k_gemm_h(
    const float* __restrict__ A, const float* __restrict__ A2,
    const float* __restrict__ W, const float* __restrict__ bias,
    float* __restrict__ C, int R, int accum, int act, int clearA) {
    constexpr int PK = K + 8;
    extern __shared__ __half smh[];
    __half* W_h = smh;             // [128 n][PK k]
    __half* A_h = W_h + 128 * PK;  // [64 m][PK k]

    int tid = threadIdx.x;
    int w = tid >> 5, lane = tid & 31, gid = lane >> 2, tig = lane & 3;

    // stage W transposed [n][k]
    for (int m = tid; m < K * 128; m += 256) {
        int k = m >> 7, n = m & 127;
        W_h[n * PK + k] = __float2half(W[m]);
    }

    int m0 = (w & 3) * 16;       // row block
    int nbase = (w >> 2) * 64;   // col block

    int sec = lane >> 3, r8 = lane & 7;
    unsigned a_base = (unsigned)__cvta_generic_to_shared(A_h);
    unsigned w_base = (unsigned)__cvta_generic_to_shared(W_h);
    unsigned aAddr = a_base +
        (((m0 + r8 + ((sec & 1) << 3)) * PK + ((sec >> 1) << 3)) << 1);
    unsigned bAddr[4];
#pragma unroll
    for (int j = 0; j < 4; ++j)
        bAddr[j] = w_base +
            (((nbase + j * 16 + r8 + ((sec >> 1) << 3)) * PK + ((sec & 1) << 3)) << 1);

    int nT = (R + 63) >> 6;
    for (int t = blockIdx.x; t < nT; t += gridDim.x) {
        int r0 = t << 6;
        __syncthreads();  // prev tile consumed (and W staged on first iter)
        for (int m4 = tid; m4 < 64 * (K / 4); m4 += 256) {
            int r = m4 / (K / 4), c = (m4 % (K / 4)) * 4;
            int rr = r0 + r;
            float4 v = make_float4(0.f, 0.f, 0.f, 0.f);
            if (rr < R) {
                if (MODE == 2) {
                    if (c < 128) {
                        v = *(const float4*)&A[rr * 128 + c];
                    } else {
                        int cc = c - 128;
                        float4 a0 = *(const float4*)&A2[(rr * 3 + 0) * 128 + cc];
                        float4 a1 = *(const float4*)&A2[(rr * 3 + 1) * 128 + cc];
                        float4 a2 = *(const float4*)&A2[(rr * 3 + 2) * 128 + cc];
                        v.x = sqrtf(a0.x * a0.x + a1.x * a1.x + a2.x * a2.x + 1e-8f);
                        v.y = sqrtf(a0.y * a0.y + a1.y * a1.y + a2.y * a2.y + 1e-8f);
                        v.z = sqrtf(a0.z * a0.z + a1.z * a1.z + a2.z * a2.z + 1e-8f);
                        v.w = sqrtf(a0.w * a0.w + a1.w * a1.w + a2.w * a2.w + 1e-8f);
                    }
                } else {
                    v = *(const float4*)&A[rr * K + c];
                    if (clearA)
                        *(float4*)&((float*)A)[rr * K + c] =
                            make_float4(0.f, 0.f, 0.f, 0.f);
                }
            }
            __half2 h0 = __floats2half2_rn(v.x, v.y);
            __half2 h1 = __floats2half2_rn(v.z, v.w);
            *(uint2*)&A_h[r * PK + c] = make_uint2(*(unsigned*)&h0, *(unsigned*)&h1);
        }
        __syncthreads();

        float acc[8][4];
#pragma unroll
        for (int it = 0; it < 8; ++it)
#pragma unroll
            for (int q = 0; q < 4; ++q) acc[it][q] = 0.0f;

#pragma unroll
        for (int ks = 0; ks < K / 16; ++ks) {
            unsigned koff = ks * 32;
            unsigned a0, a1, a2, a3;
            ldsm_x4(a0, a1, a2, a3, aAddr + koff);
#pragma unroll
            for (int j = 0; j < 4; ++j) {
                unsigned b0, b1, b2, b3;
                ldsm_x4(b0, b1, b2, b3, bAddr[j] + koff);
                mma_f16(acc[2 * j], a0, a1, a2, a3, b0, b1);
                mma_f16(acc[2 * j + 1], a0, a1, a2, a3, b2, b3);
            }
        }

#pragma unroll
        for (int it = 0; it < 8; ++it) {
            int n0 = nbase + it * 8;
            int col = n0 + 2 * tig;
            float bb0 = bias ? bias[col] : 0.0f;
            float bb1 = bias ? bias[col + 1] : 0.0f;
#pragma unroll
            for (int h = 0; h < 2; ++h) {
                int row = r0 + m0 + gid + h * 8;
                if (row < R) {
                    float v0 = acc[it][2 * h + 0] + bb0;
                    float v1 = acc[it][2 * h + 1] + bb1;
                    if (accum) {
                        v0 += C[row * 128 + col];
                        v1 += C[row * 128 + col + 1];
                    }
                    if (act) { v0 = silu(v0); v1 = silu(v1); }
                    C[row * 128 + col] = v0;
                    C[row * 128 + col + 1] = v1;
                }
            }
        }
    }
}

// ---------------- fused fp16 edge kernel (512 threads, 3 CTAs/SM, LDSM frags) ----------------
__global__ __launch_bounds__(512, 3) void k_edge(
    const int* __restrict__ ei, const unsigned* __restrict__ wrbfp,
    const float* __restrict__ W1, int novmix) {
    extern __shared__ __half smh[];
    __half* W1T    = smh;                      // [128 n][PADH k]
    __half* filt_h = W1T + 128 * PADH;         // [64 e][PADH c]
    __half* t_h    = filt_h + ET * PADH;       // [64 e][PADH k] (phi alias)
    float* dirn_s = (float*)(t_h + ET * PADH);
    int* src_s = (int*)(dirn_s + 192);
    int* dst_s = src_s + ET;

    int tid = threadIdx.x;
    int w = tid >> 5, lane = tid & 31, gid = lane >> 2, tig = lane & 3;

    for (int m = tid; m < 128 * 128; m += 512) {
        int i = m >> 7, j = m & 127;
        W1T[j * PADH + i] = __float2half(W1[m]);
    }

    int m0 = (w & 3) * 16;
    int nbase = (w >> 2) * 32;
    int c4 = lane * 4;

    int sec = lane >> 3, r8 = lane & 7;
    unsigned t_base  = (unsigned)__cvta_generic_to_shared(t_h);
    unsigned w1_base = (unsigned)__cvta_generic_to_shared(W1T);
    unsigned aAddr = t_base +
        (((m0 + r8 + ((sec & 1) << 3)) * PADH + ((sec >> 1) << 3)) << 1);
    unsigned bAddr1 = w1_base +
        (((nbase + r8 + ((sec >> 1) << 3)) * PADH + ((sec & 1) << 3)) << 1);
    unsigned bAddr2 = bAddr1 + ((16 * PADH) << 1);

    int nTiles = N_EDGES / ET;
    for (int t = blockIdx.x; t < nTiles; t += gridDim.x) {
        int e0 = t * ET;
        __syncthreads();

        if (tid < ET) src_s[tid] = ei[e0 + tid];
        else if (tid < 2 * ET) dst_s[tid - ET] = ei[N_EDGES + e0 + (tid - ET)];
        if (tid < ET * 3) dirn_s[tid] = g_dirn[e0 * 3 + tid];
        __syncthreads();

        // filt = rbf @ Wrbf
        {
            float acc[4][4];
#pragma unroll
            for (int it = 0; it < 4; ++it)
#pragma unroll
                for (int q = 0; q < 4; ++q) acc[it][q] = 0.0f;
#pragma unroll
            for (int ks = 0; ks < 2; ++ks) {
                int k0 = ks * 16;
                unsigned a0 = H2U(&g_rbf[(e0 + m0 + gid) * 32 + k0 + 2 * tig]);
                unsigned a1 = H2U(&g_rbf[(e0 + m0 + gid + 8) * 32 + k0 + 2 * tig]);
                unsigned a2 = H2U(&g_rbf[(e0 + m0 + gid) * 32 + k0 + 2 * tig + 8]);
                unsigned a3 = H2U(&g_rbf[(e0 + m0 + gid + 8) * 32 + k0 + 2 * tig + 8]);
#pragma unroll
                for (int it = 0; it < 4; ++it) {
                    int n0 = nbase + it * 8;
                    unsigned b0 = wrbfp[(n0 + gid) * 16 + 8 * ks + tig];
                    unsigned b1 = wrbfp[(n0 + gid) * 16 + 8 * ks + tig + 4];
                    mma_f16(acc[it], a0, a1, a2, a3, b0, b1);
                }
            }
#pragma unroll
            for (int it = 0; it < 4; ++it) {
                int n0 = nbase + it * 8;
                *(__half2*)&filt_h[(m0 + gid) * PADH + n0 + 2 * tig] =
                    __floats2half2_rn(acc[it][0], acc[it][1]);
                *(__half2*)&filt_h[(m0 + gid + 8) * PADH + n0 + 2 * tig] =
                    __floats2half2_rn(acc[it][2], acc[it][3]);
            }
        }
        __syncthreads();

        // t[e][c] = x[src[e]][c] * filt[e][c]
#pragma unroll
        for (int q = 0; q < 4; ++q) {
            int e = w + 16 * q;
            int s = src_s[e];
            float4 xv = *(const float4*)&g_x[s * 128 + c4];
            uint2 fu = *(const uint2*)&filt_h[e * PADH + c4];
            float2 f01 = __half22float2(*(__half2*)&fu.x);
            float2 f23 = __half22float2(*(__half2*)&fu.y);
            __half2 h0 = __floats2half2_rn(xv.x * f01.x, xv.y * f01.y);
            __half2 h1 = __floats2half2_rn(xv.z * f23.x, xv.w * f23.y);
            *(uint2*)&t_h[e * PADH + c4] = make_uint2(*(unsigned*)&h0, *(unsigned*)&h1);
        }
        __syncthreads();

        // phi = t @ W1
        float acc[4][4];
#pragma unroll
        for (int it = 0; it < 4; ++it)
#pragma unroll
            for (int q = 0; q < 4; ++q) acc[it][q] = 0.0f;
#pragma unroll
        for (int ks = 0; ks < 8; ++ks) {
            unsigned koff = ks * 32;
            unsigned a0, a1, a2, a3;
            ldsm_x4(a0, a1, a2, a3, aAddr + koff);
            unsigned b00, b01, b10, b11;
            ldsm_x4(b00, b01, b10, b11, bAddr1 + koff);
            unsigned b20, b21, b30, b31;
            ldsm_x4(b20, b21, b30, b31, bAddr2 + koff);
            mma_f16(acc[0], a0, a1, a2, a3, b00, b01);
            mma_f16(acc[1], a0, a1, a2, a3, b10, b11);
            mma_f16(acc[2], a0, a1, a2, a3, b20, b21);
            mma_f16(acc[3], a0, a1, a2, a3, b30, b31);
        }
        __syncthreads();

#pragma unroll
        for (int it = 0; it < 4; ++it) {
            int n0 = nbase + it * 8;
            *(__half2*)&t_h[(m0 + gid) * PADH + n0 + 2 * tig] =
                __floats2half2_rn(silu(acc[it][0]), silu(acc[it][1]));
            *(__half2*)&t_h[(m0 + gid + 8) * PADH + n0 + 2 * tig] =
                __floats2half2_rn(silu(acc[it][2]), silu(acc[it][3]));
        }
        __syncthreads();

        // scatter
#pragma unroll
        for (int q = 0; q < 4; ++q) {
            int e = w + 16 * q;
            int s = src_s[e], d = dst_s[e];
            uint2 pu = *(const uint2*)&t_h[e * PADH + c4];
            float2 p01 = __half22float2(*(__half2*)&pu.x);
            float2 p23 = __half22float2(*(__half2*)&pu.y);
            float d0 = dirn_s[e * 3 + 0];
            float d1 = dirn_s[e * 3 + 1];
            float d2 = dirn_s[e * 3 + 2];
            red4(&g_dx[d * 128 + c4], p01.x, p01.y, p23.x, p23.y);
            if (novmix) {
                red4(&g_vec[(d * 3 + 0) * 128 + c4],
                     p01.x * d0, p01.y * d0, p23.x * d0, p23.y * d0);
                red4(&g_vec[(d * 3 + 1) * 128 + c4],
                     p01.x * d1, p01.y * d1, p23.x * d1, p23.y * d1);
                red4(&g_vec[(d * 3 + 2) * 128 + c4],
                     p01.x * d2, p01.y * d2, p23.x * d2, p23.y * d2);
            } else {
                uint2 fu = *(const uint2*)&filt_h[e * PADH + c4];
                float2 f01 = __half22float2(*(__half2*)&fu.x);
                float2 f23 = __half22float2(*(__half2*)&fu.y);
                float4 m0v = *(const float4*)&g_vmix[(s * 3 + 0) * 128 + c4];
                red4(&g_vec[(d * 3 + 0) * 128 + c4],
                     m0v.x * f01.x + p01.x * d0, m0v.y * f01.y + p01.y * d0,
                     m0v.z * f23.x + p23.x * d0, m0v.w * f23.y + p23.y * d0);
                float4 m1v = *(const float4*)&g_vmix[(s * 3 + 1) * 128 + c4];
                red4(&g_vec[(d * 3 + 1) * 128 + c4],
                     m1v.x * f01.x + p01.x * d1, m1v.y * f01.y + p01.y * d1,
                     m1v.z * f23.x + p23.x * d1, m1v.w * f23.y + p23.y * d1);
                float4 m2v = *(const float4*)&g_vmix[(s * 3 + 2) * 128 + c4];
                red4(&g_vec[(d * 3 + 2) * 128 + c4],
                     m2v.x * f01.x + p01.x * d2, m2v.y * f01.y + p01.y * d2,
                     m2v.z * f23.x + p23.x * d2, m2v.w * f23.y + p23.y * d2);
            }
        }
    }
}

__global__ void k_pool(const float* __restrict__ a, const int* __restrict__ batch,
                       const float* __restrict__ Wb, const float* __restrict__ bb) {
    __shared__ float Wb_s[128 * 65];
    __shared__ float bb_s[65];
    __shared__ float a_s[4][128];
    int tx = threadIdx.x, ty = threadIdx.y;
    int tid = ty * 65 + tx;
    for (int m = tid; m < 128 * 65; m += 260) Wb_s[m] = Wb[m];
    if (tid < 65) bb_s[tid] = bb[tid];
    __syncthreads();
    for (int base = blockIdx.x * 4; base < N_NODES; base += gridDim.x * 4) {
        int n = base + ty;
        a_s[ty][tx] = a[n * 128 + tx];
        if (tx + 65 < 128) a_s[ty][tx + 65] = a[n * 128 + tx + 65];
        __syncthreads();
        float acc = bb_s[tx];
#pragma unroll 4
        for (int jj = 0; jj < 128; ++jj) acc += a_s[ty][jj] * Wb_s[jj * 65 + tx];
        atomicAdd(&g_pooled[batch[n] * 65 + tx], acc);
        __syncthreads();
    }
}

__global__ void k_final(float* __restrict__ out) {
    int idx = blockIdx.x * blockDim.x + threadIdx.x;
    if (idx < N_GRAPHS * LATENT) {
        int g = idx / LATENT, k = idx % LATENT;
        out[idx] = g_pooled[g * 65 + k];
    } else if (idx < N_GRAPHS * LATENT + N_GRAPHS) {
        int g = idx - N_GRAPHS * LATENT;
        float lv = g_pooled[g * 65 + 64];
        out[idx] = fminf(fmaxf(lv, -10.0f), 2.0f);
    }
}

extern "C" void kernel_launch(void* const* d_in, const int* in_sizes, int n_in,
                              void* d_out, int out_size) {
    (void)in_sizes; (void)n_in; (void)out_size;
    const int* z = (const int*)d_in[0];
    const float* pos = (const float*)d_in[1];
    const int* batch = (const int*)d_in[2];
    const int* ei = (const int*)d_in[3];
    const float* embed = (const float*)d_in[4];
    const float* W_rbf = (const float*)d_in[5];
    const float* W1 = (const float*)d_in[6];
    const float* Wo = (const float*)d_in[7];
    const float* Wv = (const float*)d_in[8];
    const float* Wvec2 = (const float*)d_in[10];
    const float* W_a = (const float*)d_in[11];
    const float* b_a = (const float*)d_in[12];
    const float* W_b = (const float*)d_in[13];
    const float* b_b = (const float*)d_in[14];
    float* out = (float*)d_out;

    float *p_x, *p_vec, *p_vmix, *p_dx, *p_a;
    unsigned* p_wrbfp;
    cudaGetSymbolAddress((void**)&p_x, g_x);
    cudaGetSymbolAddress((void**)&p_vec, g_vec);
    cudaGetSymbolAddress((void**)&p_vmix, g_vmix);
    cudaGetSymbolAddress((void**)&p_dx, g_dx);
    cudaGetSymbolAddress((void**)&p_a, g_a);
    cudaGetSymbolAddress((void**)&p_wrbfp, g_wrbfp);

    size_t smem_g128 = (size_t)(192 * (128 + 8)) * 2;   // 52224
    size_t smem_g256 = (size_t)(192 * (256 + 8)) * 2;   // 101376
    size_t smem_edge = (size_t)(128 * PADH + 2 * ET * PADH) * 2
                       + 192 * 4 + 2 * ET * 4;          // ~69.3 KB
    cudaFuncSetAttribute(k_gemm_h<128, 0>, cudaFuncAttributeMaxDynamicSharedMemorySize, (int)smem_g128);
    cudaFuncSetAttribute(k_gemm_h<256, 2>, cudaFuncAttributeMaxDynamicSharedMemorySize, (int)smem_g256);
    cudaFuncSetAttribute(k_edge, cudaFuncAttributeMaxDynamicSharedMemorySize, (int)smem_edge);

    k_setup<<<(N_NODES * 384 + 255) / 256, 256>>>(z, embed, W_rbf);
    k_geom<<<(N_EDGES + 255) / 256, 256>>>(pos, ei);

    // ---- layer 0: vec == 0 -> vmix == 0 ----
    k_edge<<<444, 512, smem_edge>>>(ei, p_wrbfp, W1, 1);
    // x += dx @ Wo[0]; clear dx while staging
    k_gemm_h<128, 0><<<148, 256, smem_g128>>>(p_dx, nullptr, Wo, nullptr, p_x,
                                              N_NODES, 1, 0, 1);

    // ---- layer 1 ----
    k_gemm_h<128, 0><<<148, 256, smem_g128>>>(p_vec, nullptr, Wv + 128 * 128, nullptr,
                                              p_vmix, N_NODES * 3, 0, 0, 0);
    k_edge<<<444, 512, smem_edge>>>(ei, p_wrbfp + 128 * 16, W1 + 128 * 128, 0);
    k_gemm_h<128, 0><<<148, 256, smem_g128>>>(p_dx, nullptr, Wo + 128 * 128, nullptr,
                                              p_x, N_NODES, 1, 0, 0);

    // v2 = vec @ Wvec2
    k_gemm_h<128, 0><<<148, 256, smem_g128>>>(p_vec, nullptr, Wvec2, nullptr,
                                              p_vmix, N_NODES * 3, 0, 0, 0);

    // a = silu([x | vnorm(v2)] @ W_a + b_a)  — fused K=256
    k_gemm_h<256, 2><<<148, 256, smem_g256>>>(p_x, p_vmix, W_a, b_a, p_a,
                                              N_NODES, 0, 1, 0);

    dim3 pb(65, 4);
    k_pool<<<296, pb>>>(p_a, batch, W_b, b_b);

    k_final<<<(N_GRAPHS * LATENT + N_GRAPHS + 255) / 256, 256>>>(out);
}

// round 12
// speedup vs baseline: 5.0975x; 1.0993x over previous
#include <cuda_runtime.h>
#include <cuda_fp16.h>
#include <math.h>

#define N_NODES 10000
#define N_EDGES 160000
#define HIDDEN 128
#define NUM_RBF 32
#define N_GRAPHS 128
#define LATENT 64
#define ET 64
#define PADH 136   // half stride for 128-wide rows (272B: conflict-free for LDSM/trans)

// ---------------- scratch ----------------
__device__ float g_x[N_NODES * HIDDEN];
__device__ float g_vec[N_NODES * 3 * HIDDEN];
__device__ float g_vmix[N_NODES * 3 * HIDDEN];
__device__ float g_dx[N_NODES * HIDDEN];
__device__ float g_a[N_NODES * HIDDEN];
__device__ float g_dirn[N_EDGES * 3];
__device__ __half g_rbf[N_EDGES * NUM_RBF];
__device__ unsigned g_wrbfp[2 * 128 * 16];
__device__ float g_pooled[N_GRAPHS * 65];

// ---------------- helpers ----------------
__device__ __forceinline__ void mma_f16(float c[4], unsigned a0, unsigned a1,
                                        unsigned a2, unsigned a3,
                                        unsigned b0, unsigned b1) {
    asm volatile(
        "mma.sync.aligned.m16n8k16.row.col.f32.f16.f16.f32 "
        "{%0,%1,%2,%3}, {%4,%5,%6,%7}, {%8,%9}, {%0,%1,%2,%3};"
        : "+f"(c[0]), "+f"(c[1]), "+f"(c[2]), "+f"(c[3])
        : "r"(a0), "r"(a1), "r"(a2), "r"(a3), "r"(b0), "r"(b1));
}

__device__ __forceinline__ void ldsm_x4(unsigned& r0, unsigned& r1,
                                        unsigned& r2, unsigned& r3, unsigned addr) {
    asm volatile("ldmatrix.sync.aligned.m8n8.x4.shared.b16 {%0,%1,%2,%3}, [%4];"
                 : "=r"(r0), "=r"(r1), "=r"(r2), "=r"(r3) : "r"(addr));
}

__device__ __forceinline__ void ldsm_x4_t(unsigned& r0, unsigned& r1,
                                          unsigned& r2, unsigned& r3, unsigned addr) {
    asm volatile("ldmatrix.sync.aligned.m8n8.x4.trans.shared.b16 {%0,%1,%2,%3}, [%4];"
                 : "=r"(r0), "=r"(r1), "=r"(r2), "=r"(r3) : "r"(addr));
}

__device__ __forceinline__ void red4(float* p, float a, float b, float c, float d) {
    unsigned long long addr = (unsigned long long)p;
    asm volatile("red.global.add.v4.f32 [%0], {%1,%2,%3,%4};"
                 :: "l"(addr), "f"(a), "f"(b), "f"(c), "f"(d) : "memory");
}

__device__ __forceinline__ float silu(float v) {
    return __fdividef(v, 1.0f + __expf(-v));
}

#define H2U(p) (*(const unsigned*)(p))

// ---------------- setup ----------------
__global__ void k_setup(const int* __restrict__ z, const float* __restrict__ emb,
                        const float* __restrict__ W_rbf) {
    int i = blockIdx.x * blockDim.x + threadIdx.x;
    if (i < N_NODES * 384) g_vec[i] = 0.0f;
    if (i < N_NODES * 128) {
        g_dx[i] = 0.0f;
        int n = i >> 7, j = i & 127;
        g_x[i] = emb[z[n] * HIDDEN + j];
    }
    if (i < N_GRAPHS * 65) g_pooled[i] = 0.0f;
    if (i < 2 * 128 * 16) {
        int l = i >> 11, n = (i >> 4) & 127, kk = i & 15;
        const float* base = W_rbf + l * 32 * 128;
        __half lo = __float2half(base[(2 * kk) * 128 + n]);
        __half hi = __float2half(base[(2 * kk + 1) * 128 + n]);
        __half2 h2 = __halves2half2(lo, hi);
        g_wrbfp[i] = *(unsigned*)&h2;
    }
}

__global__ void k_geom(const float* __restrict__ pos, const int* __restrict__ ei) {
    int e = blockIdx.x * blockDim.x + threadIdx.x;
    if (e >= N_EDGES) return;
    int s = ei[e], d = ei[N_EDGES + e];
    float dx = pos[d * 3 + 0] - pos[s * 3 + 0];
    float dy = pos[d * 3 + 1] - pos[s * 3 + 1];
    float dz = pos[d * 3 + 2] - pos[s * 3 + 2];
    float r = sqrtf(dx * dx + dy * dy + dz * dz + 1e-8f);
    float inv = 1.0f / r;
    g_dirn[e * 3 + 0] = dx * inv;
    g_dirn[e * 3 + 1] = dy * inv;
    g_dirn[e * 3 + 2] = dz * inv;

    uint4* rp = (uint4*)&g_rbf[e * 32];
    uint4 z4 = make_uint4(0, 0, 0, 0);
    rp[0] = z4; rp[1] = z4; rp[2] = z4; rp[3] = z4;

    if (r < 5.0f) {
        const float c0 = 0.006737946999085467f;
        const float step = (1.0f - c0) / 31.0f;
        const float tmp = (2.0f / 32.0f) * (1.0f - c0);
        const float beta = 1.0f / (tmp * tmp);
        float cut = 0.5f * (__cosf(0.6283185307179586f * r) + 1.0f);
        float er = __expf(-r);
        int kc = (int)((er - c0) * (1.0f / step));
        int base = kc - 8;
        base = base < 0 ? 0 : (base > 15 ? 15 : base);
#pragma unroll
        for (int kk = 0; kk < 17; ++kk) {
            int k = base + kk;
            float m = c0 + (float)k * step;
            float dd = er - m;
            g_rbf[e * 32 + k] = __float2half(cut * __expf(-beta * dd * dd));
        }
    }
}

// ---------------- one 64-row GEMM tile (fp16 mma, W staged [k][n], trans-LDSM B) ----
// MODE 0: A row-major RxK.  MODE 2 (K=256): A-row = [x | vnorm(A2)].
template <int K, int MODE>
__device__ __forceinline__ void gemm_tile(
    const float* __restrict__ A, const float* __restrict__ A2,
    const float* __restrict__ W, const float* __restrict__ bias,
    float* __restrict__ C, int R, int r0, int accum, int act, int clearA,
    __half* smh) {
    constexpr int PK = K + 8;
    __half* W_h = smh;            // [K][PADH]  (k rows, n cols)
    __half* A_h = W_h + K * PADH; // [64][PK]
    int tid = threadIdx.x;
    int w = tid >> 5, lane = tid & 31, gid = lane >> 2, tig = lane & 3;

    // stage W [k][n]: coalesced float4 loads, vector half stores
    for (int m4 = tid; m4 < K * 32; m4 += 256) {
        int k = m4 >> 5, n = (m4 & 31) * 4;
        float4 v = *(const float4*)&W[k * 128 + n];
        __half2 h0 = __floats2half2_rn(v.x, v.y);
        __half2 h1 = __floats2half2_rn(v.z, v.w);
        *(uint2*)&W_h[k * PADH + n] = make_uint2(*(unsigned*)&h0, *(unsigned*)&h1);
    }
    // stage A
    for (int m4 = tid; m4 < 64 * (K / 4); m4 += 256) {
        int r = m4 / (K / 4), c = (m4 % (K / 4)) * 4;
        int rr = r0 + r;
        float4 v = make_float4(0.f, 0.f, 0.f, 0.f);
        if (rr < R) {
            if (MODE == 2) {
                if (c < 128) {
                    v = *(const float4*)&A[rr * 128 + c];
                } else {
                    int cc = c - 128;
                    float4 a0 = *(const float4*)&A2[(rr * 3 + 0) * 128 + cc];
                    float4 a1 = *(const float4*)&A2[(rr * 3 + 1) * 128 + cc];
                    float4 a2 = *(const float4*)&A2[(rr * 3 + 2) * 128 + cc];
                    v.x = sqrtf(a0.x * a0.x + a1.x * a1.x + a2.x * a2.x + 1e-8f);
                    v.y = sqrtf(a0.y * a0.y + a1.y * a1.y + a2.y * a2.y + 1e-8f);
                    v.z = sqrtf(a0.z * a0.z + a1.z * a1.z + a2.z * a2.z + 1e-8f);
                    v.w = sqrtf(a0.w * a0.w + a1.w * a1.w + a2.w * a2.w + 1e-8f);
                }
            } else {
                v = *(const float4*)&A[rr * K + c];
                if (clearA)
                    *(float4*)&((float*)A)[rr * K + c] = make_float4(0.f, 0.f, 0.f, 0.f);
            }
        }
        __half2 h0 = __floats2half2_rn(v.x, v.y);
        __half2 h1 = __floats2half2_rn(v.z, v.w);
        *(uint2*)&A_h[r * PK + c] = make_uint2(*(unsigned*)&h0, *(unsigned*)&h1);
    }
    __syncthreads();

    int m0 = (w & 3) * 16;
    int nbase = (w >> 2) * 64;
    int sec = lane >> 3, r8 = lane & 7;
    unsigned a_base = (unsigned)__cvta_generic_to_shared(A_h);
    unsigned w_base = (unsigned)__cvta_generic_to_shared(W_h);
    unsigned aAddr = a_base +
        (((m0 + r8 + ((sec & 1) << 3)) * PK + ((sec >> 1) << 3)) << 1);
    // trans-LDSM B: matrix g: row k0 + (g&1)*8 + r8, col nbase + j*16 + (g>>1)*8
    unsigned bAddrT = w_base +
        (((((sec & 1) << 3) + r8) * PADH + ((sec >> 1) << 3) + nbase) << 1);

    float acc[8][4];
#pragma unroll
    for (int it = 0; it < 8; ++it)
#pragma unroll
        for (int q = 0; q < 4; ++q) acc[it][q] = 0.0f;

#pragma unroll
    for (int ks = 0; ks < K / 16; ++ks) {
        unsigned koff_a = ks * 32;
        unsigned koff_b = ks * 16 * PADH * 2;
        unsigned a0, a1, a2, a3;
        ldsm_x4(a0, a1, a2, a3, aAddr + koff_a);
#pragma unroll
        for (int j = 0; j < 4; ++j) {
            unsigned b0, b1, b2, b3;
            ldsm_x4_t(b0, b1, b2, b3, bAddrT + koff_b + j * 32);
            mma_f16(acc[2 * j], a0, a1, a2, a3, b0, b1);
            mma_f16(acc[2 * j + 1], a0, a1, a2, a3, b2, b3);
        }
    }

#pragma unroll
    for (int it = 0; it < 8; ++it) {
        int n0 = nbase + it * 8;
        int col = n0 + 2 * tig;
        float bb0 = bias ? bias[col] : 0.0f;
        float bb1 = bias ? bias[col + 1] : 0.0f;
#pragma unroll
        for (int h = 0; h < 2; ++h) {
            int row = r0 + m0 + gid + h * 8;
            if (row < R) {
                float v0 = acc[it][2 * h + 0] + bb0;
                float v1 = acc[it][2 * h + 1] + bb1;
                if (accum) {
                    v0 += C[row * 128 + col];
                    v1 += C[row * 128 + col + 1];
                }
                if (act) { v0 = silu(v0); v1 = silu(v1); }
                C[row * 128 + col] = v0;
                C[row * 128 + col + 1] = v1;
            }
        }
    }
}

// merged: branch-1 small GEMM (accum into C1, optional clear of A1) ∥ branch-2 big GEMM
__global__ __launch_bounds__(256, 3) void k_gemm2(
    const float* A1, const float* W1, float* C1, int R1, int clear1,
    const float* A2, const float* W2, float* C2, int R2) {
    extern __shared__ __half smh[];
    int nT1 = (R1 + 63) >> 6;
    if ((int)blockIdx.x < nT1)
        gemm_tile<128, 0>(A1, nullptr, W1, nullptr, C1, R1, blockIdx.x << 6,
                          1, 0, clear1, smh);
    else
        gemm_tile<128, 0>(A2, nullptr, W2, nullptr, C2, R2,
                          ((int)blockIdx.x - nT1) << 6, 0, 0, 0, smh);
}

// Wa fused: a = silu([x | vnorm(v2)] @ W_a + b_a)
__global__ __launch_bounds__(256, 2) void k_gemma(
    const float* X, const float* V2, const float* W, const float* bias,
    float* C, int R) {
    extern __shared__ __half smh[];
    gemm_tile<256, 2>(X, V2, W, bias, C, R, blockIdx.x << 6, 0, 1, 0, smh);
}

// ---------------- fused fp16 edge kernel ----------------
__global__ __launch_bounds__(512, 3) void k_edge(
    const int* __restrict__ ei, const unsigned* __restrict__ wrbfp,
    const float* __restrict__ W1, int novmix) {
    extern __shared__ __half smh[];
    __half* W1KN   = smh;                      // [128 k][PADH n]
    __half* filt_h = W1KN + 128 * PADH;        // [64 e][PADH c]
    __half* t_h    = filt_h + ET * PADH;       // [64 e][PADH k] (phi alias)
    float* dirn_s = (float*)(t_h + ET * PADH);
    int* src_s = (int*)(dirn_s + 192);
    int* dst_s = src_s + ET;

    int tid = threadIdx.x;
    int w = tid >> 5, lane = tid & 31, gid = lane >> 2, tig = lane & 3;

    // stage W1 [k][n]: coalesced
    for (int m4 = tid; m4 < 128 * 32; m4 += 512) {
        int k = m4 >> 5, n = (m4 & 31) * 4;
        float4 v = *(const float4*)&W1[k * 128 + n];
        __half2 h0 = __floats2half2_rn(v.x, v.y);
        __half2 h1 = __floats2half2_rn(v.z, v.w);
        *(uint2*)&W1KN[k * PADH + n] = make_uint2(*(unsigned*)&h0, *(unsigned*)&h1);
    }

    int m0 = (w & 3) * 16;
    int nbase = (w >> 2) * 32;
    int c4 = lane * 4;

    int sec = lane >> 3, r8 = lane & 7;
    unsigned t_base  = (unsigned)__cvta_generic_to_shared(t_h);
    unsigned w1_base = (unsigned)__cvta_generic_to_shared(W1KN);
    unsigned aAddr = t_base +
        (((m0 + r8 + ((sec & 1) << 3)) * PADH + ((sec >> 1) << 3)) << 1);
    unsigned bAddrT = w1_base +
        (((((sec & 1) << 3) + r8) * PADH + ((sec >> 1) << 3) + nbase) << 1);

    int nTiles = N_EDGES / ET;
    for (int t = blockIdx.x; t < nTiles; t += gridDim.x) {
        int e0 = t * ET;
        __syncthreads();

        if (tid < ET) src_s[tid] = ei[e0 + tid];
        else if (tid < 2 * ET) dst_s[tid - ET] = ei[N_EDGES + e0 + (tid - ET)];
        if (tid < ET * 3) dirn_s[tid] = g_dirn[e0 * 3 + tid];
        __syncthreads();

        // filt = rbf @ Wrbf
        {
            float acc[4][4];
#pragma unroll
            for (int it = 0; it < 4; ++it)
#pragma unroll
                for (int q = 0; q < 4; ++q) acc[it][q] = 0.0f;
#pragma unroll
            for (int ks = 0; ks < 2; ++ks) {
                int k0 = ks * 16;
                unsigned a0 = H2U(&g_rbf[(e0 + m0 + gid) * 32 + k0 + 2 * tig]);
                unsigned a1 = H2U(&g_rbf[(e0 + m0 + gid + 8) * 32 + k0 + 2 * tig]);
                unsigned a2 = H2U(&g_rbf[(e0 + m0 + gid) * 32 + k0 + 2 * tig + 8]);
                unsigned a3 = H2U(&g_rbf[(e0 + m0 + gid + 8) * 32 + k0 + 2 * tig + 8]);
#pragma unroll
                for (int it = 0; it < 4; ++it) {
                    int n0 = nbase + it * 8;
                    unsigned b0 = wrbfp[(n0 + gid) * 16 + 8 * ks + tig];
                    unsigned b1 = wrbfp[(n0 + gid) * 16 + 8 * ks + tig + 4];
                    mma_f16(acc[it], a0, a1, a2, a3, b0, b1);
                }
            }
#pragma unroll
            for (int it = 0; it < 4; ++it) {
                int n0 = nbase + it * 8;
                *(__half2*)&filt_h[(m0 + gid) * PADH + n0 + 2 * tig] =
                    __floats2half2_rn(acc[it][0], acc[it][1]);
                *(__half2*)&filt_h[(m0 + gid + 8) * PADH + n0 + 2 * tig] =
                    __floats2half2_rn(acc[it][2], acc[it][3]);
            }
        }
        __syncthreads();

        // t[e][c] = x[src[e]][c] * filt[e][c]
#pragma unroll
        for (int q = 0; q < 4; ++q) {
            int e = w + 16 * q;
            int s = src_s[e];
            float4 xv = *(const float4*)&g_x[s * 128 + c4];
            uint2 fu = *(const uint2*)&filt_h[e * PADH + c4];
            float2 f01 = __half22float2(*(__half2*)&fu.x);
            float2 f23 = __half22float2(*(__half2*)&fu.y);
            __half2 h0 = __floats2half2_rn(xv.x * f01.x, xv.y * f01.y);
            __half2 h1 = __floats2half2_rn(xv.z * f23.x, xv.w * f23.y);
            *(uint2*)&t_h[e * PADH + c4] = make_uint2(*(unsigned*)&h0, *(unsigned*)&h1);
        }
        __syncthreads();

        // phi = t @ W1  (A: LDSM, B: trans-LDSM from [k][n])
        float acc[4][4];
#pragma unroll
        for (int it = 0; it < 4; ++it)
#pragma unroll
            for (int q = 0; q < 4; ++q) acc[it][q] = 0.0f;
#pragma unroll
        for (int ks = 0; ks < 8; ++ks) {
            unsigned koff_a = ks * 32;
            unsigned koff_b = ks * 16 * PADH * 2;
            unsigned a0, a1, a2, a3;
            ldsm_x4(a0, a1, a2, a3, aAddr + koff_a);
            unsigned b00, b01, b10, b11;
            ldsm_x4_t(b00, b01, b10, b11, bAddrT + koff_b);
            unsigned b20, b21, b30, b31;
            ldsm_x4_t(b20, b21, b30, b31, bAddrT + koff_b + 32);
            mma_f16(acc[0], a0, a1, a2, a3, b00, b01);
            mma_f16(acc[1], a0, a1, a2, a3, b10, b11);
            mma_f16(acc[2], a0, a1, a2, a3, b20, b21);
            mma_f16(acc[3], a0, a1, a2, a3, b30, b31);
        }
        __syncthreads();

#pragma unroll
        for (int it = 0; it < 4; ++it) {
            int n0 = nbase + it * 8;
            *(__half2*)&t_h[(m0 + gid) * PADH + n0 + 2 * tig] =
                __floats2half2_rn(silu(acc[it][0]), silu(acc[it][1]));
            *(__half2*)&t_h[(m0 + gid + 8) * PADH + n0 + 2 * tig] =
                __floats2half2_rn(silu(acc[it][2]), silu(acc[it][3]));
        }
        __syncthreads();

        // scatter
#pragma unroll
        for (int q = 0; q < 4; ++q) {
            int e = w + 16 * q;
            int s = src_s[e], d = dst_s[e];
            uint2 pu = *(const uint2*)&t_h[e * PADH + c4];
            float2 p01 = __half22float2(*(__half2*)&pu.x);
            float2 p23 = __half22float2(*(__half2*)&pu.y);
            float d0 = dirn_s[e * 3 + 0];
            float d1 = dirn_s[e * 3 + 1];
            float d2 = dirn_s[e * 3 + 2];
            red4(&g_dx[d * 128 + c4], p01.x, p01.y, p23.x, p23.y);
            if (novmix) {
                red4(&g_vec[(d * 3 + 0) * 128 + c4],
                     p01.x * d0, p01.y * d0, p23.x * d0, p23.y * d0);
                red4(&g_vec[(d * 3 + 1) * 128 + c4],
                     p01.x * d1, p01.y * d1, p23.x * d1, p23.y * d1);
                red4(&g_vec[(d * 3 + 2) * 128 + c4],
                     p01.x * d2, p01.y * d2, p23.x * d2, p23.y * d2);
            } else {
                uint2 fu = *(const uint2*)&filt_h[e * PADH + c4];
                float2 f01 = __half22float2(*(__half2*)&fu.x);
                float2 f23 = __half22float2(*(__half2*)&fu.y);
                float4 m0v = *(const float4*)&g_vmix[(s * 3 + 0) * 128 + c4];
                red4(&g_vec[(d * 3 + 0) * 128 + c4],
                     m0v.x * f01.x + p01.x * d0, m0v.y * f01.y + p01.y * d0,
                     m0v.z * f23.x + p23.x * d0, m0v.w * f23.y + p23.y * d0);
                float4 m1v = *(const float4*)&g_vmix[(s * 3 + 1) * 128 + c4];
                red4(&g_vec[(d * 3 + 1) * 128 + c4],
                     m1v.x * f01.x + p01.x * d1, m1v.y * f01.y + p01.y * d1,
                     m1v.z * f23.x + p23.x * d1, m1v.w * f23.y + p23.y * d1);
                float4 m2v = *(const float4*)&g_vmix[(s * 3 + 2) * 128 + c4];
                red4(&g_vec[(d * 3 + 2) * 128 + c4],
                     m2v.x * f01.x + p01.x * d2, m2v.y * f01.y + p01.y * d2,
                     m2v.z * f23.x + p23.x * d2, m2v.w * f23.y + p23.y * d2);
            }
        }
    }
}

__global__ void k_pool(const float* __restrict__ a, const int* __restrict__ batch,
                       const float* __restrict__ Wb, const float* __restrict__ bb) {
    __shared__ float Wb_s[128 * 65];
    __shared__ float bb_s[65];
    __shared__ float a_s[4][128];
    int tx = threadIdx.x, ty = threadIdx.y;
    int tid = ty * 65 + tx;
    for (int m = tid; m < 128 * 65; m += 260) Wb_s[m] = Wb[m];
    if (tid < 65) bb_s[tid] = bb[tid];
    __syncthreads();
    for (int base = blockIdx.x * 4; base < N_NODES; base += gridDim.x * 4) {
        int n = base + ty;
        a_s[ty][tx] = a[n * 128 + tx];
        if (tx + 65 < 128) a_s[ty][tx + 65] = a[n * 128 + tx + 65];
        __syncthreads();
        float acc = bb_s[tx];
#pragma unroll 4
        for (int jj = 0; jj < 128; ++jj) acc += a_s[ty][jj] * Wb_s[jj * 65 + tx];
        atomicAdd(&g_pooled[batch[n] * 65 + tx], acc);
        __syncthreads();
    }
}

__global__ void k_final(float* __restrict__ out) {
    int idx = blockIdx.x * blockDim.x + threadIdx.x;
    if (idx < N_GRAPHS * LATENT) {
        int g = idx / LATENT, k = idx % LATENT;
        out[idx] = g_pooled[g * 65 + k];
    } else if (idx < N_GRAPHS * LATENT + N_GRAPHS) {
        int g = idx - N_GRAPHS * LATENT;
        float lv = g_pooled[g * 65 + 64];
        out[idx] = fminf(fmaxf(lv, -10.0f), 2.0f);
    }
}

extern "C" void kernel_launch(void* const* d_in, const int* in_sizes, int n_in,
                              void* d_out, int out_size) {
    (void)in_sizes; (void)n_in; (void)out_size;
    const int* z = (const int*)d_in[0];
    const float* pos = (const float*)d_in[1];
    const int* batch = (const int*)d_in[2];
    const int* ei = (const int*)d_in[3];
    const float* embed = (const float*)d_in[4];
    const float* W_rbf = (const float*)d_in[5];
    const float* W1 = (const float*)d_in[6];
    const float* Wo = (const float*)d_in[7];
    const float* Wv = (const float*)d_in[8];
    const float* Wvec2 = (const float*)d_in[10];
    const float* W_a = (const float*)d_in[11];
    const float* b_a = (const float*)d_in[12];
    const float* W_b = (const float*)d_in[13];
    const float* b_b = (const float*)d_in[14];
    float* out = (float*)d_out;

    float *p_x, *p_vec, *p_vmix, *p_dx, *p_a;
    unsigned* p_wrbfp;
    cudaGetSymbolAddress((void**)&p_x, g_x);
    cudaGetSymbolAddress((void**)&p_vec, g_vec);
    cudaGetSymbolAddress((void**)&p_vmix, g_vmix);
    cudaGetSymbolAddress((void**)&p_dx, g_dx);
    cudaGetSymbolAddress((void**)&p_a, g_a);
    cudaGetSymbolAddress((void**)&p_wrbfp, g_wrbfp);

    size_t smem_g128 = (size_t)(128 * PADH + 64 * 136) * 2;       // 52224
    size_t smem_g256 = (size_t)(256 * PADH + 64 * 264) * 2;       // 103424
    size_t smem_edge = (size_t)(128 * PADH + 2 * ET * PADH) * 2
                       + 192 * 4 + 2 * ET * 4;                    // ~69.3 KB
    cudaFuncSetAttribute(k_gemm2, cudaFuncAttributeMaxDynamicSharedMemorySize, (int)smem_g128);
    cudaFuncSetAttribute(k_gemma, cudaFuncAttributeMaxDynamicSharedMemorySize, (int)smem_g256);
    cudaFuncSetAttribute(k_edge, cudaFuncAttributeMaxDynamicSharedMemorySize, (int)smem_edge);

    int nT_small = (N_NODES + 63) / 64;          // 157
    int nT_big = (N_NODES * 3 + 63) / 64;        // 469

    k_setup<<<(N_NODES * 384 + 255) / 256, 256>>>(z, embed, W_rbf);
    k_geom<<<(N_EDGES + 255) / 256, 256>>>(pos, ei);

    // ---- layer 0 (vmix == 0) ----
    k_edge<<<444, 512, smem_edge>>>(ei, p_wrbfp, W1, 1);
    // merged: x += dx@Wo0 (clear dx) ∥ vmix = vec@Wv1
    k_gemm2<<<nT_small + nT_big, 256, smem_g128>>>(
        p_dx, Wo, p_x, N_NODES, 1,
        p_vec, Wv + 128 * 128, p_vmix, N_NODES * 3);

    // ---- layer 1 ----
    k_edge<<<444, 512, smem_edge>>>(ei, p_wrbfp + 128 * 16, W1 + 128 * 128, 0);
    // merged: x += dx@Wo1 ∥ v2 = vec@Wvec2
    k_gemm2<<<nT_small + nT_big, 256, smem_g128>>>(
        p_dx, Wo + 128 * 128, p_x, N_NODES, 0,
        p_vec, Wvec2, p_vmix, N_NODES * 3);

    // a = silu([x | vnorm(v2)] @ W_a + b_a)
    k_gemma<<<nT_small, 256, smem_g256>>>(p_x, p_vmix, W_a, b_a, p_a, N_NODES);

    dim3 pb(65, 4);
    k_pool<<<296, pb>>>(p_a, batch, W_b, b_b);

    k_final<<<(N_GRAPHS * LATENT + N_GRAPHS + 255) / 256, 256>>>(out);
}